// round 1
// baseline (speedup 1.0000x reference)
#include <cuda_runtime.h>

// Self_Attn: B=4, C=512, N=4096 (64x64), D=64
// Outputs (tuple order): out [B,C,64,64] fp32, attention [B,N,N] fp32.

namespace {
constexpr int B_ = 4;
constexpr int C_ = 512;
constexpr int N_ = 4096;
constexpr int D_ = 64;
}

// Scratch (device globals; no runtime allocation allowed).
__device__ float g_q[B_ * N_ * D_];            // [B][N][D]
__device__ float g_k[B_ * N_ * D_];            // [B][N][D]  (k transposed)
__device__ float g_v[(size_t)B_ * N_ * C_];    // [B][N][C]  (v transposed)

// ---------------------------------------------------------------------------
// Projection: out[b,n,d] = sum_c W[d,c] * x[b,c,n] + bias[d]
// Block tile: 64 n x 64 d, 256 threads, 4x4 micro-tile, kc=16 over C.
// ---------------------------------------------------------------------------
__global__ void proj_kernel(const float* __restrict__ x,
                            const float* __restrict__ W,
                            const float* __restrict__ bias,
                            float* __restrict__ out, int Dout) {
    const int b  = blockIdx.z;
    const int n0 = blockIdx.x * 64;
    const int d0 = blockIdx.y * 64;
    const float* xb = x + (size_t)b * C_ * N_;
    float* ob = out + (size_t)b * N_ * Dout;

    __shared__ float xs[16][64];   // xs[kk][n]
    __shared__ float ws[16][65];   // ws[kk][d]

    const int tid = threadIdx.x;
    const int tx = tid & 15;   // d
    const int ty = tid >> 4;   // n

    float acc[4][4] = {};
    for (int c0 = 0; c0 < C_; c0 += 16) {
#pragma unroll
        for (int i = 0; i < 4; i++) {
            int idx = tid + i * 256;
            int kk = idx >> 6, col = idx & 63;
            xs[kk][col] = xb[(size_t)(c0 + kk) * N_ + n0 + col];
        }
#pragma unroll
        for (int i = 0; i < 4; i++) {
            int idx = tid + i * 256;
            int kk = idx & 15, d = idx >> 4;
            ws[kk][d] = W[(size_t)(d0 + d) * C_ + c0 + kk];
        }
        __syncthreads();
#pragma unroll
        for (int kk = 0; kk < 16; kk++) {
            float ar[4], br[4];
#pragma unroll
            for (int i = 0; i < 4; i++) ar[i] = xs[kk][ty + 16 * i];
#pragma unroll
            for (int j = 0; j < 4; j++) br[j] = ws[kk][tx + 16 * j];
#pragma unroll
            for (int i = 0; i < 4; i++)
#pragma unroll
                for (int j = 0; j < 4; j++) acc[i][j] += ar[i] * br[j];
        }
        __syncthreads();
    }
#pragma unroll
    for (int i = 0; i < 4; i++) {
        int n = n0 + ty + 16 * i;
#pragma unroll
        for (int j = 0; j < 4; j++) {
            int d = d0 + tx + 16 * j;
            ob[(size_t)n * Dout + d] = acc[i][j] + bias[d];
        }
    }
}

// ---------------------------------------------------------------------------
// Energy: E[b,m,n] = sum_d q[b,m,d] * k[b,n,d]   (written as raw logits)
// Block tile 64m x 64n; full K=64 tiles resident in smem (one sync pair).
// ---------------------------------------------------------------------------
__global__ void energy_kernel(float* __restrict__ attn) {
    const int b  = blockIdx.z;
    const int m0 = blockIdx.y * 64;
    const int n0 = blockIdx.x * 64;
    const float* qb = g_q + (size_t)b * N_ * D_;
    const float* kb = g_k + (size_t)b * N_ * D_;
    float* eb = attn + (size_t)b * N_ * N_;

    __shared__ float qs[64][65];  // qs[d][m]
    __shared__ float ks[64][65];  // ks[d][n]

    const int tid = threadIdx.x;
    const int tx = tid & 15;  // n (contiguous stores)
    const int ty = tid >> 4;  // m

#pragma unroll
    for (int i = 0; i < 16; i++) {
        int idx = tid + i * 256;
        int kk = idx & 63, row = idx >> 6;
        qs[kk][row] = qb[(size_t)(m0 + row) * D_ + kk];
        ks[kk][row] = kb[(size_t)(n0 + row) * D_ + kk];
    }
    __syncthreads();

    float acc[4][4] = {};
#pragma unroll
    for (int kk = 0; kk < 64; kk++) {
        float ar[4], br[4];
#pragma unroll
        for (int i = 0; i < 4; i++) ar[i] = qs[kk][ty + 16 * i];
#pragma unroll
        for (int j = 0; j < 4; j++) br[j] = ks[kk][tx + 16 * j];
#pragma unroll
        for (int i = 0; i < 4; i++)
#pragma unroll
            for (int j = 0; j < 4; j++) acc[i][j] += ar[i] * br[j];
    }
#pragma unroll
    for (int i = 0; i < 4; i++) {
        size_t rowoff = (size_t)(m0 + ty + 16 * i) * N_ + n0;
#pragma unroll
        for (int j = 0; j < 4; j++) eb[rowoff + tx + 16 * j] = acc[i][j];
    }
}

// ---------------------------------------------------------------------------
// Row softmax in place. One block (256 thr) per row of 4096; row cached in regs.
// ---------------------------------------------------------------------------
__global__ void softmax_kernel(float* __restrict__ attn) {
    float* p = attn + (size_t)blockIdx.x * N_;
    const int tid = threadIdx.x;

    float v[16];
    float mx = -3.0e38f;
#pragma unroll
    for (int i = 0; i < 16; i++) {
        v[i] = p[tid + i * 256];
        mx = fmaxf(mx, v[i]);
    }
    __shared__ float red[8];
#pragma unroll
    for (int o = 16; o; o >>= 1) mx = fmaxf(mx, __shfl_xor_sync(0xffffffffu, mx, o));
    if ((tid & 31) == 0) red[tid >> 5] = mx;
    __syncthreads();
    mx = red[0];
#pragma unroll
    for (int i = 1; i < 8; i++) mx = fmaxf(mx, red[i]);
    __syncthreads();

    float s = 0.f;
#pragma unroll
    for (int i = 0; i < 16; i++) {
        v[i] = __expf(v[i] - mx);
        s += v[i];
    }
#pragma unroll
    for (int o = 16; o; o >>= 1) s += __shfl_xor_sync(0xffffffffu, s, o);
    if ((tid & 31) == 0) red[tid >> 5] = s;
    __syncthreads();
    s = 0.f;
#pragma unroll
    for (int i = 0; i < 8; i++) s += red[i];
    const float inv = 1.0f / s;
#pragma unroll
    for (int i = 0; i < 16; i++) p[tid + i * 256] = v[i] * inv;
}

// ---------------------------------------------------------------------------
// out[b,c,m] = gamma * sum_n attn[b,m,n] * vT[b,n,c] + x[b,c,m]
// Block tile 64m x 64c, kc=32 over n. Stores coalesced along m.
// ---------------------------------------------------------------------------
__global__ void out_kernel(const float* __restrict__ attn,
                           const float* __restrict__ x,
                           const float* __restrict__ gamma,
                           float* __restrict__ out) {
    const int b  = blockIdx.z;
    const int c0 = blockIdx.x * 64;   // c fastest: 8 sibling blocks share attn rows in L2
    const int m0 = blockIdx.y * 64;
    const float* A  = attn + (size_t)b * N_ * N_;
    const float* Bm = g_v + (size_t)b * N_ * C_;

    __shared__ float as_[32][65];  // as_[kk][m]
    __shared__ float bs_[32][65];  // bs_[kk][c]

    const int tid = threadIdx.x;
    const int tx = tid & 15;  // m (contiguous stores)
    const int ty = tid >> 4;  // c

    float acc[4][4] = {};
    for (int nn0 = 0; nn0 < N_; nn0 += 32) {
#pragma unroll
        for (int i = 0; i < 8; i++) {
            int idx = tid + i * 256;
            {
                int kk = idx & 31, m = idx >> 5;
                as_[kk][m] = A[(size_t)(m0 + m) * N_ + nn0 + kk];
            }
            {
                int c = idx & 63, kk = idx >> 6;
                bs_[kk][c] = Bm[(size_t)(nn0 + kk) * C_ + c0 + c];
            }
        }
        __syncthreads();
#pragma unroll
        for (int kk = 0; kk < 32; kk++) {
            float ar[4], br[4];
#pragma unroll
            for (int i = 0; i < 4; i++) ar[i] = as_[kk][tx + 16 * i];
#pragma unroll
            for (int j = 0; j < 4; j++) br[j] = bs_[kk][ty + 16 * j];
#pragma unroll
            for (int i = 0; i < 4; i++)
#pragma unroll
                for (int j = 0; j < 4; j++) acc[i][j] += ar[i] * br[j];
        }
        __syncthreads();
    }

    const float g = gamma[0];
#pragma unroll
    for (int j = 0; j < 4; j++) {
        int c = c0 + ty + 16 * j;
        size_t base = (size_t)b * C_ * N_ + (size_t)c * N_ + m0;
#pragma unroll
        for (int i = 0; i < 4; i++) {
            size_t idx = base + tx + 16 * i;
            out[idx] = g * acc[i][j] + x[idx];
        }
    }
}

// ---------------------------------------------------------------------------
extern "C" void kernel_launch(void* const* d_in, const int* in_sizes, int n_in,
                              void* d_out, int out_size) {
    (void)in_sizes; (void)n_in; (void)out_size;
    const float* x     = (const float*)d_in[0];
    const float* Wq    = (const float*)d_in[1];
    const float* bq    = (const float*)d_in[2];
    const float* Wk    = (const float*)d_in[3];
    const float* bk    = (const float*)d_in[4];
    const float* Wv    = (const float*)d_in[5];
    const float* bv    = (const float*)d_in[6];
    const float* gamma = (const float*)d_in[7];

    float* out  = (float*)d_out;
    float* attn = out + (size_t)B_ * C_ * N_;   // tuple order: (out, attention)

    float *q = nullptr, *k = nullptr, *v = nullptr;
    cudaGetSymbolAddress((void**)&q, g_q);
    cudaGetSymbolAddress((void**)&k, g_k);
    cudaGetSymbolAddress((void**)&v, g_v);

    dim3 blk(256);
    proj_kernel<<<dim3(N_ / 64, D_ / 64, B_), blk>>>(x, Wq, bq, q, D_);
    proj_kernel<<<dim3(N_ / 64, D_ / 64, B_), blk>>>(x, Wk, bk, k, D_);
    proj_kernel<<<dim3(N_ / 64, C_ / 64, B_), blk>>>(x, Wv, bv, v, C_);
    energy_kernel<<<dim3(N_ / 64, N_ / 64, B_), blk>>>(attn);
    softmax_kernel<<<dim3(B_ * N_), blk>>>(attn);
    out_kernel<<<dim3(C_ / 64, N_ / 64, B_), blk>>>(attn, x, gamma, out);
}

// round 3
// speedup vs baseline: 2.2444x; 2.2444x over previous
#include <cuda_runtime.h>
#include <cuda_bf16.h>
#include <cstdint>

// Self_Attn: B=4, C=512, N=4096 (64x64), D=64
// Outputs (tuple order): out [B,C,64,64] fp32, attention [B,N,N] fp32.

namespace {
constexpr int B_ = 4;
constexpr int C_ = 512;
constexpr int N_ = 4096;
constexpr int D_ = 64;

constexpr int KC = 32;             // K elems (bf16) per chunk; hi+lo pack = 128B row
constexpr int NCHUNK = N_ / KC;    // 128
constexpr int STAGE = 32768;       // A tile 16KB + B tile 16KB
constexpr int EPI_P = 132;         // epilogue smem pitch (floats)
constexpr int DYN_SMEM = 128 * EPI_P * 4;  // 67584 > 2*STAGE
}

// Scratch (device globals; no runtime allocation allowed).
__device__ float g_q[B_ * N_ * D_];                     // [B][N][D]
__device__ float g_k[B_ * N_ * D_];                     // [B][N][D]
__device__ __nv_bfloat16 g_vhi[(size_t)B_ * C_ * N_];   // [B][C][N] K-major
__device__ __nv_bfloat16 g_vlo[(size_t)B_ * C_ * N_];
__device__ __nv_bfloat16 g_ahi[(size_t)B_ * N_ * N_];   // [B][M][N] K-major
__device__ __nv_bfloat16 g_alo[(size_t)B_ * N_ * N_];

// ---------------------------------------------------------------------------
// helpers
// ---------------------------------------------------------------------------
__device__ __forceinline__ uint32_t smem_u32(const void* p) {
    uint32_t a;
    asm("{ .reg .u64 t; cvta.to.shared.u64 t, %1; cvt.u32.u64 %0, t; }" : "=r"(a) : "l"(p));
    return a;
}

__device__ __forceinline__ void cp16(uint32_t dst, const void* src) {
    asm volatile("cp.async.cg.shared.global [%0], [%1], 16;" :: "r"(dst), "l"(src) : "memory");
}

__device__ __forceinline__ void ldsm4(uint32_t* r, uint32_t addr) {
    asm volatile("ldmatrix.sync.aligned.m8n8.x4.shared.b16 {%0,%1,%2,%3}, [%4];"
                 : "=r"(r[0]), "=r"(r[1]), "=r"(r[2]), "=r"(r[3]) : "r"(addr));
}

__device__ __forceinline__ void mma16816(float* d, const uint32_t* a, uint32_t b0, uint32_t b1) {
    asm volatile(
        "mma.sync.aligned.m16n8k16.row.col.f32.bf16.bf16.f32 "
        "{%0,%1,%2,%3}, {%4,%5,%6,%7}, {%8,%9}, {%0,%1,%2,%3};"
        : "+f"(d[0]), "+f"(d[1]), "+f"(d[2]), "+f"(d[3])
        : "r"(a[0]), "r"(a[1]), "r"(a[2]), "r"(a[3]), "r"(b0), "r"(b1));
}

// 128B-row XOR swizzle (conflict-free for ldmatrix + cp.async stores)
__device__ __forceinline__ uint32_t swz(uint32_t row, uint32_t colbyte) {
    return row * 128u + (colbyte ^ ((row & 7u) << 4));
}

// ---------------------------------------------------------------------------
// Projection (q,k): out[b,n,d] = sum_c W[d,c] * x[b,c,n] + bias[d]
// ---------------------------------------------------------------------------
__global__ void proj_kernel(const float* __restrict__ x,
                            const float* __restrict__ W,
                            const float* __restrict__ bias,
                            float* __restrict__ out, int Dout) {
    const int b  = blockIdx.z;
    const int n0 = blockIdx.x * 64;
    const int d0 = blockIdx.y * 64;
    const float* xb = x + (size_t)b * C_ * N_;
    float* ob = out + (size_t)b * N_ * Dout;

    __shared__ float xs[16][64];
    __shared__ float ws[16][65];

    const int tid = threadIdx.x;
    const int tx = tid & 15;   // d
    const int ty = tid >> 4;   // n

    float acc[4][4] = {};
    for (int c0 = 0; c0 < C_; c0 += 16) {
#pragma unroll
        for (int i = 0; i < 4; i++) {
            int idx = tid + i * 256;
            int kk = idx >> 6, col = idx & 63;
            xs[kk][col] = xb[(size_t)(c0 + kk) * N_ + n0 + col];
        }
#pragma unroll
        for (int i = 0; i < 4; i++) {
            int idx = tid + i * 256;
            int kk = idx & 15, d = idx >> 4;
            ws[kk][d] = W[(size_t)(d0 + d) * C_ + c0 + kk];
        }
        __syncthreads();
#pragma unroll
        for (int kk = 0; kk < 16; kk++) {
            float ar[4], br[4];
#pragma unroll
            for (int i = 0; i < 4; i++) ar[i] = xs[kk][ty + 16 * i];
#pragma unroll
            for (int j = 0; j < 4; j++) br[j] = ws[kk][tx + 16 * j];
#pragma unroll
            for (int i = 0; i < 4; i++)
#pragma unroll
                for (int j = 0; j < 4; j++) acc[i][j] += ar[i] * br[j];
        }
        __syncthreads();
    }
#pragma unroll
    for (int i = 0; i < 4; i++) {
        int n = n0 + ty + 16 * i;
#pragma unroll
        for (int j = 0; j < 4; j++) {
            int d = d0 + tx + 16 * j;
            ob[(size_t)n * Dout + d] = acc[i][j] + bias[d];
        }
    }
}

// ---------------------------------------------------------------------------
// Projection (v): bf16 hi/lo pair in [B,C,N] (n contiguous, K-major B operand)
// ---------------------------------------------------------------------------
__global__ void proj_v_kernel(const float* __restrict__ x,
                              const float* __restrict__ W,
                              const float* __restrict__ bias,
                              __nv_bfloat16* __restrict__ vhi,
                              __nv_bfloat16* __restrict__ vlo) {
    const int b  = blockIdx.z;
    const int n0 = blockIdx.x * 64;
    const int c0 = blockIdx.y * 64;
    const float* xb = x + (size_t)b * C_ * N_;

    __shared__ float xs[16][64];   // xs[kk][n]
    __shared__ float ws[16][65];   // ws[kk][c]

    const int tid = threadIdx.x;
    const int tx = tid & 15;   // n
    const int ty = tid >> 4;   // c

    float acc[4][4] = {};   // [c][n]
    for (int k0 = 0; k0 < C_; k0 += 16) {
#pragma unroll
        for (int i = 0; i < 4; i++) {
            int idx = tid + i * 256;
            int kk = idx >> 6, col = idx & 63;
            xs[kk][col] = xb[(size_t)(k0 + kk) * N_ + n0 + col];
        }
#pragma unroll
        for (int i = 0; i < 4; i++) {
            int idx = tid + i * 256;
            int kk = idx & 15, c = idx >> 4;
            ws[kk][c] = W[(size_t)(c0 + c) * C_ + k0 + kk];
        }
        __syncthreads();
#pragma unroll
        for (int kk = 0; kk < 16; kk++) {
            float ar[4], br[4];
#pragma unroll
            for (int i = 0; i < 4; i++) ar[i] = ws[kk][ty + 16 * i];
#pragma unroll
            for (int j = 0; j < 4; j++) br[j] = xs[kk][tx + 16 * j];
#pragma unroll
            for (int i = 0; i < 4; i++)
#pragma unroll
                for (int j = 0; j < 4; j++) acc[i][j] += ar[i] * br[j];
        }
        __syncthreads();
    }
#pragma unroll
    for (int i = 0; i < 4; i++) {
        int c = c0 + ty + 16 * i;
        float bv = bias[c];
        size_t rowbase = ((size_t)b * C_ + c) * N_ + n0;
#pragma unroll
        for (int j = 0; j < 4; j++) {
            float val = acc[i][j] + bv;
            __nv_bfloat16 h = __float2bfloat16(val);
            vhi[rowbase + tx + 16 * j] = h;
            vlo[rowbase + tx + 16 * j] = __float2bfloat16(val - __bfloat162float(h));
        }
    }
}

// ---------------------------------------------------------------------------
// Energy: E[b,m,n] = sum_d q[b,m,d] * k[b,n,d] (raw logits, fp32)
// ---------------------------------------------------------------------------
__global__ void energy_kernel(float* __restrict__ attn) {
    const int b  = blockIdx.z;
    const int m0 = blockIdx.y * 64;
    const int n0 = blockIdx.x * 64;
    const float* qb = g_q + (size_t)b * N_ * D_;
    const float* kb = g_k + (size_t)b * N_ * D_;
    float* eb = attn + (size_t)b * N_ * N_;

    __shared__ float qs[64][65];
    __shared__ float ks[64][65];

    const int tid = threadIdx.x;
    const int tx = tid & 15;  // n
    const int ty = tid >> 4;  // m

#pragma unroll
    for (int i = 0; i < 16; i++) {
        int idx = tid + i * 256;
        int kk = idx & 63, row = idx >> 6;
        qs[kk][row] = qb[(size_t)(m0 + row) * D_ + kk];
        ks[kk][row] = kb[(size_t)(n0 + row) * D_ + kk];
    }
    __syncthreads();

    float acc[4][4] = {};
#pragma unroll
    for (int kk = 0; kk < 64; kk++) {
        float ar[4], br[4];
#pragma unroll
        for (int i = 0; i < 4; i++) ar[i] = qs[kk][ty + 16 * i];
#pragma unroll
        for (int j = 0; j < 4; j++) br[j] = ks[kk][tx + 16 * j];
#pragma unroll
        for (int i = 0; i < 4; i++)
#pragma unroll
            for (int j = 0; j < 4; j++) acc[i][j] += ar[i] * br[j];
    }
#pragma unroll
    for (int i = 0; i < 4; i++) {
        size_t rowoff = (size_t)(m0 + ty + 16 * i) * N_ + n0;
#pragma unroll
        for (int j = 0; j < 4; j++) eb[rowoff + tx + 16 * j] = acc[i][j];
    }
}

// ---------------------------------------------------------------------------
// Row softmax in place; also emit attn as bf16 hi/lo split.
// ---------------------------------------------------------------------------
__global__ void softmax_kernel(float* __restrict__ attn,
                               __nv_bfloat16* __restrict__ ahi,
                               __nv_bfloat16* __restrict__ alo) {
    const size_t row = blockIdx.x;
    float* p = attn + row * N_;
    __nv_bfloat16* ph = ahi + row * N_;
    __nv_bfloat16* pl = alo + row * N_;
    const int tid = threadIdx.x;

    float v[16];
    float mx = -3.0e38f;
#pragma unroll
    for (int i = 0; i < 16; i++) {
        v[i] = p[tid + i * 256];
        mx = fmaxf(mx, v[i]);
    }
    __shared__ float red[8];
#pragma unroll
    for (int o = 16; o; o >>= 1) mx = fmaxf(mx, __shfl_xor_sync(0xffffffffu, mx, o));
    if ((tid & 31) == 0) red[tid >> 5] = mx;
    __syncthreads();
    mx = red[0];
#pragma unroll
    for (int i = 1; i < 8; i++) mx = fmaxf(mx, red[i]);
    __syncthreads();

    float s = 0.f;
#pragma unroll
    for (int i = 0; i < 16; i++) {
        v[i] = __expf(v[i] - mx);
        s += v[i];
    }
#pragma unroll
    for (int o = 16; o; o >>= 1) s += __shfl_xor_sync(0xffffffffu, s, o);
    if ((tid & 31) == 0) red[tid >> 5] = s;
    __syncthreads();
    s = 0.f;
#pragma unroll
    for (int i = 0; i < 8; i++) s += red[i];
    const float inv = 1.0f / s;
#pragma unroll
    for (int i = 0; i < 16; i++) {
        float r = v[i] * inv;
        p[tid + i * 256] = r;
        __nv_bfloat16 h = __float2bfloat16(r);
        ph[tid + i * 256] = h;
        pl[tid + i * 256] = __float2bfloat16(r - __bfloat162float(h));
    }
}

// ---------------------------------------------------------------------------
// out[b,c,m] = gamma * sum_n attn[b,m,n] * v[b,c,n] + x[b,c,m]
// HMMA bf16 (mma.sync m16n8k16), compensated split:
//   D = Ahi*Bhi + Alo*Bhi + Ahi*Blo
// CTA 128m x 128c, 8 warps (64m x 32c each), K chunks of 32, cp.async 2-stage.
// smem rows pack [hi(64B) | lo(64B)] = 128B, XOR-swizzled.
// ---------------------------------------------------------------------------
__global__ void __launch_bounds__(256, 1)
out_gemm_kernel(const float* __restrict__ x,
                const float* __restrict__ gamma,
                float* __restrict__ out) {
    extern __shared__ char dynsmem[];
    const uint32_t sbase = smem_u32(dynsmem);

    const int tid  = threadIdx.x;
    const int wid  = tid >> 5;
    const int lane = tid & 31;

    const int b  = blockIdx.z;
    const int c0 = blockIdx.x * 128;
    const int m0 = blockIdx.y * 128;

    const __nv_bfloat16* Ahi = g_ahi + (size_t)b * N_ * N_;
    const __nv_bfloat16* Alo = g_alo + (size_t)b * N_ * N_;
    const __nv_bfloat16* Bhi = g_vhi + (size_t)b * C_ * N_;
    const __nv_bfloat16* Blo = g_vlo + (size_t)b * C_ * N_;

    const int wm = (wid >> 2) * 64;   // warp m offset in tile
    const int wc = (wid & 3) * 32;    // warp c offset in tile

    // per-thread cp.async indices (A and B use identical local layout)
    const int prow = tid >> 3;        // 0..31 (4 rows per t-step of 32... rows = idx>>3)
    const int pseg = tid & 7;         // 16B segment within 128B row

    // ldmatrix per-lane address pieces: row = base + (lane&15), row&7 == lane&7
    const uint32_t lrow = lane & 15;
    const uint32_t lswz = (lane & 7) << 4;
    const uint32_t lcol = (lane >> 4) << 4;   // 0 or 16

    float acc[4][4][4] = {};   // [mtile][n8][reg]

    // ---- prefetch chunk 0 ----
    {
        const uint32_t Ab = sbase, Bb = sbase + 16384;
#pragma unroll
        for (int t = 0; t < 4; t++) {
            const int row = prow + t * 32;
            const uint32_t dcol = (uint32_t)(pseg * 16);
            cp16(Ab + swz(row, dcol),
                 (pseg < 4 ? Ahi : Alo) + (size_t)(m0 + row) * N_ + (pseg & 3) * 8);
            cp16(Bb + swz(row, dcol),
                 (pseg < 4 ? Bhi : Blo) + (size_t)(c0 + row) * N_ + (pseg & 3) * 8);
        }
        asm volatile("cp.async.commit_group;" ::: "memory");
    }

    for (int kc = 0; kc < NCHUNK; kc++) {
        if (kc + 1 < NCHUNK) {
            const uint32_t st = (uint32_t)((kc + 1) & 1) * STAGE;
            const uint32_t Ab = sbase + st, Bb = Ab + 16384;
            const size_t koff = (size_t)(kc + 1) * KC;
#pragma unroll
            for (int t = 0; t < 4; t++) {
                const int row = prow + t * 32;
                const uint32_t dcol = (uint32_t)(pseg * 16);
                cp16(Ab + swz(row, dcol),
                     (pseg < 4 ? Ahi : Alo) + (size_t)(m0 + row) * N_ + koff + (pseg & 3) * 8);
                cp16(Bb + swz(row, dcol),
                     (pseg < 4 ? Bhi : Blo) + (size_t)(c0 + row) * N_ + koff + (pseg & 3) * 8);
            }
            asm volatile("cp.async.commit_group;" ::: "memory");
            asm volatile("cp.async.wait_group 1;" ::: "memory");
        } else {
            asm volatile("cp.async.wait_group 0;" ::: "memory");
        }
        __syncthreads();

        const uint32_t st = (uint32_t)(kc & 1) * STAGE;
        const uint32_t Ab = sbase + st, Bb = Ab + 16384;

#pragma unroll
        for (int ks = 0; ks < 2; ks++) {
            const uint32_t kbHi = (uint32_t)(ks * 32);
            const uint32_t kbLo = 64u + kbHi;

            uint32_t ahi[4][4], alo[4][4], bhi[2][4], blo[2][4];
#pragma unroll
            for (int i = 0; i < 4; i++) {
                const uint32_t row = (uint32_t)(wm + i * 16) + lrow;
                ldsm4(ahi[i], Ab + row * 128u + ((kbHi + lcol) ^ lswz));
                ldsm4(alo[i], Ab + row * 128u + ((kbLo + lcol) ^ lswz));
            }
#pragma unroll
            for (int j = 0; j < 2; j++) {
                const uint32_t row = (uint32_t)(wc + j * 16) + lrow;
                ldsm4(bhi[j], Bb + row * 128u + ((kbHi + lcol) ^ lswz));
                ldsm4(blo[j], Bb + row * 128u + ((kbLo + lcol) ^ lswz));
            }
#pragma unroll
            for (int i = 0; i < 4; i++)
#pragma unroll
                for (int j = 0; j < 4; j++) {
                    const int t2 = j >> 1, p2 = j & 1;
                    mma16816(acc[i][j], ahi[i], bhi[t2][p2], bhi[t2][2 + p2]);
                    mma16816(acc[i][j], alo[i], bhi[t2][p2], bhi[t2][2 + p2]);
                    mma16816(acc[i][j], ahi[i], blo[t2][p2], blo[t2][2 + p2]);
                }
        }
        __syncthreads();
    }

    // ---- epilogue: transpose through smem, fused gamma*acc + x ----
    float* sOut = reinterpret_cast<float*>(dynsmem);
#pragma unroll
    for (int i = 0; i < 4; i++) {
        const int mt = wm + i * 16 + (lane >> 2);
#pragma unroll
        for (int j = 0; j < 4; j++) {
            const int ct = wc + j * 8 + (lane & 3) * 2;
            sOut[ct * EPI_P + mt]           = acc[i][j][0];
            sOut[(ct + 1) * EPI_P + mt]     = acc[i][j][1];
            sOut[ct * EPI_P + mt + 8]       = acc[i][j][2];
            sOut[(ct + 1) * EPI_P + mt + 8] = acc[i][j][3];
        }
    }
    __syncthreads();

    const float g = gamma[0];
    const int ce = tid >> 1;
    const int me = (tid & 1) * 64;
    const size_t gb = ((size_t)b * C_ + c0 + ce) * N_ + m0 + me;
    const float* srow = sOut + ce * EPI_P + me;
#pragma unroll
    for (int v = 0; v < 16; v++) {
        const float4 xv = *reinterpret_cast<const float4*>(x + gb + v * 4);
        float4 ov;
        ov.x = g * srow[v * 4 + 0] + xv.x;
        ov.y = g * srow[v * 4 + 1] + xv.y;
        ov.z = g * srow[v * 4 + 2] + xv.z;
        ov.w = g * srow[v * 4 + 3] + xv.w;
        *reinterpret_cast<float4*>(out + gb + v * 4) = ov;
    }
}

// ---------------------------------------------------------------------------
extern "C" void kernel_launch(void* const* d_in, const int* in_sizes, int n_in,
                              void* d_out, int out_size) {
    (void)in_sizes; (void)n_in; (void)out_size;
    const float* x     = (const float*)d_in[0];
    const float* Wq    = (const float*)d_in[1];
    const float* bq    = (const float*)d_in[2];
    const float* Wk    = (const float*)d_in[3];
    const float* bk    = (const float*)d_in[4];
    const float* Wv    = (const float*)d_in[5];
    const float* bv    = (const float*)d_in[6];
    const float* gamma = (const float*)d_in[7];

    float* out  = (float*)d_out;
    float* attn = out + (size_t)B_ * C_ * N_;   // tuple order: (out, attention)

    float *q = nullptr, *k = nullptr;
    __nv_bfloat16 *vhi = nullptr, *vlo = nullptr, *ahi = nullptr, *alo = nullptr;
    cudaGetSymbolAddress((void**)&q, g_q);
    cudaGetSymbolAddress((void**)&k, g_k);
    cudaGetSymbolAddress((void**)&vhi, g_vhi);
    cudaGetSymbolAddress((void**)&vlo, g_vlo);
    cudaGetSymbolAddress((void**)&ahi, g_ahi);
    cudaGetSymbolAddress((void**)&alo, g_alo);

    cudaFuncSetAttribute(out_gemm_kernel,
                         cudaFuncAttributeMaxDynamicSharedMemorySize, DYN_SMEM);

    dim3 blk(256);
    proj_kernel<<<dim3(N_ / 64, D_ / 64, B_), blk>>>(x, Wq, bq, q, D_);
    proj_kernel<<<dim3(N_ / 64, D_ / 64, B_), blk>>>(x, Wk, bk, k, D_);
    proj_v_kernel<<<dim3(N_ / 64, C_ / 64, B_), blk>>>(x, Wv, bv, vhi, vlo);
    energy_kernel<<<dim3(N_ / 64, N_ / 64, B_), blk>>>(attn);
    softmax_kernel<<<dim3(B_ * N_), blk>>>(attn, ahi, alo);
    out_gemm_kernel<<<dim3(C_ / 128, N_ / 128, B_), blk, DYN_SMEM>>>(x, gamma, out);
}

// round 4
// speedup vs baseline: 2.3683x; 1.0552x over previous
#include <cuda_runtime.h>
#include <cuda_bf16.h>
#include <cstdint>

// Self_Attn: B=4, C=512, N=4096 (64x64), D=64
// Outputs (tuple order): out [B,C,64,64] fp32, attention [B,N,N] fp32.

namespace {
constexpr int B_ = 4;
constexpr int C_ = 512;
constexpr int N_ = 4096;
constexpr int D_ = 64;

constexpr int KC = 32;             // out-GEMM K elems per chunk
constexpr int NCHUNK = N_ / KC;    // 128
constexpr int STAGE = 32768;       // out-GEMM stage: A 16KB + B 16KB
constexpr int EPI_P = 132;         // epilogue smem pitch (floats)
constexpr int DYN_OUT = 3 * STAGE; // 98304 (3-stage ring; > epi 67584)
constexpr int DYN_E = 128 * EPI_P * 4;  // 67584 (> 64KB tiles)
}

// Scratch (device globals; no runtime allocation allowed).
__device__ __nv_bfloat16 g_qhi[B_ * N_ * D_];           // [B][N][D]
__device__ __nv_bfloat16 g_qlo[B_ * N_ * D_];
__device__ __nv_bfloat16 g_khi[B_ * N_ * D_];
__device__ __nv_bfloat16 g_klo[B_ * N_ * D_];
__device__ __nv_bfloat16 g_vhi[(size_t)B_ * C_ * N_];   // [B][C][N] K-major
__device__ __nv_bfloat16 g_vlo[(size_t)B_ * C_ * N_];
__device__ __nv_bfloat16 g_ahi[(size_t)B_ * N_ * N_];   // [B][M][N] K-major
__device__ __nv_bfloat16 g_alo[(size_t)B_ * N_ * N_];

// ---------------------------------------------------------------------------
// helpers
// ---------------------------------------------------------------------------
__device__ __forceinline__ uint32_t smem_u32(const void* p) {
    uint32_t a;
    asm("{ .reg .u64 t; cvta.to.shared.u64 t, %1; cvt.u32.u64 %0, t; }" : "=r"(a) : "l"(p));
    return a;
}

__device__ __forceinline__ void cp16(uint32_t dst, const void* src) {
    asm volatile("cp.async.cg.shared.global [%0], [%1], 16;" :: "r"(dst), "l"(src) : "memory");
}

__device__ __forceinline__ void ldsm4(uint32_t* r, uint32_t addr) {
    asm volatile("ldmatrix.sync.aligned.m8n8.x4.shared.b16 {%0,%1,%2,%3}, [%4];"
                 : "=r"(r[0]), "=r"(r[1]), "=r"(r[2]), "=r"(r[3]) : "r"(addr));
}

__device__ __forceinline__ void mma16816(float* d, const uint32_t* a, uint32_t b0, uint32_t b1) {
    asm volatile(
        "mma.sync.aligned.m16n8k16.row.col.f32.bf16.bf16.f32 "
        "{%0,%1,%2,%3}, {%4,%5,%6,%7}, {%8,%9}, {%0,%1,%2,%3};"
        : "+f"(d[0]), "+f"(d[1]), "+f"(d[2]), "+f"(d[3])
        : "r"(a[0]), "r"(a[1]), "r"(a[2]), "r"(a[3]), "r"(b0), "r"(b1));
}

// 128B-row XOR swizzle (conflict-free for ldmatrix + cp.async stores)
__device__ __forceinline__ uint32_t swz(uint32_t row, uint32_t colbyte) {
    return row * 128u + (colbyte ^ ((row & 7u) << 4));
}

// ---------------------------------------------------------------------------
// Projection (q,k): t[n,d] = sum_c W[d,c] x[b,c,n] + bias[d], emit bf16 hi/lo.
// ---------------------------------------------------------------------------
__global__ void proj_qk_kernel(const float* __restrict__ x,
                               const float* __restrict__ W,
                               const float* __restrict__ bias,
                               __nv_bfloat16* __restrict__ ohi,
                               __nv_bfloat16* __restrict__ olo) {
    const int b  = blockIdx.z;
    const int n0 = blockIdx.x * 64;
    const float* xb = x + (size_t)b * C_ * N_;

    __shared__ float xs[16][64];
    __shared__ float ws[16][65];

    const int tid = threadIdx.x;
    const int tx = tid & 15;   // d
    const int ty = tid >> 4;   // n

    float acc[4][4] = {};
    for (int c0 = 0; c0 < C_; c0 += 16) {
#pragma unroll
        for (int i = 0; i < 4; i++) {
            int idx = tid + i * 256;
            int kk = idx >> 6, col = idx & 63;
            xs[kk][col] = xb[(size_t)(c0 + kk) * N_ + n0 + col];
        }
#pragma unroll
        for (int i = 0; i < 4; i++) {
            int idx = tid + i * 256;
            int kk = idx & 15, d = idx >> 4;
            ws[kk][d] = W[(size_t)d * C_ + c0 + kk];
        }
        __syncthreads();
#pragma unroll
        for (int kk = 0; kk < 16; kk++) {
            float ar[4], br[4];
#pragma unroll
            for (int i = 0; i < 4; i++) ar[i] = xs[kk][ty + 16 * i];
#pragma unroll
            for (int j = 0; j < 4; j++) br[j] = ws[kk][tx + 16 * j];
#pragma unroll
            for (int i = 0; i < 4; i++)
#pragma unroll
                for (int j = 0; j < 4; j++) acc[i][j] += ar[i] * br[j];
        }
        __syncthreads();
    }
    const size_t ob = (size_t)b * N_ * D_;
#pragma unroll
    for (int i = 0; i < 4; i++) {
        int n = n0 + ty + 16 * i;
#pragma unroll
        for (int j = 0; j < 4; j++) {
            int d = tx + 16 * j;
            float val = acc[i][j] + bias[d];
            __nv_bfloat16 h = __float2bfloat16(val);
            ohi[ob + (size_t)n * D_ + d] = h;
            olo[ob + (size_t)n * D_ + d] = __float2bfloat16(val - __bfloat162float(h));
        }
    }
}

// ---------------------------------------------------------------------------
// Projection (v): bf16 hi/lo pair in [B,C,N] (n contiguous, K-major B operand)
// ---------------------------------------------------------------------------
__global__ void proj_v_kernel(const float* __restrict__ x,
                              const float* __restrict__ W,
                              const float* __restrict__ bias,
                              __nv_bfloat16* __restrict__ vhi,
                              __nv_bfloat16* __restrict__ vlo) {
    const int b  = blockIdx.z;
    const int n0 = blockIdx.x * 64;
    const int c0 = blockIdx.y * 64;
    const float* xb = x + (size_t)b * C_ * N_;

    __shared__ float xs[16][64];   // xs[kk][n]
    __shared__ float ws[16][65];   // ws[kk][c]

    const int tid = threadIdx.x;
    const int tx = tid & 15;   // n
    const int ty = tid >> 4;   // c

    float acc[4][4] = {};   // [c][n]
    for (int k0 = 0; k0 < C_; k0 += 16) {
#pragma unroll
        for (int i = 0; i < 4; i++) {
            int idx = tid + i * 256;
            int kk = idx >> 6, col = idx & 63;
            xs[kk][col] = xb[(size_t)(k0 + kk) * N_ + n0 + col];
        }
#pragma unroll
        for (int i = 0; i < 4; i++) {
            int idx = tid + i * 256;
            int kk = idx & 15, c = idx >> 4;
            ws[kk][c] = W[(size_t)(c0 + c) * C_ + k0 + kk];
        }
        __syncthreads();
#pragma unroll
        for (int kk = 0; kk < 16; kk++) {
            float ar[4], br[4];
#pragma unroll
            for (int i = 0; i < 4; i++) ar[i] = ws[kk][ty + 16 * i];
#pragma unroll
            for (int j = 0; j < 4; j++) br[j] = xs[kk][tx + 16 * j];
#pragma unroll
            for (int i = 0; i < 4; i++)
#pragma unroll
                for (int j = 0; j < 4; j++) acc[i][j] += ar[i] * br[j];
        }
        __syncthreads();
    }
#pragma unroll
    for (int i = 0; i < 4; i++) {
        int c = c0 + ty + 16 * i;
        float bv = bias[c];
        size_t rowbase = ((size_t)b * C_ + c) * N_ + n0;
#pragma unroll
        for (int j = 0; j < 4; j++) {
            float val = acc[i][j] + bv;
            __nv_bfloat16 h = __float2bfloat16(val);
            vhi[rowbase + tx + 16 * j] = h;
            vlo[rowbase + tx + 16 * j] = __float2bfloat16(val - __bfloat162float(h));
        }
    }
}

// ---------------------------------------------------------------------------
// Energy (HMMA): E[b,m,n] = sum_d q[b,m,d] k[b,n,d], compensated bf16 split.
// CTA 128m x 128n, 8 warps (64x32). K=64: single fill, hi group then lo group
// so hi*hi MMAs overlap the lo-group cp.async. Epilogue via smem transpose.
// smem: Ahi@0, Bhi@16K, Alo@32K, Blo@48K (16KB each, 128B rows, swizzled).
// ---------------------------------------------------------------------------
__global__ void __launch_bounds__(256)
energy_hmma_kernel(float* __restrict__ attn) {
    extern __shared__ char dynsmem[];
    const uint32_t sbase = smem_u32(dynsmem);

    const int tid  = threadIdx.x;
    const int wid  = tid >> 5;
    const int lane = tid & 31;

    const int b  = blockIdx.z;
    const int n0 = blockIdx.x * 128;
    const int m0 = blockIdx.y * 128;

    const __nv_bfloat16* Qhi = g_qhi + (size_t)b * N_ * D_;
    const __nv_bfloat16* Qlo = g_qlo + (size_t)b * N_ * D_;
    const __nv_bfloat16* Khi = g_khi + (size_t)b * N_ * D_;
    const __nv_bfloat16* Klo = g_klo + (size_t)b * N_ * D_;

    const int wm = (wid >> 2) * 64;
    const int wn = (wid & 3) * 32;

    const uint32_t lrow = lane & 15;
    const uint32_t lswz = (lane & 7) << 4;
    const uint32_t lcol = (lane >> 4) << 4;

    // ---- loads: hi group, then lo group ----
#pragma unroll
    for (int t = 0; t < 4; t++) {
        const int idx = tid + t * 256;
        const int row = idx >> 3, seg = idx & 7;
        cp16(sbase + swz(row, seg * 16), Qhi + (size_t)(m0 + row) * D_ + seg * 8);
        cp16(sbase + 16384 + swz(row, seg * 16), Khi + (size_t)(n0 + row) * D_ + seg * 8);
    }
    asm volatile("cp.async.commit_group;" ::: "memory");
#pragma unroll
    for (int t = 0; t < 4; t++) {
        const int idx = tid + t * 256;
        const int row = idx >> 3, seg = idx & 7;
        cp16(sbase + 32768 + swz(row, seg * 16), Qlo + (size_t)(m0 + row) * D_ + seg * 8);
        cp16(sbase + 49152 + swz(row, seg * 16), Klo + (size_t)(n0 + row) * D_ + seg * 8);
    }
    asm volatile("cp.async.commit_group;" ::: "memory");

    float acc[4][4][4] = {};

    // ---- pass 1: hi*hi ----
    asm volatile("cp.async.wait_group 1;" ::: "memory");
    __syncthreads();
#pragma unroll
    for (int ks = 0; ks < 4; ks++) {
        const uint32_t kb = (uint32_t)(ks * 32);
        uint32_t a[4][4], bm[2][4];
#pragma unroll
        for (int i = 0; i < 4; i++) {
            const uint32_t row = (uint32_t)(wm + i * 16) + lrow;
            ldsm4(a[i], sbase + row * 128u + ((kb + lcol) ^ lswz));
        }
#pragma unroll
        for (int j = 0; j < 2; j++) {
            const uint32_t row = (uint32_t)(wn + j * 16) + lrow;
            ldsm4(bm[j], sbase + 16384 + row * 128u + ((kb + lcol) ^ lswz));
        }
#pragma unroll
        for (int i = 0; i < 4; i++)
#pragma unroll
            for (int j = 0; j < 4; j++) {
                const int t2 = j >> 1, p2 = j & 1;
                mma16816(acc[i][j], a[i], bm[t2][p2], bm[t2][2 + p2]);
            }
    }

    // ---- pass 2: lo*hi + hi*lo ----
    asm volatile("cp.async.wait_group 0;" ::: "memory");
    __syncthreads();
#pragma unroll
    for (int ks = 0; ks < 4; ks++) {
        const uint32_t kb = (uint32_t)(ks * 32);
        uint32_t ah[4][4], al[4][4], bh[2][4], bl[2][4];
#pragma unroll
        for (int i = 0; i < 4; i++) {
            const uint32_t row = (uint32_t)(wm + i * 16) + lrow;
            ldsm4(ah[i], sbase + row * 128u + ((kb + lcol) ^ lswz));
            ldsm4(al[i], sbase + 32768 + row * 128u + ((kb + lcol) ^ lswz));
        }
#pragma unroll
        for (int j = 0; j < 2; j++) {
            const uint32_t row = (uint32_t)(wn + j * 16) + lrow;
            ldsm4(bh[j], sbase + 16384 + row * 128u + ((kb + lcol) ^ lswz));
            ldsm4(bl[j], sbase + 49152 + row * 128u + ((kb + lcol) ^ lswz));
        }
#pragma unroll
        for (int i = 0; i < 4; i++)
#pragma unroll
            for (int j = 0; j < 4; j++) {
                const int t2 = j >> 1, p2 = j & 1;
                mma16816(acc[i][j], al[i], bh[t2][p2], bh[t2][2 + p2]);
                mma16816(acc[i][j], ah[i], bl[t2][p2], bl[t2][2 + p2]);
            }
    }

    // ---- epilogue: smem transpose, coalesced fp32 stores ----
    __syncthreads();
    float* sOut = reinterpret_cast<float*>(dynsmem);
#pragma unroll
    for (int i = 0; i < 4; i++) {
        const int mt = wm + i * 16 + (lane >> 2);
#pragma unroll
        for (int j = 0; j < 4; j++) {
            const int nt = wn + j * 8 + (lane & 3) * 2;
            sOut[mt * EPI_P + nt]           = acc[i][j][0];
            sOut[mt * EPI_P + nt + 1]       = acc[i][j][1];
            sOut[(mt + 8) * EPI_P + nt]     = acc[i][j][2];
            sOut[(mt + 8) * EPI_P + nt + 1] = acc[i][j][3];
        }
    }
    __syncthreads();

    float* eb = attn + (size_t)b * N_ * N_;
    const int row = tid >> 1;
    const int col0 = (tid & 1) * 64;
    const float* srow = sOut + row * EPI_P + col0;
    float* grow = eb + (size_t)(m0 + row) * N_ + n0 + col0;
#pragma unroll
    for (int v = 0; v < 16; v++)
        *reinterpret_cast<float4*>(grow + v * 4) =
            *reinterpret_cast<const float4*>(srow + v * 4);
}

// ---------------------------------------------------------------------------
// Row softmax in place (vectorized); emit attn bf16 hi/lo (packed stores).
// ---------------------------------------------------------------------------
__global__ void softmax_kernel(float* __restrict__ attn,
                               __nv_bfloat16* __restrict__ ahi,
                               __nv_bfloat16* __restrict__ alo) {
    const size_t row = blockIdx.x;
    float* p = attn + row * N_;
    const int tid = threadIdx.x;

    float4 v[4];
    float mx = -3.0e38f;
#pragma unroll
    for (int i = 0; i < 4; i++) {
        v[i] = *reinterpret_cast<const float4*>(p + tid * 4 + i * 1024);
        mx = fmaxf(mx, fmaxf(fmaxf(v[i].x, v[i].y), fmaxf(v[i].z, v[i].w)));
    }
    __shared__ float red[8];
#pragma unroll
    for (int o = 16; o; o >>= 1) mx = fmaxf(mx, __shfl_xor_sync(0xffffffffu, mx, o));
    if ((tid & 31) == 0) red[tid >> 5] = mx;
    __syncthreads();
    mx = red[0];
#pragma unroll
    for (int i = 1; i < 8; i++) mx = fmaxf(mx, red[i]);
    __syncthreads();

    float s = 0.f;
#pragma unroll
    for (int i = 0; i < 4; i++) {
        v[i].x = __expf(v[i].x - mx); v[i].y = __expf(v[i].y - mx);
        v[i].z = __expf(v[i].z - mx); v[i].w = __expf(v[i].w - mx);
        s += (v[i].x + v[i].y) + (v[i].z + v[i].w);
    }
#pragma unroll
    for (int o = 16; o; o >>= 1) s += __shfl_xor_sync(0xffffffffu, s, o);
    if ((tid & 31) == 0) red[tid >> 5] = s;
    __syncthreads();
    s = 0.f;
#pragma unroll
    for (int i = 0; i < 8; i++) s += red[i];
    const float inv = 1.0f / s;

    __nv_bfloat16* ph = ahi + row * N_;
    __nv_bfloat16* pl = alo + row * N_;
#pragma unroll
    for (int i = 0; i < 4; i++) {
        float4 r;
        r.x = v[i].x * inv; r.y = v[i].y * inv; r.z = v[i].z * inv; r.w = v[i].w * inv;
        *reinterpret_cast<float4*>(p + tid * 4 + i * 1024) = r;

        __nv_bfloat162 h01 = __floats2bfloat162_rn(r.x, r.y);
        __nv_bfloat162 h23 = __floats2bfloat162_rn(r.z, r.w);
        float2 hf01 = __bfloat1622float2(h01);
        float2 hf23 = __bfloat1622float2(h23);
        __nv_bfloat162 l01 = __floats2bfloat162_rn(r.x - hf01.x, r.y - hf01.y);
        __nv_bfloat162 l23 = __floats2bfloat162_rn(r.z - hf23.x, r.w - hf23.y);

        uint2 hh, ll;
        hh.x = *reinterpret_cast<uint32_t*>(&h01);
        hh.y = *reinterpret_cast<uint32_t*>(&h23);
        ll.x = *reinterpret_cast<uint32_t*>(&l01);
        ll.y = *reinterpret_cast<uint32_t*>(&l23);
        *reinterpret_cast<uint2*>(ph + tid * 4 + i * 1024) = hh;
        *reinterpret_cast<uint2*>(pl + tid * 4 + i * 1024) = ll;
    }
}

// ---------------------------------------------------------------------------
// out[b,c,m] = gamma * sum_n attn[b,m,n] * v[b,c,n] + x[b,c,m]
// HMMA bf16, compensated split; 3-stage cp.async ring.
// ---------------------------------------------------------------------------
__global__ void __launch_bounds__(256, 1)
out_gemm_kernel(const float* __restrict__ x,
                const float* __restrict__ gamma,
                float* __restrict__ out) {
    extern __shared__ char dynsmem[];
    const uint32_t sbase = smem_u32(dynsmem);

    const int tid  = threadIdx.x;
    const int wid  = tid >> 5;
    const int lane = tid & 31;

    const int b  = blockIdx.z;
    const int c0 = blockIdx.x * 128;
    const int m0 = blockIdx.y * 128;

    const __nv_bfloat16* Ahi = g_ahi + (size_t)b * N_ * N_;
    const __nv_bfloat16* Alo = g_alo + (size_t)b * N_ * N_;
    const __nv_bfloat16* Bhi = g_vhi + (size_t)b * C_ * N_;
    const __nv_bfloat16* Blo = g_vlo + (size_t)b * C_ * N_;

    const int wm = (wid >> 2) * 64;
    const int wc = (wid & 3) * 32;

    const int prow = tid >> 3;
    const int pseg = tid & 7;

    const uint32_t lrow = lane & 15;
    const uint32_t lswz = (lane & 7) << 4;
    const uint32_t lcol = (lane >> 4) << 4;

    float acc[4][4][4] = {};

    auto load_chunk = [&](int kc) {
        const uint32_t st = (uint32_t)(kc % 3) * STAGE;
        const uint32_t Ab = sbase + st, Bb = Ab + 16384;
        const size_t koff = (size_t)kc * KC;
#pragma unroll
        for (int t = 0; t < 4; t++) {
            const int row = prow + t * 32;
            const uint32_t dcol = (uint32_t)(pseg * 16);
            cp16(Ab + swz(row, dcol),
                 (pseg < 4 ? Ahi : Alo) + (size_t)(m0 + row) * N_ + koff + (pseg & 3) * 8);
            cp16(Bb + swz(row, dcol),
                 (pseg < 4 ? Bhi : Blo) + (size_t)(c0 + row) * N_ + koff + (pseg & 3) * 8);
        }
        asm volatile("cp.async.commit_group;" ::: "memory");
    };

    load_chunk(0);
    load_chunk(1);

    for (int kc = 0; kc < NCHUNK; kc++) {
        if (kc + 2 < NCHUNK) {
            load_chunk(kc + 2);
            asm volatile("cp.async.wait_group 2;" ::: "memory");
        } else if (kc + 1 < NCHUNK) {
            asm volatile("cp.async.wait_group 1;" ::: "memory");
        } else {
            asm volatile("cp.async.wait_group 0;" ::: "memory");
        }
        __syncthreads();

        const uint32_t st = (uint32_t)(kc % 3) * STAGE;
        const uint32_t Ab = sbase + st, Bb = Ab + 16384;

#pragma unroll
        for (int ks = 0; ks < 2; ks++) {
            const uint32_t kbHi = (uint32_t)(ks * 32);
            const uint32_t kbLo = 64u + kbHi;

            uint32_t ahi[4][4], alo[4][4], bhi[2][4], blo[2][4];
#pragma unroll
            for (int i = 0; i < 4; i++) {
                const uint32_t row = (uint32_t)(wm + i * 16) + lrow;
                ldsm4(ahi[i], Ab + row * 128u + ((kbHi + lcol) ^ lswz));
                ldsm4(alo[i], Ab + row * 128u + ((kbLo + lcol) ^ lswz));
            }
#pragma unroll
            for (int j = 0; j < 2; j++) {
                const uint32_t row = (uint32_t)(wc + j * 16) + lrow;
                ldsm4(bhi[j], Bb + row * 128u + ((kbHi + lcol) ^ lswz));
                ldsm4(blo[j], Bb + row * 128u + ((kbLo + lcol) ^ lswz));
            }
#pragma unroll
            for (int i = 0; i < 4; i++)
#pragma unroll
                for (int j = 0; j < 4; j++) {
                    const int t2 = j >> 1, p2 = j & 1;
                    mma16816(acc[i][j], ahi[i], bhi[t2][p2], bhi[t2][2 + p2]);
                    mma16816(acc[i][j], alo[i], bhi[t2][p2], bhi[t2][2 + p2]);
                    mma16816(acc[i][j], ahi[i], blo[t2][p2], blo[t2][2 + p2]);
                }
        }
        __syncthreads();
    }

    // ---- epilogue: transpose through smem, fused gamma*acc + x ----
    float* sOut = reinterpret_cast<float*>(dynsmem);
#pragma unroll
    for (int i = 0; i < 4; i++) {
        const int mt = wm + i * 16 + (lane >> 2);
#pragma unroll
        for (int j = 0; j < 4; j++) {
            const int ct = wc + j * 8 + (lane & 3) * 2;
            sOut[ct * EPI_P + mt]           = acc[i][j][0];
            sOut[(ct + 1) * EPI_P + mt]     = acc[i][j][1];
            sOut[ct * EPI_P + mt + 8]       = acc[i][j][2];
            sOut[(ct + 1) * EPI_P + mt + 8] = acc[i][j][3];
        }
    }
    __syncthreads();

    const float g = gamma[0];
    const int ce = tid >> 1;
    const int me = (tid & 1) * 64;
    const size_t gb = ((size_t)b * C_ + c0 + ce) * N_ + m0 + me;
    const float* srow = sOut + ce * EPI_P + me;
#pragma unroll
    for (int v = 0; v < 16; v++) {
        const float4 xv = *reinterpret_cast<const float4*>(x + gb + v * 4);
        float4 ov;
        ov.x = g * srow[v * 4 + 0] + xv.x;
        ov.y = g * srow[v * 4 + 1] + xv.y;
        ov.z = g * srow[v * 4 + 2] + xv.z;
        ov.w = g * srow[v * 4 + 3] + xv.w;
        *reinterpret_cast<float4*>(out + gb + v * 4) = ov;
    }
}

// ---------------------------------------------------------------------------
extern "C" void kernel_launch(void* const* d_in, const int* in_sizes, int n_in,
                              void* d_out, int out_size) {
    (void)in_sizes; (void)n_in; (void)out_size;
    const float* x     = (const float*)d_in[0];
    const float* Wq    = (const float*)d_in[1];
    const float* bq    = (const float*)d_in[2];
    const float* Wk    = (const float*)d_in[3];
    const float* bk    = (const float*)d_in[4];
    const float* Wv    = (const float*)d_in[5];
    const float* bv    = (const float*)d_in[6];
    const float* gamma = (const float*)d_in[7];

    float* out  = (float*)d_out;
    float* attn = out + (size_t)B_ * C_ * N_;   // tuple order: (out, attention)

    __nv_bfloat16 *qhi, *qlo, *khi, *klo, *vhi, *vlo, *ahi, *alo;
    cudaGetSymbolAddress((void**)&qhi, g_qhi);
    cudaGetSymbolAddress((void**)&qlo, g_qlo);
    cudaGetSymbolAddress((void**)&khi, g_khi);
    cudaGetSymbolAddress((void**)&klo, g_klo);
    cudaGetSymbolAddress((void**)&vhi, g_vhi);
    cudaGetSymbolAddress((void**)&vlo, g_vlo);
    cudaGetSymbolAddress((void**)&ahi, g_ahi);
    cudaGetSymbolAddress((void**)&alo, g_alo);

    cudaFuncSetAttribute(out_gemm_kernel,
                         cudaFuncAttributeMaxDynamicSharedMemorySize, DYN_OUT);
    cudaFuncSetAttribute(energy_hmma_kernel,
                         cudaFuncAttributeMaxDynamicSharedMemorySize, DYN_E);

    dim3 blk(256);
    proj_qk_kernel<<<dim3(N_ / 64, 1, B_), blk>>>(x, Wq, bq, qhi, qlo);
    proj_qk_kernel<<<dim3(N_ / 64, 1, B_), blk>>>(x, Wk, bk, khi, klo);
    proj_v_kernel<<<dim3(N_ / 64, C_ / 64, B_), blk>>>(x, Wv, bv, vhi, vlo);
    energy_hmma_kernel<<<dim3(N_ / 128, N_ / 128, B_), blk, DYN_E>>>(attn);
    softmax_kernel<<<dim3(B_ * N_), blk>>>(attn, ahi, alo);
    out_gemm_kernel<<<dim3(C_ / 128, N_ / 128, B_), blk, DYN_OUT>>>(x, gamma, out);
}

// round 5
// speedup vs baseline: 2.5066x; 1.0584x over previous
#include <cuda_runtime.h>
#include <cuda_bf16.h>
#include <cstdint>

// Self_Attn: B=4, C=512, N=4096 (64x64), D=64
// Outputs (tuple order): out [B,C,64,64] fp32, attention [B,N,N] fp32.

namespace {
constexpr int B_ = 4;
constexpr int C_ = 512;
constexpr int N_ = 4096;
constexpr int D_ = 64;

constexpr int KC = 32;             // out-GEMM K elems per chunk
constexpr int NCHUNK = N_ / KC;    // 128
constexpr int STAGE = 32768;       // out-GEMM stage: A 16KB + B 16KB
constexpr int EPI_P = 132;         // epilogue smem pitch (floats)
constexpr int DYN_OUT = 3 * STAGE; // 98304; half-epilogue (33.8KB) reuses stage 0
constexpr int DYN_E = 128 * EPI_P * 4;  // 67584 (> 64KB tiles)
}

// Scratch (device globals; no runtime allocation allowed).
__device__ __nv_bfloat16 g_qhi[B_ * N_ * D_];           // [B][N][D]
__device__ __nv_bfloat16 g_qlo[B_ * N_ * D_];
__device__ __nv_bfloat16 g_khi[B_ * N_ * D_];
__device__ __nv_bfloat16 g_klo[B_ * N_ * D_];
__device__ __nv_bfloat16 g_vhi[(size_t)B_ * C_ * N_];   // [B][C][N] K-major
__device__ __nv_bfloat16 g_vlo[(size_t)B_ * C_ * N_];
__device__ __nv_bfloat16 g_ahi[(size_t)B_ * N_ * N_];   // [B][M][N] K-major
__device__ __nv_bfloat16 g_alo[(size_t)B_ * N_ * N_];

// ---------------------------------------------------------------------------
// helpers
// ---------------------------------------------------------------------------
__device__ __forceinline__ uint32_t smem_u32(const void* p) {
    uint32_t a;
    asm("{ .reg .u64 t; cvta.to.shared.u64 t, %1; cvt.u32.u64 %0, t; }" : "=r"(a) : "l"(p));
    return a;
}

__device__ __forceinline__ void cp16(uint32_t dst, const void* src) {
    asm volatile("cp.async.cg.shared.global [%0], [%1], 16;" :: "r"(dst), "l"(src) : "memory");
}

__device__ __forceinline__ void ldsm4(uint32_t* r, uint32_t addr) {
    asm volatile("ldmatrix.sync.aligned.m8n8.x4.shared.b16 {%0,%1,%2,%3}, [%4];"
                 : "=r"(r[0]), "=r"(r[1]), "=r"(r[2]), "=r"(r[3]) : "r"(addr));
}

__device__ __forceinline__ void mma16816(float* d, const uint32_t* a, uint32_t b0, uint32_t b1) {
    asm volatile(
        "mma.sync.aligned.m16n8k16.row.col.f32.bf16.bf16.f32 "
        "{%0,%1,%2,%3}, {%4,%5,%6,%7}, {%8,%9}, {%0,%1,%2,%3};"
        : "+f"(d[0]), "+f"(d[1]), "+f"(d[2]), "+f"(d[3])
        : "r"(a[0]), "r"(a[1]), "r"(a[2]), "r"(a[3]), "r"(b0), "r"(b1));
}

// 128B-row XOR swizzle (conflict-free for ldmatrix + cp.async stores)
__device__ __forceinline__ uint32_t swz(uint32_t row, uint32_t colbyte) {
    return row * 128u + (colbyte ^ ((row & 7u) << 4));
}

// ---------------------------------------------------------------------------
// Projection (q,k): t[n,d] = sum_c W[d,c] x[b,c,n] + bias[d], emit bf16 hi/lo.
// ---------------------------------------------------------------------------
__global__ void proj_qk_kernel(const float* __restrict__ x,
                               const float* __restrict__ W,
                               const float* __restrict__ bias,
                               __nv_bfloat16* __restrict__ ohi,
                               __nv_bfloat16* __restrict__ olo) {
    const int b  = blockIdx.z;
    const int n0 = blockIdx.x * 64;
    const float* xb = x + (size_t)b * C_ * N_;

    __shared__ float xs[16][64];
    __shared__ float ws[16][65];

    const int tid = threadIdx.x;
    const int tx = tid & 15;   // d
    const int ty = tid >> 4;   // n

    float acc[4][4] = {};
    for (int c0 = 0; c0 < C_; c0 += 16) {
#pragma unroll
        for (int i = 0; i < 4; i++) {
            int idx = tid + i * 256;
            int kk = idx >> 6, col = idx & 63;
            xs[kk][col] = xb[(size_t)(c0 + kk) * N_ + n0 + col];
        }
#pragma unroll
        for (int i = 0; i < 4; i++) {
            int idx = tid + i * 256;
            int kk = idx & 15, d = idx >> 4;
            ws[kk][d] = W[(size_t)d * C_ + c0 + kk];
        }
        __syncthreads();
#pragma unroll
        for (int kk = 0; kk < 16; kk++) {
            float ar[4], br[4];
#pragma unroll
            for (int i = 0; i < 4; i++) ar[i] = xs[kk][ty + 16 * i];
#pragma unroll
            for (int j = 0; j < 4; j++) br[j] = ws[kk][tx + 16 * j];
#pragma unroll
            for (int i = 0; i < 4; i++)
#pragma unroll
                for (int j = 0; j < 4; j++) acc[i][j] += ar[i] * br[j];
        }
        __syncthreads();
    }
    const size_t ob = (size_t)b * N_ * D_;
#pragma unroll
    for (int i = 0; i < 4; i++) {
        int n = n0 + ty + 16 * i;
#pragma unroll
        for (int j = 0; j < 4; j++) {
            int d = tx + 16 * j;
            float val = acc[i][j] + bias[d];
            __nv_bfloat16 h = __float2bfloat16(val);
            ohi[ob + (size_t)n * D_ + d] = h;
            olo[ob + (size_t)n * D_ + d] = __float2bfloat16(val - __bfloat162float(h));
        }
    }
}

// ---------------------------------------------------------------------------
// Projection (v): bf16 hi/lo pair in [B,C,N] (n contiguous, K-major B operand)
// ---------------------------------------------------------------------------
__global__ void proj_v_kernel(const float* __restrict__ x,
                              const float* __restrict__ W,
                              const float* __restrict__ bias,
                              __nv_bfloat16* __restrict__ vhi,
                              __nv_bfloat16* __restrict__ vlo) {
    const int b  = blockIdx.z;
    const int n0 = blockIdx.x * 64;
    const int c0 = blockIdx.y * 64;
    const float* xb = x + (size_t)b * C_ * N_;

    __shared__ float xs[16][64];   // xs[kk][n]
    __shared__ float ws[16][65];   // ws[kk][c]

    const int tid = threadIdx.x;
    const int tx = tid & 15;   // n
    const int ty = tid >> 4;   // c

    float acc[4][4] = {};   // [c][n]
    for (int k0 = 0; k0 < C_; k0 += 16) {
#pragma unroll
        for (int i = 0; i < 4; i++) {
            int idx = tid + i * 256;
            int kk = idx >> 6, col = idx & 63;
            xs[kk][col] = xb[(size_t)(k0 + kk) * N_ + n0 + col];
        }
#pragma unroll
        for (int i = 0; i < 4; i++) {
            int idx = tid + i * 256;
            int kk = idx & 15, c = idx >> 4;
            ws[kk][c] = W[(size_t)(c0 + c) * C_ + k0 + kk];
        }
        __syncthreads();
#pragma unroll
        for (int kk = 0; kk < 16; kk++) {
            float ar[4], br[4];
#pragma unroll
            for (int i = 0; i < 4; i++) ar[i] = ws[kk][ty + 16 * i];
#pragma unroll
            for (int j = 0; j < 4; j++) br[j] = xs[kk][tx + 16 * j];
#pragma unroll
            for (int i = 0; i < 4; i++)
#pragma unroll
                for (int j = 0; j < 4; j++) acc[i][j] += ar[i] * br[j];
        }
        __syncthreads();
    }
#pragma unroll
    for (int i = 0; i < 4; i++) {
        int c = c0 + ty + 16 * i;
        float bv = bias[c];
        size_t rowbase = ((size_t)b * C_ + c) * N_ + n0;
#pragma unroll
        for (int j = 0; j < 4; j++) {
            float val = acc[i][j] + bv;
            __nv_bfloat16 h = __float2bfloat16(val);
            vhi[rowbase + tx + 16 * j] = h;
            vlo[rowbase + tx + 16 * j] = __float2bfloat16(val - __bfloat162float(h));
        }
    }
}

// ---------------------------------------------------------------------------
// Energy (HMMA): E[b,m,n] = sum_d q[b,m,d] k[b,n,d], compensated bf16 split.
// CTA 128m x 128n, 8 warps (64x32). K=64: hi group then lo group so hi*hi
// MMAs overlap the lo-group cp.async. Epilogue via smem transpose.
// ---------------------------------------------------------------------------
__global__ void __launch_bounds__(256)
energy_hmma_kernel(float* __restrict__ attn) {
    extern __shared__ char dynsmem[];
    const uint32_t sbase = smem_u32(dynsmem);

    const int tid  = threadIdx.x;
    const int wid  = tid >> 5;
    const int lane = tid & 31;

    const int b  = blockIdx.z;
    const int n0 = blockIdx.x * 128;
    const int m0 = blockIdx.y * 128;

    const __nv_bfloat16* Qhi = g_qhi + (size_t)b * N_ * D_;
    const __nv_bfloat16* Qlo = g_qlo + (size_t)b * N_ * D_;
    const __nv_bfloat16* Khi = g_khi + (size_t)b * N_ * D_;
    const __nv_bfloat16* Klo = g_klo + (size_t)b * N_ * D_;

    const int wm = (wid >> 2) * 64;
    const int wn = (wid & 3) * 32;

    const uint32_t lrow = lane & 15;
    const uint32_t lswz = (lane & 7) << 4;
    const uint32_t lcol = (lane >> 4) << 4;

#pragma unroll
    for (int t = 0; t < 4; t++) {
        const int idx = tid + t * 256;
        const int row = idx >> 3, seg = idx & 7;
        cp16(sbase + swz(row, seg * 16), Qhi + (size_t)(m0 + row) * D_ + seg * 8);
        cp16(sbase + 16384 + swz(row, seg * 16), Khi + (size_t)(n0 + row) * D_ + seg * 8);
    }
    asm volatile("cp.async.commit_group;" ::: "memory");
#pragma unroll
    for (int t = 0; t < 4; t++) {
        const int idx = tid + t * 256;
        const int row = idx >> 3, seg = idx & 7;
        cp16(sbase + 32768 + swz(row, seg * 16), Qlo + (size_t)(m0 + row) * D_ + seg * 8);
        cp16(sbase + 49152 + swz(row, seg * 16), Klo + (size_t)(n0 + row) * D_ + seg * 8);
    }
    asm volatile("cp.async.commit_group;" ::: "memory");

    float acc[4][4][4] = {};

    asm volatile("cp.async.wait_group 1;" ::: "memory");
    __syncthreads();
#pragma unroll
    for (int ks = 0; ks < 4; ks++) {
        const uint32_t kb = (uint32_t)(ks * 32);
        uint32_t a[4][4], bm[2][4];
#pragma unroll
        for (int i = 0; i < 4; i++) {
            const uint32_t row = (uint32_t)(wm + i * 16) + lrow;
            ldsm4(a[i], sbase + row * 128u + ((kb + lcol) ^ lswz));
        }
#pragma unroll
        for (int j = 0; j < 2; j++) {
            const uint32_t row = (uint32_t)(wn + j * 16) + lrow;
            ldsm4(bm[j], sbase + 16384 + row * 128u + ((kb + lcol) ^ lswz));
        }
#pragma unroll
        for (int i = 0; i < 4; i++)
#pragma unroll
            for (int j = 0; j < 4; j++) {
                const int t2 = j >> 1, p2 = j & 1;
                mma16816(acc[i][j], a[i], bm[t2][p2], bm[t2][2 + p2]);
            }
    }

    asm volatile("cp.async.wait_group 0;" ::: "memory");
    __syncthreads();
#pragma unroll
    for (int ks = 0; ks < 4; ks++) {
        const uint32_t kb = (uint32_t)(ks * 32);
        uint32_t ah[4][4], al[4][4], bh[2][4], bl[2][4];
#pragma unroll
        for (int i = 0; i < 4; i++) {
            const uint32_t row = (uint32_t)(wm + i * 16) + lrow;
            ldsm4(ah[i], sbase + row * 128u + ((kb + lcol) ^ lswz));
            ldsm4(al[i], sbase + 32768 + row * 128u + ((kb + lcol) ^ lswz));
        }
#pragma unroll
        for (int j = 0; j < 2; j++) {
            const uint32_t row = (uint32_t)(wn + j * 16) + lrow;
            ldsm4(bh[j], sbase + 16384 + row * 128u + ((kb + lcol) ^ lswz));
            ldsm4(bl[j], sbase + 49152 + row * 128u + ((kb + lcol) ^ lswz));
        }
#pragma unroll
        for (int i = 0; i < 4; i++)
#pragma unroll
            for (int j = 0; j < 4; j++) {
                const int t2 = j >> 1, p2 = j & 1;
                mma16816(acc[i][j], al[i], bh[t2][p2], bh[t2][2 + p2]);
                mma16816(acc[i][j], ah[i], bl[t2][p2], bl[t2][2 + p2]);
            }
    }

    __syncthreads();
    float* sOut = reinterpret_cast<float*>(dynsmem);
#pragma unroll
    for (int i = 0; i < 4; i++) {
        const int mt = wm + i * 16 + (lane >> 2);
#pragma unroll
        for (int j = 0; j < 4; j++) {
            const int nt = wn + j * 8 + (lane & 3) * 2;
            sOut[mt * EPI_P + nt]           = acc[i][j][0];
            sOut[mt * EPI_P + nt + 1]       = acc[i][j][1];
            sOut[(mt + 8) * EPI_P + nt]     = acc[i][j][2];
            sOut[(mt + 8) * EPI_P + nt + 1] = acc[i][j][3];
        }
    }
    __syncthreads();

    float* eb = attn + (size_t)b * N_ * N_;
    const int row = tid >> 1;
    const int col0 = (tid & 1) * 64;
    const float* srow = sOut + row * EPI_P + col0;
    float* grow = eb + (size_t)(m0 + row) * N_ + n0 + col0;
#pragma unroll
    for (int v = 0; v < 16; v++)
        *reinterpret_cast<float4*>(grow + v * 4) =
            *reinterpret_cast<const float4*>(srow + v * 4);
}

// ---------------------------------------------------------------------------
// Row softmax in place (vectorized); emit attn bf16 hi/lo (packed stores).
// ---------------------------------------------------------------------------
__global__ void softmax_kernel(float* __restrict__ attn,
                               __nv_bfloat16* __restrict__ ahi,
                               __nv_bfloat16* __restrict__ alo) {
    const size_t row = blockIdx.x;
    float* p = attn + row * N_;
    const int tid = threadIdx.x;

    float4 v[4];
    float mx = -3.0e38f;
#pragma unroll
    for (int i = 0; i < 4; i++) {
        v[i] = *reinterpret_cast<const float4*>(p + tid * 4 + i * 1024);
        mx = fmaxf(mx, fmaxf(fmaxf(v[i].x, v[i].y), fmaxf(v[i].z, v[i].w)));
    }
    __shared__ float red[8];
#pragma unroll
    for (int o = 16; o; o >>= 1) mx = fmaxf(mx, __shfl_xor_sync(0xffffffffu, mx, o));
    if ((tid & 31) == 0) red[tid >> 5] = mx;
    __syncthreads();
    mx = red[0];
#pragma unroll
    for (int i = 1; i < 8; i++) mx = fmaxf(mx, red[i]);
    __syncthreads();

    float s = 0.f;
#pragma unroll
    for (int i = 0; i < 4; i++) {
        v[i].x = __expf(v[i].x - mx); v[i].y = __expf(v[i].y - mx);
        v[i].z = __expf(v[i].z - mx); v[i].w = __expf(v[i].w - mx);
        s += (v[i].x + v[i].y) + (v[i].z + v[i].w);
    }
#pragma unroll
    for (int o = 16; o; o >>= 1) s += __shfl_xor_sync(0xffffffffu, s, o);
    if ((tid & 31) == 0) red[tid >> 5] = s;
    __syncthreads();
    s = 0.f;
#pragma unroll
    for (int i = 0; i < 8; i++) s += red[i];
    const float inv = 1.0f / s;

    __nv_bfloat16* ph = ahi + row * N_;
    __nv_bfloat16* pl = alo + row * N_;
#pragma unroll
    for (int i = 0; i < 4; i++) {
        float4 r;
        r.x = v[i].x * inv; r.y = v[i].y * inv; r.z = v[i].z * inv; r.w = v[i].w * inv;
        *reinterpret_cast<float4*>(p + tid * 4 + i * 1024) = r;

        __nv_bfloat162 h01 = __floats2bfloat162_rn(r.x, r.y);
        __nv_bfloat162 h23 = __floats2bfloat162_rn(r.z, r.w);
        float2 hf01 = __bfloat1622float2(h01);
        float2 hf23 = __bfloat1622float2(h23);
        __nv_bfloat162 l01 = __floats2bfloat162_rn(r.x - hf01.x, r.y - hf01.y);
        __nv_bfloat162 l23 = __floats2bfloat162_rn(r.z - hf23.x, r.w - hf23.y);

        uint2 hh, ll;
        hh.x = *reinterpret_cast<uint32_t*>(&h01);
        hh.y = *reinterpret_cast<uint32_t*>(&h23);
        ll.x = *reinterpret_cast<uint32_t*>(&l01);
        ll.y = *reinterpret_cast<uint32_t*>(&l23);
        *reinterpret_cast<uint2*>(ph + tid * 4 + i * 1024) = hh;
        *reinterpret_cast<uint2*>(pl + tid * 4 + i * 1024) = ll;
    }
}

// ---------------------------------------------------------------------------
// out[b,c,m] = gamma * sum_n attn[b,m,n] * v[b,c,n] + x[b,c,m]
// HMMA bf16, compensated split; 3-stage cp.async ring; 2 CTAs/SM.
// Epilogue transposes in TWO 64-col halves (33.8KB) so smem stays 98.3KB.
// ---------------------------------------------------------------------------
__global__ void __launch_bounds__(256, 2)
out_gemm_kernel(const float* __restrict__ x,
                const float* __restrict__ gamma,
                float* __restrict__ out) {
    extern __shared__ char dynsmem[];
    const uint32_t sbase = smem_u32(dynsmem);

    const int tid  = threadIdx.x;
    const int wid  = tid >> 5;
    const int lane = tid & 31;

    const int b  = blockIdx.z;
    const int c0 = blockIdx.x * 128;
    const int m0 = blockIdx.y * 128;

    const __nv_bfloat16* Ahi = g_ahi + (size_t)b * N_ * N_;
    const __nv_bfloat16* Alo = g_alo + (size_t)b * N_ * N_;
    const __nv_bfloat16* Bhi = g_vhi + (size_t)b * C_ * N_;
    const __nv_bfloat16* Blo = g_vlo + (size_t)b * C_ * N_;

    const int wm = (wid >> 2) * 64;
    const int wc = (wid & 3) * 32;

    const int prow = tid >> 3;
    const int pseg = tid & 7;

    const uint32_t lrow = lane & 15;
    const uint32_t lswz = (lane & 7) << 4;
    const uint32_t lcol = (lane >> 4) << 4;

    float acc[4][4][4] = {};

    auto load_chunk = [&](int kc) {
        const uint32_t st = (uint32_t)(kc % 3) * STAGE;
        const uint32_t Ab = sbase + st, Bb = Ab + 16384;
        const size_t koff = (size_t)kc * KC;
#pragma unroll
        for (int t = 0; t < 4; t++) {
            const int row = prow + t * 32;
            const uint32_t dcol = (uint32_t)(pseg * 16);
            cp16(Ab + swz(row, dcol),
                 (pseg < 4 ? Ahi : Alo) + (size_t)(m0 + row) * N_ + koff + (pseg & 3) * 8);
            cp16(Bb + swz(row, dcol),
                 (pseg < 4 ? Bhi : Blo) + (size_t)(c0 + row) * N_ + koff + (pseg & 3) * 8);
        }
        asm volatile("cp.async.commit_group;" ::: "memory");
    };

    load_chunk(0);
    load_chunk(1);

    for (int kc = 0; kc < NCHUNK; kc++) {
        if (kc + 2 < NCHUNK) {
            load_chunk(kc + 2);
            asm volatile("cp.async.wait_group 2;" ::: "memory");
        } else if (kc + 1 < NCHUNK) {
            asm volatile("cp.async.wait_group 1;" ::: "memory");
        } else {
            asm volatile("cp.async.wait_group 0;" ::: "memory");
        }
        __syncthreads();

        const uint32_t st = (uint32_t)(kc % 3) * STAGE;
        const uint32_t Ab = sbase + st, Bb = Ab + 16384;

#pragma unroll
        for (int ks = 0; ks < 2; ks++) {
            const uint32_t kbHi = (uint32_t)(ks * 32);
            const uint32_t kbLo = 64u + kbHi;

            uint32_t ahi[4][4], alo[4][4], bhi[2][4], blo[2][4];
#pragma unroll
            for (int i = 0; i < 4; i++) {
                const uint32_t row = (uint32_t)(wm + i * 16) + lrow;
                ldsm4(ahi[i], Ab + row * 128u + ((kbHi + lcol) ^ lswz));
                ldsm4(alo[i], Ab + row * 128u + ((kbLo + lcol) ^ lswz));
            }
#pragma unroll
            for (int j = 0; j < 2; j++) {
                const uint32_t row = (uint32_t)(wc + j * 16) + lrow;
                ldsm4(bhi[j], Bb + row * 128u + ((kbHi + lcol) ^ lswz));
                ldsm4(blo[j], Bb + row * 128u + ((kbLo + lcol) ^ lswz));
            }
#pragma unroll
            for (int i = 0; i < 4; i++)
#pragma unroll
                for (int j = 0; j < 4; j++) {
                    const int t2 = j >> 1, p2 = j & 1;
                    mma16816(acc[i][j], ahi[i], bhi[t2][p2], bhi[t2][2 + p2]);
                    mma16816(acc[i][j], alo[i], bhi[t2][p2], bhi[t2][2 + p2]);
                    mma16816(acc[i][j], ahi[i], blo[t2][p2], blo[t2][2 + p2]);
                }
        }
        __syncthreads();
    }

    // ---- epilogue: two 64-col halves; transpose via smem (33.8KB reuse) ----
    float* sOut = reinterpret_cast<float*>(dynsmem);
    const float g = gamma[0];
#pragma unroll
    for (int h = 0; h < 2; h++) {
        if (((wid & 3) >> 1) == h) {
            const int cbase = wc - h * 64;   // 0 or 32 within the half
#pragma unroll
            for (int i = 0; i < 4; i++) {
                const int mt = wm + i * 16 + (lane >> 2);
#pragma unroll
                for (int j = 0; j < 4; j++) {
                    const int ct = cbase + j * 8 + (lane & 3) * 2;
                    sOut[ct * EPI_P + mt]           = acc[i][j][0];
                    sOut[(ct + 1) * EPI_P + mt]     = acc[i][j][1];
                    sOut[ct * EPI_P + mt + 8]       = acc[i][j][2];
                    sOut[(ct + 1) * EPI_P + mt + 8] = acc[i][j][3];
                }
            }
        }
        __syncthreads();

        const int ce = tid >> 2;             // 0..63 (c within half)
        const int me = (tid & 3) * 32;       // m offset
        const size_t gb = ((size_t)b * C_ + c0 + h * 64 + ce) * N_ + m0 + me;
        const float* srow = sOut + ce * EPI_P + me;
#pragma unroll
        for (int v = 0; v < 8; v++) {
            const float4 xv = *reinterpret_cast<const float4*>(x + gb + v * 4);
            float4 ov;
            ov.x = g * srow[v * 4 + 0] + xv.x;
            ov.y = g * srow[v * 4 + 1] + xv.y;
            ov.z = g * srow[v * 4 + 2] + xv.z;
            ov.w = g * srow[v * 4 + 3] + xv.w;
            *reinterpret_cast<float4*>(out + gb + v * 4) = ov;
        }
        __syncthreads();
    }
}

// ---------------------------------------------------------------------------
extern "C" void kernel_launch(void* const* d_in, const int* in_sizes, int n_in,
                              void* d_out, int out_size) {
    (void)in_sizes; (void)n_in; (void)out_size;
    const float* x     = (const float*)d_in[0];
    const float* Wq    = (const float*)d_in[1];
    const float* bq    = (const float*)d_in[2];
    const float* Wk    = (const float*)d_in[3];
    const float* bk    = (const float*)d_in[4];
    const float* Wv    = (const float*)d_in[5];
    const float* bv    = (const float*)d_in[6];
    const float* gamma = (const float*)d_in[7];

    float* out  = (float*)d_out;
    float* attn = out + (size_t)B_ * C_ * N_;   // tuple order: (out, attention)

    __nv_bfloat16 *qhi, *qlo, *khi, *klo, *vhi, *vlo, *ahi, *alo;
    cudaGetSymbolAddress((void**)&qhi, g_qhi);
    cudaGetSymbolAddress((void**)&qlo, g_qlo);
    cudaGetSymbolAddress((void**)&khi, g_khi);
    cudaGetSymbolAddress((void**)&klo, g_klo);
    cudaGetSymbolAddress((void**)&vhi, g_vhi);
    cudaGetSymbolAddress((void**)&vlo, g_vlo);
    cudaGetSymbolAddress((void**)&ahi, g_ahi);
    cudaGetSymbolAddress((void**)&alo, g_alo);

    cudaFuncSetAttribute(out_gemm_kernel,
                         cudaFuncAttributeMaxDynamicSharedMemorySize, DYN_OUT);
    cudaFuncSetAttribute(energy_hmma_kernel,
                         cudaFuncAttributeMaxDynamicSharedMemorySize, DYN_E);

    dim3 blk(256);
    proj_qk_kernel<<<dim3(N_ / 64, 1, B_), blk>>>(x, Wq, bq, qhi, qlo);
    proj_qk_kernel<<<dim3(N_ / 64, 1, B_), blk>>>(x, Wk, bk, khi, klo);
    proj_v_kernel<<<dim3(N_ / 64, C_ / 64, B_), blk>>>(x, Wv, bv, vhi, vlo);
    energy_hmma_kernel<<<dim3(N_ / 128, N_ / 128, B_), blk, DYN_E>>>(attn);
    softmax_kernel<<<dim3(B_ * N_), blk>>>(attn, ahi, alo);
    out_gemm_kernel<<<dim3(C_ / 128, N_ / 128, B_), blk, DYN_OUT>>>(x, gamma, out);
}

// round 6
// speedup vs baseline: 3.1480x; 1.2559x over previous
#include <cuda_runtime.h>
#include <cuda_bf16.h>
#include <cuda_fp16.h>
#include <cstdint>

// Self_Attn: B=4, C=512, N=4096 (64x64), D=64
// Outputs (tuple order): out [B,C,64,64] fp32, attention [B,N,N] fp32.

namespace {
constexpr int B_ = 4;
constexpr int C_ = 512;
constexpr int N_ = 4096;
constexpr int D_ = 64;

constexpr int KC = 64;             // out-GEMM K elems per chunk (128B fp16 row)
constexpr int NCHUNK = N_ / KC;    // 64
constexpr int STAGE = 49152;       // A 16K + Vhi 16K + Vlo 16K
constexpr int EPI_P = 132;         // epilogue smem pitch (floats)
constexpr int DYN_OUT = 2 * STAGE; // 98304; epilogue (33.8KB) reuses stage 0
constexpr int DYN_E = 128 * EPI_P * 4;  // 67584
}

// Scratch (device globals; no runtime allocation allowed).
__device__ __nv_bfloat16 g_qhi[B_ * N_ * D_];           // [B][N][D]
__device__ __nv_bfloat16 g_qlo[B_ * N_ * D_];
__device__ __nv_bfloat16 g_khi[B_ * N_ * D_];
__device__ __nv_bfloat16 g_klo[B_ * N_ * D_];
__device__ __half g_vhi[(size_t)B_ * C_ * N_];          // [B][C][N] K-major fp16
__device__ __half g_vlo[(size_t)B_ * C_ * N_];
__device__ __half g_af16[(size_t)B_ * N_ * N_];         // attn fp16 [B][M][N]

// ---------------------------------------------------------------------------
// helpers
// ---------------------------------------------------------------------------
__device__ __forceinline__ uint32_t smem_u32(const void* p) {
    uint32_t a;
    asm("{ .reg .u64 t; cvta.to.shared.u64 t, %1; cvt.u32.u64 %0, t; }" : "=r"(a) : "l"(p));
    return a;
}

__device__ __forceinline__ void cp16(uint32_t dst, const void* src) {
    asm volatile("cp.async.cg.shared.global [%0], [%1], 16;" :: "r"(dst), "l"(src) : "memory");
}

__device__ __forceinline__ void ldsm4(uint32_t* r, uint32_t addr) {
    asm volatile("ldmatrix.sync.aligned.m8n8.x4.shared.b16 {%0,%1,%2,%3}, [%4];"
                 : "=r"(r[0]), "=r"(r[1]), "=r"(r[2]), "=r"(r[3]) : "r"(addr));
}

__device__ __forceinline__ void mma_bf16(float* d, const uint32_t* a, uint32_t b0, uint32_t b1) {
    asm volatile(
        "mma.sync.aligned.m16n8k16.row.col.f32.bf16.bf16.f32 "
        "{%0,%1,%2,%3}, {%4,%5,%6,%7}, {%8,%9}, {%0,%1,%2,%3};"
        : "+f"(d[0]), "+f"(d[1]), "+f"(d[2]), "+f"(d[3])
        : "r"(a[0]), "r"(a[1]), "r"(a[2]), "r"(a[3]), "r"(b0), "r"(b1));
}

__device__ __forceinline__ void mma_f16(float* d, const uint32_t* a, uint32_t b0, uint32_t b1) {
    asm volatile(
        "mma.sync.aligned.m16n8k16.row.col.f32.f16.f16.f32 "
        "{%0,%1,%2,%3}, {%4,%5,%6,%7}, {%8,%9}, {%0,%1,%2,%3};"
        : "+f"(d[0]), "+f"(d[1]), "+f"(d[2]), "+f"(d[3])
        : "r"(a[0]), "r"(a[1]), "r"(a[2]), "r"(a[3]), "r"(b0), "r"(b1));
}

// 128B-row XOR swizzle (conflict-free for ldmatrix + cp.async stores)
__device__ __forceinline__ uint32_t swz(uint32_t row, uint32_t colbyte) {
    return row * 128u + (colbyte ^ ((row & 7u) << 4));
}

// ---------------------------------------------------------------------------
// Projection (q,k): t[n,d] = sum_c W[d,c] x[b,c,n] + bias[d], emit bf16 hi/lo.
// ---------------------------------------------------------------------------
__global__ void proj_qk_kernel(const float* __restrict__ x,
                               const float* __restrict__ W,
                               const float* __restrict__ bias,
                               __nv_bfloat16* __restrict__ ohi,
                               __nv_bfloat16* __restrict__ olo) {
    const int b  = blockIdx.z;
    const int n0 = blockIdx.x * 64;
    const float* xb = x + (size_t)b * C_ * N_;

    __shared__ float xs[16][64];
    __shared__ float ws[16][65];

    const int tid = threadIdx.x;
    const int tx = tid & 15;   // d
    const int ty = tid >> 4;   // n

    float acc[4][4] = {};
    for (int c0 = 0; c0 < C_; c0 += 16) {
#pragma unroll
        for (int i = 0; i < 4; i++) {
            int idx = tid + i * 256;
            int kk = idx >> 6, col = idx & 63;
            xs[kk][col] = xb[(size_t)(c0 + kk) * N_ + n0 + col];
        }
#pragma unroll
        for (int i = 0; i < 4; i++) {
            int idx = tid + i * 256;
            int kk = idx & 15, d = idx >> 4;
            ws[kk][d] = W[(size_t)d * C_ + c0 + kk];
        }
        __syncthreads();
#pragma unroll
        for (int kk = 0; kk < 16; kk++) {
            float ar[4], br[4];
#pragma unroll
            for (int i = 0; i < 4; i++) ar[i] = xs[kk][ty + 16 * i];
#pragma unroll
            for (int j = 0; j < 4; j++) br[j] = ws[kk][tx + 16 * j];
#pragma unroll
            for (int i = 0; i < 4; i++)
#pragma unroll
                for (int j = 0; j < 4; j++) acc[i][j] += ar[i] * br[j];
        }
        __syncthreads();
    }
    const size_t ob = (size_t)b * N_ * D_;
#pragma unroll
    for (int i = 0; i < 4; i++) {
        int n = n0 + ty + 16 * i;
#pragma unroll
        for (int j = 0; j < 4; j++) {
            int d = tx + 16 * j;
            float val = acc[i][j] + bias[d];
            __nv_bfloat16 h = __float2bfloat16(val);
            ohi[ob + (size_t)n * D_ + d] = h;
            olo[ob + (size_t)n * D_ + d] = __float2bfloat16(val - __bfloat162float(h));
        }
    }
}

// ---------------------------------------------------------------------------
// Projection (v): fp16 hi/lo pair in [B,C,N] (n contiguous, K-major B operand)
// ---------------------------------------------------------------------------
__global__ void proj_v_kernel(const float* __restrict__ x,
                              const float* __restrict__ W,
                              const float* __restrict__ bias,
                              __half* __restrict__ vhi,
                              __half* __restrict__ vlo) {
    const int b  = blockIdx.z;
    const int n0 = blockIdx.x * 64;
    const int c0 = blockIdx.y * 64;
    const float* xb = x + (size_t)b * C_ * N_;

    __shared__ float xs[16][64];   // xs[kk][n]
    __shared__ float ws[16][65];   // ws[kk][c]

    const int tid = threadIdx.x;
    const int tx = tid & 15;   // n
    const int ty = tid >> 4;   // c

    float acc[4][4] = {};   // [c][n]
    for (int k0 = 0; k0 < C_; k0 += 16) {
#pragma unroll
        for (int i = 0; i < 4; i++) {
            int idx = tid + i * 256;
            int kk = idx >> 6, col = idx & 63;
            xs[kk][col] = xb[(size_t)(k0 + kk) * N_ + n0 + col];
        }
#pragma unroll
        for (int i = 0; i < 4; i++) {
            int idx = tid + i * 256;
            int kk = idx & 15, c = idx >> 4;
            ws[kk][c] = W[(size_t)(c0 + c) * C_ + k0 + kk];
        }
        __syncthreads();
#pragma unroll
        for (int kk = 0; kk < 16; kk++) {
            float ar[4], br[4];
#pragma unroll
            for (int i = 0; i < 4; i++) ar[i] = ws[kk][ty + 16 * i];
#pragma unroll
            for (int j = 0; j < 4; j++) br[j] = xs[kk][tx + 16 * j];
#pragma unroll
            for (int i = 0; i < 4; i++)
#pragma unroll
                for (int j = 0; j < 4; j++) acc[i][j] += ar[i] * br[j];
        }
        __syncthreads();
    }
#pragma unroll
    for (int i = 0; i < 4; i++) {
        int c = c0 + ty + 16 * i;
        float bv = bias[c];
        size_t rowbase = ((size_t)b * C_ + c) * N_ + n0;
#pragma unroll
        for (int j = 0; j < 4; j++) {
            float val = acc[i][j] + bv;
            __half h = __float2half(val);
            vhi[rowbase + tx + 16 * j] = h;
            vlo[rowbase + tx + 16 * j] = __float2half(val - __half2float(h));
        }
    }
}

// ---------------------------------------------------------------------------
// Energy (HMMA): E[b,m,n] = sum_d q[b,m,d] k[b,n,d], compensated bf16 split.
// ---------------------------------------------------------------------------
__global__ void __launch_bounds__(256)
energy_hmma_kernel(float* __restrict__ attn) {
    extern __shared__ char dynsmem[];
    const uint32_t sbase = smem_u32(dynsmem);

    const int tid  = threadIdx.x;
    const int wid  = tid >> 5;
    const int lane = tid & 31;

    const int b  = blockIdx.z;
    const int n0 = blockIdx.x * 128;
    const int m0 = blockIdx.y * 128;

    const __nv_bfloat16* Qhi = g_qhi + (size_t)b * N_ * D_;
    const __nv_bfloat16* Qlo = g_qlo + (size_t)b * N_ * D_;
    const __nv_bfloat16* Khi = g_khi + (size_t)b * N_ * D_;
    const __nv_bfloat16* Klo = g_klo + (size_t)b * N_ * D_;

    const int wm = (wid >> 2) * 64;
    const int wn = (wid & 3) * 32;

    const uint32_t lrow = lane & 15;
    const uint32_t lswz = (lane & 7) << 4;
    const uint32_t lcol = (lane >> 4) << 4;

#pragma unroll
    for (int t = 0; t < 4; t++) {
        const int idx = tid + t * 256;
        const int row = idx >> 3, seg = idx & 7;
        cp16(sbase + swz(row, seg * 16), Qhi + (size_t)(m0 + row) * D_ + seg * 8);
        cp16(sbase + 16384 + swz(row, seg * 16), Khi + (size_t)(n0 + row) * D_ + seg * 8);
    }
    asm volatile("cp.async.commit_group;" ::: "memory");
#pragma unroll
    for (int t = 0; t < 4; t++) {
        const int idx = tid + t * 256;
        const int row = idx >> 3, seg = idx & 7;
        cp16(sbase + 32768 + swz(row, seg * 16), Qlo + (size_t)(m0 + row) * D_ + seg * 8);
        cp16(sbase + 49152 + swz(row, seg * 16), Klo + (size_t)(n0 + row) * D_ + seg * 8);
    }
    asm volatile("cp.async.commit_group;" ::: "memory");

    float acc[4][4][4] = {};

    asm volatile("cp.async.wait_group 1;" ::: "memory");
    __syncthreads();
#pragma unroll
    for (int ks = 0; ks < 4; ks++) {
        const uint32_t kb = (uint32_t)(ks * 32);
        uint32_t a[4][4], bm[2][4];
#pragma unroll
        for (int i = 0; i < 4; i++) {
            const uint32_t row = (uint32_t)(wm + i * 16) + lrow;
            ldsm4(a[i], sbase + row * 128u + ((kb + lcol) ^ lswz));
        }
#pragma unroll
        for (int j = 0; j < 2; j++) {
            const uint32_t row = (uint32_t)(wn + j * 16) + lrow;
            ldsm4(bm[j], sbase + 16384 + row * 128u + ((kb + lcol) ^ lswz));
        }
#pragma unroll
        for (int i = 0; i < 4; i++)
#pragma unroll
            for (int j = 0; j < 4; j++) {
                const int t2 = j >> 1, p2 = j & 1;
                mma_bf16(acc[i][j], a[i], bm[t2][p2], bm[t2][2 + p2]);
            }
    }

    asm volatile("cp.async.wait_group 0;" ::: "memory");
    __syncthreads();
#pragma unroll
    for (int ks = 0; ks < 4; ks++) {
        const uint32_t kb = (uint32_t)(ks * 32);
        uint32_t ah[4][4], al[4][4], bh[2][4], bl[2][4];
#pragma unroll
        for (int i = 0; i < 4; i++) {
            const uint32_t row = (uint32_t)(wm + i * 16) + lrow;
            ldsm4(ah[i], sbase + row * 128u + ((kb + lcol) ^ lswz));
            ldsm4(al[i], sbase + 32768 + row * 128u + ((kb + lcol) ^ lswz));
        }
#pragma unroll
        for (int j = 0; j < 2; j++) {
            const uint32_t row = (uint32_t)(wn + j * 16) + lrow;
            ldsm4(bh[j], sbase + 16384 + row * 128u + ((kb + lcol) ^ lswz));
            ldsm4(bl[j], sbase + 49152 + row * 128u + ((kb + lcol) ^ lswz));
        }
#pragma unroll
        for (int i = 0; i < 4; i++)
#pragma unroll
            for (int j = 0; j < 4; j++) {
                const int t2 = j >> 1, p2 = j & 1;
                mma_bf16(acc[i][j], al[i], bh[t2][p2], bh[t2][2 + p2]);
                mma_bf16(acc[i][j], ah[i], bl[t2][p2], bl[t2][2 + p2]);
            }
    }

    __syncthreads();
    float* sOut = reinterpret_cast<float*>(dynsmem);
#pragma unroll
    for (int i = 0; i < 4; i++) {
        const int mt = wm + i * 16 + (lane >> 2);
#pragma unroll
        for (int j = 0; j < 4; j++) {
            const int nt = wn + j * 8 + (lane & 3) * 2;
            sOut[mt * EPI_P + nt]           = acc[i][j][0];
            sOut[mt * EPI_P + nt + 1]       = acc[i][j][1];
            sOut[(mt + 8) * EPI_P + nt]     = acc[i][j][2];
            sOut[(mt + 8) * EPI_P + nt + 1] = acc[i][j][3];
        }
    }
    __syncthreads();

    float* eb = attn + (size_t)b * N_ * N_;
    const int row = tid >> 1;
    const int col0 = (tid & 1) * 64;
    const float* srow = sOut + row * EPI_P + col0;
    float* grow = eb + (size_t)(m0 + row) * N_ + n0 + col0;
#pragma unroll
    for (int v = 0; v < 16; v++)
        *reinterpret_cast<float4*>(grow + v * 4) =
            *reinterpret_cast<const float4*>(srow + v * 4);
}

// ---------------------------------------------------------------------------
// Row softmax in place (vectorized); emit attn as single fp16.
// ---------------------------------------------------------------------------
__global__ void softmax_kernel(float* __restrict__ attn,
                               __half* __restrict__ af16) {
    const size_t row = blockIdx.x;
    float* p = attn + row * N_;
    const int tid = threadIdx.x;

    float4 v[4];
    float mx = -3.0e38f;
#pragma unroll
    for (int i = 0; i < 4; i++) {
        v[i] = *reinterpret_cast<const float4*>(p + tid * 4 + i * 1024);
        mx = fmaxf(mx, fmaxf(fmaxf(v[i].x, v[i].y), fmaxf(v[i].z, v[i].w)));
    }
    __shared__ float red[8];
#pragma unroll
    for (int o = 16; o; o >>= 1) mx = fmaxf(mx, __shfl_xor_sync(0xffffffffu, mx, o));
    if ((tid & 31) == 0) red[tid >> 5] = mx;
    __syncthreads();
    mx = red[0];
#pragma unroll
    for (int i = 1; i < 8; i++) mx = fmaxf(mx, red[i]);
    __syncthreads();

    float s = 0.f;
#pragma unroll
    for (int i = 0; i < 4; i++) {
        v[i].x = __expf(v[i].x - mx); v[i].y = __expf(v[i].y - mx);
        v[i].z = __expf(v[i].z - mx); v[i].w = __expf(v[i].w - mx);
        s += (v[i].x + v[i].y) + (v[i].z + v[i].w);
    }
#pragma unroll
    for (int o = 16; o; o >>= 1) s += __shfl_xor_sync(0xffffffffu, s, o);
    if ((tid & 31) == 0) red[tid >> 5] = s;
    __syncthreads();
    s = 0.f;
#pragma unroll
    for (int i = 0; i < 8; i++) s += red[i];
    const float inv = 1.0f / s;

    __half* ph = af16 + row * N_;
#pragma unroll
    for (int i = 0; i < 4; i++) {
        float4 r;
        r.x = v[i].x * inv; r.y = v[i].y * inv; r.z = v[i].z * inv; r.w = v[i].w * inv;
        *reinterpret_cast<float4*>(p + tid * 4 + i * 1024) = r;

        __half2 h01 = __floats2half2_rn(r.x, r.y);
        __half2 h23 = __floats2half2_rn(r.z, r.w);
        uint2 hh;
        hh.x = *reinterpret_cast<uint32_t*>(&h01);
        hh.y = *reinterpret_cast<uint32_t*>(&h23);
        *reinterpret_cast<uint2*>(ph + tid * 4 + i * 1024) = hh;
    }
}

// ---------------------------------------------------------------------------
// out[b,c,m] = gamma * sum_n attn[b,m,n] * v[b,c,n] + x[b,c,m]
// HMMA fp16: A = attn single fp16 (products exact in fp32 accumulate),
// V = fp16 hi/lo split:  D = A*Vhi + A*Vlo.
// CTA 128m x 128c, 8 warps, KC=64, 2-stage ring (48KB/stage), 2 CTAs/SM.
// Stage layout: A@0 (16K), Vhi@16K, Vlo@32K; 128B rows, XOR swizzle.
// ---------------------------------------------------------------------------
__global__ void __launch_bounds__(256, 2)
out_gemm_kernel(const float* __restrict__ x,
                const float* __restrict__ gamma,
                float* __restrict__ out) {
    extern __shared__ char dynsmem[];
    const uint32_t sbase = smem_u32(dynsmem);

    const int tid  = threadIdx.x;
    const int wid  = tid >> 5;
    const int lane = tid & 31;

    const int b  = blockIdx.z;
    const int c0 = blockIdx.x * 128;
    const int m0 = blockIdx.y * 128;

    const __half* A   = g_af16 + (size_t)b * N_ * N_;
    const __half* Bhi = g_vhi + (size_t)b * C_ * N_;
    const __half* Blo = g_vlo + (size_t)b * C_ * N_;

    const int wm = (wid >> 2) * 64;
    const int wc = (wid & 3) * 32;

    const uint32_t lrow = lane & 15;
    const uint32_t lswz = (lane & 7) << 4;
    const uint32_t lcol = (lane >> 4) << 4;

    float acc[4][4][4] = {};

    // 3072 cp16 per chunk / 256 threads = 12 each
    auto load_chunk = [&](int kc) {
        const uint32_t st = (uint32_t)(kc & 1) * STAGE;
        const size_t koff = (size_t)kc * KC;
#pragma unroll
        for (int t = 0; t < 12; t++) {
            const int idx = tid + t * 256;
            const int part = idx >> 10;           // 0=A, 1=Vhi, 2=Vlo
            const int a = idx & 1023;
            const int row = a >> 3, seg = a & 7;
            const __half* src;
            if (part == 0)      src = A   + (size_t)(m0 + row) * N_ + koff + seg * 8;
            else if (part == 1) src = Bhi + (size_t)(c0 + row) * N_ + koff + seg * 8;
            else                src = Blo + (size_t)(c0 + row) * N_ + koff + seg * 8;
            cp16(sbase + st + (uint32_t)part * 16384u + swz(row, seg * 16), src);
        }
        asm volatile("cp.async.commit_group;" ::: "memory");
    };

    load_chunk(0);

    for (int kc = 0; kc < NCHUNK; kc++) {
        if (kc + 1 < NCHUNK) {
            __syncthreads();               // all warps done reading stage (kc+1)&1
            load_chunk(kc + 1);
            asm volatile("cp.async.wait_group 1;" ::: "memory");
        } else {
            asm volatile("cp.async.wait_group 0;" ::: "memory");
        }
        __syncthreads();                   // stage kc visible to all warps

        const uint32_t st = (uint32_t)(kc & 1) * STAGE;
        const uint32_t Ab = sbase + st;
        const uint32_t Hb = Ab + 16384, Lb = Ab + 32768;

#pragma unroll
        for (int ks = 0; ks < 4; ks++) {
            const uint32_t kb = (uint32_t)(ks * 32);
            uint32_t a[4][4], bh[2][4], bl[2][4];
#pragma unroll
            for (int i = 0; i < 4; i++) {
                const uint32_t row = (uint32_t)(wm + i * 16) + lrow;
                ldsm4(a[i], Ab + row * 128u + ((kb + lcol) ^ lswz));
            }
#pragma unroll
            for (int j = 0; j < 2; j++) {
                const uint32_t row = (uint32_t)(wc + j * 16) + lrow;
                ldsm4(bh[j], Hb + row * 128u + ((kb + lcol) ^ lswz));
                ldsm4(bl[j], Lb + row * 128u + ((kb + lcol) ^ lswz));
            }
#pragma unroll
            for (int i = 0; i < 4; i++)
#pragma unroll
                for (int j = 0; j < 4; j++) {
                    const int t2 = j >> 1, p2 = j & 1;
                    mma_f16(acc[i][j], a[i], bh[t2][p2], bh[t2][2 + p2]);
                    mma_f16(acc[i][j], a[i], bl[t2][p2], bl[t2][2 + p2]);
                }
        }
    }
    __syncthreads();

    // ---- epilogue: two 64-col halves; transpose via smem (33.8KB reuse) ----
    float* sOut = reinterpret_cast<float*>(dynsmem);
    const float g = gamma[0];
#pragma unroll
    for (int h = 0; h < 2; h++) {
        if (((wid & 3) >> 1) == h) {
            const int cbase = wc - h * 64;   // 0 or 32 within the half
#pragma unroll
            for (int i = 0; i < 4; i++) {
                const int mt = wm + i * 16 + (lane >> 2);
#pragma unroll
                for (int j = 0; j < 4; j++) {
                    const int ct = cbase + j * 8 + (lane & 3) * 2;
                    sOut[ct * EPI_P + mt]           = acc[i][j][0];
                    sOut[(ct + 1) * EPI_P + mt]     = acc[i][j][1];
                    sOut[ct * EPI_P + mt + 8]       = acc[i][j][2];
                    sOut[(ct + 1) * EPI_P + mt + 8] = acc[i][j][3];
                }
            }
        }
        __syncthreads();

        const int ce = tid >> 2;             // 0..63 (c within half)
        const int me = (tid & 3) * 32;       // m offset
        const size_t gb = ((size_t)b * C_ + c0 + h * 64 + ce) * N_ + m0 + me;
        const float* srow = sOut + ce * EPI_P + me;
#pragma unroll
        for (int v = 0; v < 8; v++) {
            const float4 xv = *reinterpret_cast<const float4*>(x + gb + v * 4);
            float4 ov;
            ov.x = g * srow[v * 4 + 0] + xv.x;
            ov.y = g * srow[v * 4 + 1] + xv.y;
            ov.z = g * srow[v * 4 + 2] + xv.z;
            ov.w = g * srow[v * 4 + 3] + xv.w;
            *reinterpret_cast<float4*>(out + gb + v * 4) = ov;
        }
        __syncthreads();
    }
}

// ---------------------------------------------------------------------------
extern "C" void kernel_launch(void* const* d_in, const int* in_sizes, int n_in,
                              void* d_out, int out_size) {
    (void)in_sizes; (void)n_in; (void)out_size;
    const float* x     = (const float*)d_in[0];
    const float* Wq    = (const float*)d_in[1];
    const float* bq    = (const float*)d_in[2];
    const float* Wk    = (const float*)d_in[3];
    const float* bk    = (const float*)d_in[4];
    const float* Wv    = (const float*)d_in[5];
    const float* bv    = (const float*)d_in[6];
    const float* gamma = (const float*)d_in[7];

    float* out  = (float*)d_out;
    float* attn = out + (size_t)B_ * C_ * N_;   // tuple order: (out, attention)

    __nv_bfloat16 *qhi, *qlo, *khi, *klo;
    __half *vhi, *vlo, *af16;
    cudaGetSymbolAddress((void**)&qhi, g_qhi);
    cudaGetSymbolAddress((void**)&qlo, g_qlo);
    cudaGetSymbolAddress((void**)&khi, g_khi);
    cudaGetSymbolAddress((void**)&klo, g_klo);
    cudaGetSymbolAddress((void**)&vhi, g_vhi);
    cudaGetSymbolAddress((void**)&vlo, g_vlo);
    cudaGetSymbolAddress((void**)&af16, g_af16);

    cudaFuncSetAttribute(out_gemm_kernel,
                         cudaFuncAttributeMaxDynamicSharedMemorySize, DYN_OUT);
    cudaFuncSetAttribute(energy_hmma_kernel,
                         cudaFuncAttributeMaxDynamicSharedMemorySize, DYN_E);

    dim3 blk(256);
    proj_qk_kernel<<<dim3(N_ / 64, 1, B_), blk>>>(x, Wq, bq, qhi, qlo);
    proj_qk_kernel<<<dim3(N_ / 64, 1, B_), blk>>>(x, Wk, bk, khi, klo);
    proj_v_kernel<<<dim3(N_ / 64, C_ / 64, B_), blk>>>(x, Wv, bv, vhi, vlo);
    energy_hmma_kernel<<<dim3(N_ / 128, N_ / 128, B_), blk, DYN_E>>>(attn);
    softmax_kernel<<<dim3(B_ * N_), blk>>>(attn, af16);
    out_gemm_kernel<<<dim3(C_ / 128, N_ / 128, B_), blk, DYN_OUT>>>(x, gamma, out);
}

// round 7
// speedup vs baseline: 4.7997x; 1.5247x over previous
#include <cuda_runtime.h>
#include <cuda_bf16.h>
#include <cuda_fp16.h>
#include <cstdint>

// Self_Attn: B=4, C=512, N=4096 (64x64), D=64
// Outputs (tuple order): out [B,C,64,64] fp32, attention [B,N,N] fp32.

namespace {
constexpr int B_ = 4;
constexpr int C_ = 512;
constexpr int N_ = 4096;
constexpr int D_ = 64;

constexpr int KC_O = 64;             // out-GEMM K elems per chunk (128B fp16 row)
constexpr int NCHUNK_O = N_ / KC_O;  // 64
constexpr int STAGE_O = 32768;       // A 16K + V 16K
constexpr int EPI_P = 132;           // epilogue smem pitch (floats)
constexpr int DYN_OUT = 3 * STAGE_O; // 98304 (3-stage ring; epi 33.8K reuses)
constexpr int DYN_E = 128 * EPI_P * 4;  // 67584
constexpr int DYN_V = 128 * EPI_P * 4;  // 67584 (> 2*32768)
}

// Scratch (device globals; no runtime allocation allowed).
__device__ __nv_bfloat16 g_qhi[B_ * N_ * D_];           // [B][N][D]
__device__ __nv_bfloat16 g_qlo[B_ * N_ * D_];
__device__ __nv_bfloat16 g_khi[B_ * N_ * D_];
__device__ __nv_bfloat16 g_klo[B_ * N_ * D_];
__device__ __nv_bfloat16 g_xthi[(size_t)B_ * N_ * C_];  // x^T [B][N][C] k-contig
__device__ __nv_bfloat16 g_xtlo[(size_t)B_ * N_ * C_];
__device__ __nv_bfloat16 g_wvhi[C_ * C_];               // Wv [c][k]
__device__ __nv_bfloat16 g_wvlo[C_ * C_];
__device__ __half g_vf16[(size_t)B_ * C_ * N_];         // v [B][C][N] fp16
__device__ __half g_af16[(size_t)B_ * N_ * N_];         // attn fp16 [B][M][N]

// ---------------------------------------------------------------------------
// helpers
// ---------------------------------------------------------------------------
__device__ __forceinline__ uint32_t smem_u32(const void* p) {
    uint32_t a;
    asm("{ .reg .u64 t; cvta.to.shared.u64 t, %1; cvt.u32.u64 %0, t; }" : "=r"(a) : "l"(p));
    return a;
}

__device__ __forceinline__ void cp16(uint32_t dst, const void* src) {
    asm volatile("cp.async.cg.shared.global [%0], [%1], 16;" :: "r"(dst), "l"(src) : "memory");
}

__device__ __forceinline__ void ldsm4(uint32_t* r, uint32_t addr) {
    asm volatile("ldmatrix.sync.aligned.m8n8.x4.shared.b16 {%0,%1,%2,%3}, [%4];"
                 : "=r"(r[0]), "=r"(r[1]), "=r"(r[2]), "=r"(r[3]) : "r"(addr));
}

__device__ __forceinline__ void mma_bf16(float* d, const uint32_t* a, uint32_t b0, uint32_t b1) {
    asm volatile(
        "mma.sync.aligned.m16n8k16.row.col.f32.bf16.bf16.f32 "
        "{%0,%1,%2,%3}, {%4,%5,%6,%7}, {%8,%9}, {%0,%1,%2,%3};"
        : "+f"(d[0]), "+f"(d[1]), "+f"(d[2]), "+f"(d[3])
        : "r"(a[0]), "r"(a[1]), "r"(a[2]), "r"(a[3]), "r"(b0), "r"(b1));
}

__device__ __forceinline__ void mma_f16(float* d, const uint32_t* a, uint32_t b0, uint32_t b1) {
    asm volatile(
        "mma.sync.aligned.m16n8k16.row.col.f32.f16.f16.f32 "
        "{%0,%1,%2,%3}, {%4,%5,%6,%7}, {%8,%9}, {%0,%1,%2,%3};"
        : "+f"(d[0]), "+f"(d[1]), "+f"(d[2]), "+f"(d[3])
        : "r"(a[0]), "r"(a[1]), "r"(a[2]), "r"(a[3]), "r"(b0), "r"(b1));
}

__device__ __forceinline__ uint32_t swz(uint32_t row, uint32_t colbyte) {
    return row * 128u + (colbyte ^ ((row & 7u) << 4));
}

// ---------------------------------------------------------------------------
// Transpose + split x: x[b][k][n] fp32 -> xT[b][n][k] bf16 hi/lo.
// ---------------------------------------------------------------------------
__global__ void convert_x_kernel(const float* __restrict__ x,
                                 __nv_bfloat16* __restrict__ xthi,
                                 __nv_bfloat16* __restrict__ xtlo) {
    const int b  = blockIdx.z;
    const int n0 = blockIdx.x * 32;
    const int k0 = blockIdx.y * 32;
    __shared__ float t[32][33];
    const int tid = threadIdx.x;
#pragma unroll
    for (int i = 0; i < 4; i++) {
        int idx = tid + i * 256;
        int k = idx >> 5, n = idx & 31;
        t[k][n] = x[((size_t)b * C_ + k0 + k) * N_ + n0 + n];
    }
    __syncthreads();
#pragma unroll
    for (int i = 0; i < 4; i++) {
        int idx = tid + i * 256;
        int n = idx >> 5, k = idx & 31;
        float val = t[k][n];
        __nv_bfloat16 h = __float2bfloat16(val);
        size_t off = ((size_t)b * N_ + n0 + n) * C_ + k0 + k;
        xthi[off] = h;
        xtlo[off] = __float2bfloat16(val - __bfloat162float(h));
    }
}

// Split Wv fp32 -> bf16 hi/lo (elementwise, layout [c][k] already k-contig).
__global__ void convert_w_kernel(const float* __restrict__ W,
                                 __nv_bfloat16* __restrict__ whi,
                                 __nv_bfloat16* __restrict__ wlo) {
    const int i = blockIdx.x * 256 + threadIdx.x;
    float val = W[i];
    __nv_bfloat16 h = __float2bfloat16(val);
    whi[i] = h;
    wlo[i] = __float2bfloat16(val - __bfloat162float(h));
}

// ---------------------------------------------------------------------------
// Projection (q,k): t[n,d] = sum_c W[d,c] x[b,c,n] + bias[d], emit bf16 hi/lo.
// ---------------------------------------------------------------------------
__global__ void proj_qk_kernel(const float* __restrict__ x,
                               const float* __restrict__ W,
                               const float* __restrict__ bias,
                               __nv_bfloat16* __restrict__ ohi,
                               __nv_bfloat16* __restrict__ olo) {
    const int b  = blockIdx.z;
    const int n0 = blockIdx.x * 64;
    const float* xb = x + (size_t)b * C_ * N_;

    __shared__ float xs[16][64];
    __shared__ float ws[16][65];

    const int tid = threadIdx.x;
    const int tx = tid & 15;   // d
    const int ty = tid >> 4;   // n

    float acc[4][4] = {};
    for (int c0 = 0; c0 < C_; c0 += 16) {
#pragma unroll
        for (int i = 0; i < 4; i++) {
            int idx = tid + i * 256;
            int kk = idx >> 6, col = idx & 63;
            xs[kk][col] = xb[(size_t)(c0 + kk) * N_ + n0 + col];
        }
#pragma unroll
        for (int i = 0; i < 4; i++) {
            int idx = tid + i * 256;
            int kk = idx & 15, d = idx >> 4;
            ws[kk][d] = W[(size_t)d * C_ + c0 + kk];
        }
        __syncthreads();
#pragma unroll
        for (int kk = 0; kk < 16; kk++) {
            float ar[4], br[4];
#pragma unroll
            for (int i = 0; i < 4; i++) ar[i] = xs[kk][ty + 16 * i];
#pragma unroll
            for (int j = 0; j < 4; j++) br[j] = ws[kk][tx + 16 * j];
#pragma unroll
            for (int i = 0; i < 4; i++)
#pragma unroll
                for (int j = 0; j < 4; j++) acc[i][j] += ar[i] * br[j];
        }
        __syncthreads();
    }
    const size_t ob = (size_t)b * N_ * D_;
#pragma unroll
    for (int i = 0; i < 4; i++) {
        int n = n0 + ty + 16 * i;
#pragma unroll
        for (int j = 0; j < 4; j++) {
            int d = tx + 16 * j;
            float val = acc[i][j] + bias[d];
            __nv_bfloat16 h = __float2bfloat16(val);
            ohi[ob + (size_t)n * D_ + d] = h;
            olo[ob + (size_t)n * D_ + d] = __float2bfloat16(val - __bfloat162float(h));
        }
    }
}

// ---------------------------------------------------------------------------
// proj_v (HMMA): v[b,c,n] = sum_k Wv[c,k] x[b,k,n] + bv[c], compensated bf16:
//   v = Whi*Xhi + Wlo*Xhi + Whi*Xlo.  A=Wv [c][k], B=xT [n][k]; KC=32 packed
//   rows [hi 64B | lo 64B]. Emits v as single fp16 [B][C][N].
// CTA 128c x 128n, 8 warps, 2-stage ring (16K+16K per stage).
// ---------------------------------------------------------------------------
__global__ void __launch_bounds__(256, 2)
proj_v_hmma_kernel(const float* __restrict__ bias, __half* __restrict__ vf16) {
    extern __shared__ char dynsmem[];
    const uint32_t sbase = smem_u32(dynsmem);

    const int tid  = threadIdx.x;
    const int wid  = tid >> 5;
    const int lane = tid & 31;

    const int b  = blockIdx.z;
    const int n0 = blockIdx.x * 128;
    const int c0 = blockIdx.y * 128;

    const __nv_bfloat16* Whi = g_wvhi;
    const __nv_bfloat16* Wlo = g_wvlo;
    const __nv_bfloat16* Xhi = g_xthi + (size_t)b * N_ * C_;
    const __nv_bfloat16* Xlo = g_xtlo + (size_t)b * N_ * C_;

    const int wm = (wid >> 2) * 64;   // c
    const int wn = (wid & 3) * 32;    // n

    const uint32_t lrow = lane & 15;
    const uint32_t lswz = (lane & 7) << 4;
    const uint32_t lcol = (lane >> 4) << 4;

    float acc[4][4][4] = {};

    // per chunk: 2048 cp16 / 256 = 8 each. rows pack [hi(4 segs)|lo(4 segs)].
    auto load_chunk = [&](int kc) {
        const uint32_t st = (uint32_t)(kc & 1) * STAGE_O;
        const size_t koff = (size_t)kc * 32;
#pragma unroll
        for (int t = 0; t < 8; t++) {
            const int idx = tid + t * 256;
            const int part = idx >> 10;          // 0=A(Wv), 1=B(xT)
            const int a = idx & 1023;
            const int row = a >> 3, seg = a & 7;
            const __nv_bfloat16* src;
            if (part == 0)
                src = (seg < 4 ? Whi : Wlo) + (size_t)(c0 + row) * C_ + koff + (seg & 3) * 8;
            else
                src = (seg < 4 ? Xhi : Xlo) + (size_t)(n0 + row) * C_ + koff + (seg & 3) * 8;
            cp16(sbase + st + (uint32_t)part * 16384u + swz(row, seg * 16), src);
        }
        asm volatile("cp.async.commit_group;" ::: "memory");
    };

    load_chunk(0);

    for (int kc = 0; kc < C_ / 32; kc++) {
        if (kc + 1 < C_ / 32) {
            __syncthreads();
            load_chunk(kc + 1);
            asm volatile("cp.async.wait_group 1;" ::: "memory");
        } else {
            asm volatile("cp.async.wait_group 0;" ::: "memory");
        }
        __syncthreads();

        const uint32_t st = (uint32_t)(kc & 1) * STAGE_O;
        const uint32_t Ab = sbase + st, Bb = Ab + 16384;

#pragma unroll
        for (int ks = 0; ks < 2; ks++) {
            const uint32_t kbHi = (uint32_t)(ks * 32);
            const uint32_t kbLo = 64u + kbHi;

            uint32_t ah[4][4], al[4][4], bh[2][4], bl[2][4];
#pragma unroll
            for (int i = 0; i < 4; i++) {
                const uint32_t row = (uint32_t)(wm + i * 16) + lrow;
                ldsm4(ah[i], Ab + row * 128u + ((kbHi + lcol) ^ lswz));
                ldsm4(al[i], Ab + row * 128u + ((kbLo + lcol) ^ lswz));
            }
#pragma unroll
            for (int j = 0; j < 2; j++) {
                const uint32_t row = (uint32_t)(wn + j * 16) + lrow;
                ldsm4(bh[j], Bb + row * 128u + ((kbHi + lcol) ^ lswz));
                ldsm4(bl[j], Bb + row * 128u + ((kbLo + lcol) ^ lswz));
            }
#pragma unroll
            for (int i = 0; i < 4; i++)
#pragma unroll
                for (int j = 0; j < 4; j++) {
                    const int t2 = j >> 1, p2 = j & 1;
                    mma_bf16(acc[i][j], ah[i], bh[t2][p2], bh[t2][2 + p2]);
                    mma_bf16(acc[i][j], al[i], bh[t2][p2], bh[t2][2 + p2]);
                    mma_bf16(acc[i][j], ah[i], bl[t2][p2], bl[t2][2 + p2]);
                }
        }
    }
    __syncthreads();

    // Epilogue: c-major rows in smem (n contiguous), add bias, emit fp16.
    float* sOut = reinterpret_cast<float*>(dynsmem);
#pragma unroll
    for (int i = 0; i < 4; i++) {
        const int ct = wm + i * 16 + (lane >> 2);
#pragma unroll
        for (int j = 0; j < 4; j++) {
            const int nt = wn + j * 8 + (lane & 3) * 2;
            sOut[ct * EPI_P + nt]           = acc[i][j][0];
            sOut[ct * EPI_P + nt + 1]       = acc[i][j][1];
            sOut[(ct + 8) * EPI_P + nt]     = acc[i][j][2];
            sOut[(ct + 8) * EPI_P + nt + 1] = acc[i][j][3];
        }
    }
    __syncthreads();

    const int row = tid >> 1;             // c within tile
    const int col0 = (tid & 1) * 64;      // n offset
    const float bv = bias[c0 + row];
    const float* srow = sOut + row * EPI_P + col0;
    __half* dst = vf16 + ((size_t)b * C_ + c0 + row) * N_ + n0 + col0;
#pragma unroll
    for (int v = 0; v < 16; v++) {
        float4 f = *reinterpret_cast<const float4*>(srow + v * 4);
        __half2 h01 = __floats2half2_rn(f.x + bv, f.y + bv);
        __half2 h23 = __floats2half2_rn(f.z + bv, f.w + bv);
        uint2 u;
        u.x = *reinterpret_cast<uint32_t*>(&h01);
        u.y = *reinterpret_cast<uint32_t*>(&h23);
        *reinterpret_cast<uint2*>(dst + v * 4) = u;
    }
}

// ---------------------------------------------------------------------------
// Energy (HMMA): E[b,m,n] = sum_d q[b,m,d] k[b,n,d], compensated bf16 split.
// ---------------------------------------------------------------------------
__global__ void __launch_bounds__(256)
energy_hmma_kernel(float* __restrict__ attn) {
    extern __shared__ char dynsmem[];
    const uint32_t sbase = smem_u32(dynsmem);

    const int tid  = threadIdx.x;
    const int wid  = tid >> 5;
    const int lane = tid & 31;

    const int b  = blockIdx.z;
    const int n0 = blockIdx.x * 128;
    const int m0 = blockIdx.y * 128;

    const __nv_bfloat16* Qhi = g_qhi + (size_t)b * N_ * D_;
    const __nv_bfloat16* Qlo = g_qlo + (size_t)b * N_ * D_;
    const __nv_bfloat16* Khi = g_khi + (size_t)b * N_ * D_;
    const __nv_bfloat16* Klo = g_klo + (size_t)b * N_ * D_;

    const int wm = (wid >> 2) * 64;
    const int wn = (wid & 3) * 32;

    const uint32_t lrow = lane & 15;
    const uint32_t lswz = (lane & 7) << 4;
    const uint32_t lcol = (lane >> 4) << 4;

#pragma unroll
    for (int t = 0; t < 4; t++) {
        const int idx = tid + t * 256;
        const int row = idx >> 3, seg = idx & 7;
        cp16(sbase + swz(row, seg * 16), Qhi + (size_t)(m0 + row) * D_ + seg * 8);
        cp16(sbase + 16384 + swz(row, seg * 16), Khi + (size_t)(n0 + row) * D_ + seg * 8);
    }
    asm volatile("cp.async.commit_group;" ::: "memory");
#pragma unroll
    for (int t = 0; t < 4; t++) {
        const int idx = tid + t * 256;
        const int row = idx >> 3, seg = idx & 7;
        cp16(sbase + 32768 + swz(row, seg * 16), Qlo + (size_t)(m0 + row) * D_ + seg * 8);
        cp16(sbase + 49152 + swz(row, seg * 16), Klo + (size_t)(n0 + row) * D_ + seg * 8);
    }
    asm volatile("cp.async.commit_group;" ::: "memory");

    float acc[4][4][4] = {};

    asm volatile("cp.async.wait_group 1;" ::: "memory");
    __syncthreads();
#pragma unroll
    for (int ks = 0; ks < 4; ks++) {
        const uint32_t kb = (uint32_t)(ks * 32);
        uint32_t a[4][4], bm[2][4];
#pragma unroll
        for (int i = 0; i < 4; i++) {
            const uint32_t row = (uint32_t)(wm + i * 16) + lrow;
            ldsm4(a[i], sbase + row * 128u + ((kb + lcol) ^ lswz));
        }
#pragma unroll
        for (int j = 0; j < 2; j++) {
            const uint32_t row = (uint32_t)(wn + j * 16) + lrow;
            ldsm4(bm[j], sbase + 16384 + row * 128u + ((kb + lcol) ^ lswz));
        }
#pragma unroll
        for (int i = 0; i < 4; i++)
#pragma unroll
            for (int j = 0; j < 4; j++) {
                const int t2 = j >> 1, p2 = j & 1;
                mma_bf16(acc[i][j], a[i], bm[t2][p2], bm[t2][2 + p2]);
            }
    }

    asm volatile("cp.async.wait_group 0;" ::: "memory");
    __syncthreads();
#pragma unroll
    for (int ks = 0; ks < 4; ks++) {
        const uint32_t kb = (uint32_t)(ks * 32);
        uint32_t ah[4][4], al[4][4], bh[2][4], bl[2][4];
#pragma unroll
        for (int i = 0; i < 4; i++) {
            const uint32_t row = (uint32_t)(wm + i * 16) + lrow;
            ldsm4(ah[i], sbase + row * 128u + ((kb + lcol) ^ lswz));
            ldsm4(al[i], sbase + 32768 + row * 128u + ((kb + lcol) ^ lswz));
        }
#pragma unroll
        for (int j = 0; j < 2; j++) {
            const uint32_t row = (uint32_t)(wn + j * 16) + lrow;
            ldsm4(bh[j], sbase + 16384 + row * 128u + ((kb + lcol) ^ lswz));
            ldsm4(bl[j], sbase + 49152 + row * 128u + ((kb + lcol) ^ lswz));
        }
#pragma unroll
        for (int i = 0; i < 4; i++)
#pragma unroll
            for (int j = 0; j < 4; j++) {
                const int t2 = j >> 1, p2 = j & 1;
                mma_bf16(acc[i][j], al[i], bh[t2][p2], bh[t2][2 + p2]);
                mma_bf16(acc[i][j], ah[i], bl[t2][p2], bl[t2][2 + p2]);
            }
    }

    __syncthreads();
    float* sOut = reinterpret_cast<float*>(dynsmem);
#pragma unroll
    for (int i = 0; i < 4; i++) {
        const int mt = wm + i * 16 + (lane >> 2);
#pragma unroll
        for (int j = 0; j < 4; j++) {
            const int nt = wn + j * 8 + (lane & 3) * 2;
            sOut[mt * EPI_P + nt]           = acc[i][j][0];
            sOut[mt * EPI_P + nt + 1]       = acc[i][j][1];
            sOut[(mt + 8) * EPI_P + nt]     = acc[i][j][2];
            sOut[(mt + 8) * EPI_P + nt + 1] = acc[i][j][3];
        }
    }
    __syncthreads();

    float* eb = attn + (size_t)b * N_ * N_;
    const int row = tid >> 1;
    const int col0 = (tid & 1) * 64;
    const float* srow = sOut + row * EPI_P + col0;
    float* grow = eb + (size_t)(m0 + row) * N_ + n0 + col0;
#pragma unroll
    for (int v = 0; v < 16; v++)
        *reinterpret_cast<float4*>(grow + v * 4) =
            *reinterpret_cast<const float4*>(srow + v * 4);
}

// ---------------------------------------------------------------------------
// Row softmax in place (vectorized); emit attn as single fp16.
// ---------------------------------------------------------------------------
__global__ void softmax_kernel(float* __restrict__ attn,
                               __half* __restrict__ af16) {
    const size_t row = blockIdx.x;
    float* p = attn + row * N_;
    const int tid = threadIdx.x;

    float4 v[4];
    float mx = -3.0e38f;
#pragma unroll
    for (int i = 0; i < 4; i++) {
        v[i] = *reinterpret_cast<const float4*>(p + tid * 4 + i * 1024);
        mx = fmaxf(mx, fmaxf(fmaxf(v[i].x, v[i].y), fmaxf(v[i].z, v[i].w)));
    }
    __shared__ float red[8];
#pragma unroll
    for (int o = 16; o; o >>= 1) mx = fmaxf(mx, __shfl_xor_sync(0xffffffffu, mx, o));
    if ((tid & 31) == 0) red[tid >> 5] = mx;
    __syncthreads();
    mx = red[0];
#pragma unroll
    for (int i = 1; i < 8; i++) mx = fmaxf(mx, red[i]);
    __syncthreads();

    float s = 0.f;
#pragma unroll
    for (int i = 0; i < 4; i++) {
        v[i].x = __expf(v[i].x - mx); v[i].y = __expf(v[i].y - mx);
        v[i].z = __expf(v[i].z - mx); v[i].w = __expf(v[i].w - mx);
        s += (v[i].x + v[i].y) + (v[i].z + v[i].w);
    }
#pragma unroll
    for (int o = 16; o; o >>= 1) s += __shfl_xor_sync(0xffffffffu, s, o);
    if ((tid & 31) == 0) red[tid >> 5] = s;
    __syncthreads();
    s = 0.f;
#pragma unroll
    for (int i = 0; i < 8; i++) s += red[i];
    const float inv = 1.0f / s;

    __half* ph = af16 + row * N_;
#pragma unroll
    for (int i = 0; i < 4; i++) {
        float4 r;
        r.x = v[i].x * inv; r.y = v[i].y * inv; r.z = v[i].z * inv; r.w = v[i].w * inv;
        *reinterpret_cast<float4*>(p + tid * 4 + i * 1024) = r;

        __half2 h01 = __floats2half2_rn(r.x, r.y);
        __half2 h23 = __floats2half2_rn(r.z, r.w);
        uint2 hh;
        hh.x = *reinterpret_cast<uint32_t*>(&h01);
        hh.y = *reinterpret_cast<uint32_t*>(&h23);
        *reinterpret_cast<uint2*>(ph + tid * 4 + i * 1024) = hh;
    }
}

// ---------------------------------------------------------------------------
// out[b,c,m] = gamma * sum_n attn[b,m,n] * v[b,c,n] + x[b,c,m]
// HMMA fp16, single-term (A fp16 exact-product, V fp16).
// CTA 128m x 128c, 8 warps, KC=64, 3-stage ring (32KB/stage), 2 CTAs/SM.
// ---------------------------------------------------------------------------
__global__ void __launch_bounds__(256, 2)
out_gemm_kernel(const float* __restrict__ x,
                const float* __restrict__ gamma,
                float* __restrict__ out) {
    extern __shared__ char dynsmem[];
    const uint32_t sbase = smem_u32(dynsmem);

    const int tid  = threadIdx.x;
    const int wid  = tid >> 5;
    const int lane = tid & 31;

    const int b  = blockIdx.z;
    const int c0 = blockIdx.x * 128;
    const int m0 = blockIdx.y * 128;

    const __half* A = g_af16 + (size_t)b * N_ * N_;
    const __half* V = g_vf16 + (size_t)b * C_ * N_;

    const int wm = (wid >> 2) * 64;
    const int wc = (wid & 3) * 32;

    const uint32_t lrow = lane & 15;
    const uint32_t lswz = (lane & 7) << 4;
    const uint32_t lcol = (lane >> 4) << 4;

    float acc[4][4][4] = {};

    // 2048 cp16 per chunk / 256 threads = 8 each
    auto load_chunk = [&](int kc) {
        const uint32_t st = (uint32_t)(kc % 3) * STAGE_O;
        const size_t koff = (size_t)kc * KC_O;
#pragma unroll
        for (int t = 0; t < 8; t++) {
            const int idx = tid + t * 256;
            const int part = idx >> 10;           // 0=A, 1=V
            const int a = idx & 1023;
            const int row = a >> 3, seg = a & 7;
            const __half* src = part == 0
                ? A + (size_t)(m0 + row) * N_ + koff + seg * 8
                : V + (size_t)(c0 + row) * N_ + koff + seg * 8;
            cp16(sbase + st + (uint32_t)part * 16384u + swz(row, seg * 16), src);
        }
        asm volatile("cp.async.commit_group;" ::: "memory");
    };

    load_chunk(0);
    load_chunk(1);

    for (int kc = 0; kc < NCHUNK_O; kc++) {
        if (kc + 2 < NCHUNK_O) {
            load_chunk(kc + 2);
            asm volatile("cp.async.wait_group 2;" ::: "memory");
        } else if (kc + 1 < NCHUNK_O) {
            asm volatile("cp.async.wait_group 1;" ::: "memory");
        } else {
            asm volatile("cp.async.wait_group 0;" ::: "memory");
        }
        __syncthreads();

        const uint32_t st = (uint32_t)(kc % 3) * STAGE_O;
        const uint32_t Ab = sbase + st, Vb = Ab + 16384;

#pragma unroll
        for (int ks = 0; ks < 4; ks++) {
            const uint32_t kb = (uint32_t)(ks * 32);
            uint32_t a[4][4], bh[2][4];
#pragma unroll
            for (int i = 0; i < 4; i++) {
                const uint32_t row = (uint32_t)(wm + i * 16) + lrow;
                ldsm4(a[i], Ab + row * 128u + ((kb + lcol) ^ lswz));
            }
#pragma unroll
            for (int j = 0; j < 2; j++) {
                const uint32_t row = (uint32_t)(wc + j * 16) + lrow;
                ldsm4(bh[j], Vb + row * 128u + ((kb + lcol) ^ lswz));
            }
#pragma unroll
            for (int i = 0; i < 4; i++)
#pragma unroll
                for (int j = 0; j < 4; j++) {
                    const int t2 = j >> 1, p2 = j & 1;
                    mma_f16(acc[i][j], a[i], bh[t2][p2], bh[t2][2 + p2]);
                }
        }
        __syncthreads();   // all warps done with stage kc%3 before it's reloaded
    }

    // ---- epilogue: two 64-col halves; transpose via smem (33.8KB reuse) ----
    float* sOut = reinterpret_cast<float*>(dynsmem);
    const float g = gamma[0];
#pragma unroll
    for (int h = 0; h < 2; h++) {
        if (((wid & 3) >> 1) == h) {
            const int cbase = wc - h * 64;
#pragma unroll
            for (int i = 0; i < 4; i++) {
                const int mt = wm + i * 16 + (lane >> 2);
#pragma unroll
                for (int j = 0; j < 4; j++) {
                    const int ct = cbase + j * 8 + (lane & 3) * 2;
                    sOut[ct * EPI_P + mt]           = acc[i][j][0];
                    sOut[(ct + 1) * EPI_P + mt]     = acc[i][j][1];
                    sOut[ct * EPI_P + mt + 8]       = acc[i][j][2];
                    sOut[(ct + 1) * EPI_P + mt + 8] = acc[i][j][3];
                }
            }
        }
        __syncthreads();

        const int ce = tid >> 2;
        const int me = (tid & 3) * 32;
        const size_t gb = ((size_t)b * C_ + c0 + h * 64 + ce) * N_ + m0 + me;
        const float* srow = sOut + ce * EPI_P + me;
#pragma unroll
        for (int v = 0; v < 8; v++) {
            const float4 xv = *reinterpret_cast<const float4*>(x + gb + v * 4);
            float4 ov;
            ov.x = g * srow[v * 4 + 0] + xv.x;
            ov.y = g * srow[v * 4 + 1] + xv.y;
            ov.z = g * srow[v * 4 + 2] + xv.z;
            ov.w = g * srow[v * 4 + 3] + xv.w;
            *reinterpret_cast<float4*>(out + gb + v * 4) = ov;
        }
        __syncthreads();
    }
}

// ---------------------------------------------------------------------------
extern "C" void kernel_launch(void* const* d_in, const int* in_sizes, int n_in,
                              void* d_out, int out_size) {
    (void)in_sizes; (void)n_in; (void)out_size;
    const float* x     = (const float*)d_in[0];
    const float* Wq    = (const float*)d_in[1];
    const float* bq    = (const float*)d_in[2];
    const float* Wk    = (const float*)d_in[3];
    const float* bk    = (const float*)d_in[4];
    const float* Wv    = (const float*)d_in[5];
    const float* bv    = (const float*)d_in[6];
    const float* gamma = (const float*)d_in[7];

    float* out  = (float*)d_out;
    float* attn = out + (size_t)B_ * C_ * N_;   // tuple order: (out, attention)

    __nv_bfloat16 *qhi, *qlo, *khi, *klo, *xthi, *xtlo, *wvhi, *wvlo;
    __half *vf16, *af16;
    cudaGetSymbolAddress((void**)&qhi, g_qhi);
    cudaGetSymbolAddress((void**)&qlo, g_qlo);
    cudaGetSymbolAddress((void**)&khi, g_khi);
    cudaGetSymbolAddress((void**)&klo, g_klo);
    cudaGetSymbolAddress((void**)&xthi, g_xthi);
    cudaGetSymbolAddress((void**)&xtlo, g_xtlo);
    cudaGetSymbolAddress((void**)&wvhi, g_wvhi);
    cudaGetSymbolAddress((void**)&wvlo, g_wvlo);
    cudaGetSymbolAddress((void**)&vf16, g_vf16);
    cudaGetSymbolAddress((void**)&af16, g_af16);

    cudaFuncSetAttribute(out_gemm_kernel,
                         cudaFuncAttributeMaxDynamicSharedMemorySize, DYN_OUT);
    cudaFuncSetAttribute(energy_hmma_kernel,
                         cudaFuncAttributeMaxDynamicSharedMemorySize, DYN_E);
    cudaFuncSetAttribute(proj_v_hmma_kernel,
                         cudaFuncAttributeMaxDynamicSharedMemorySize, DYN_V);

    dim3 blk(256);
    convert_x_kernel<<<dim3(N_ / 32, C_ / 32, B_), blk>>>(x, xthi, xtlo);
    convert_w_kernel<<<dim3(C_ * C_ / 256), blk>>>(Wv, wvhi, wvlo);
    proj_qk_kernel<<<dim3(N_ / 64, 1, B_), blk>>>(x, Wq, bq, qhi, qlo);
    proj_qk_kernel<<<dim3(N_ / 64, 1, B_), blk>>>(x, Wk, bk, khi, klo);
    proj_v_hmma_kernel<<<dim3(N_ / 128, C_ / 128, B_), blk, DYN_V>>>(bv, vf16);
    energy_hmma_kernel<<<dim3(N_ / 128, N_ / 128, B_), blk, DYN_E>>>(attn);
    softmax_kernel<<<dim3(B_ * N_), blk>>>(attn, af16);
    out_gemm_kernel<<<dim3(C_ / 128, N_ / 128, B_), blk, DYN_OUT>>>(x, gamma, out);
}

// round 8
// speedup vs baseline: 5.4680x; 1.1392x over previous
#include <cuda_runtime.h>
#include <cuda_bf16.h>
#include <cuda_fp16.h>
#include <cstdint>

// Self_Attn: B=4, C=512, N=4096 (64x64), D=64
// Outputs (tuple order): out [B,C,64,64] fp32, attention [B,N,N] fp32.

namespace {
constexpr int B_ = 4;
constexpr int C_ = 512;
constexpr int N_ = 4096;
constexpr int D_ = 64;

constexpr int KC_O = 64;             // out-GEMM K elems per chunk (128B fp16 row)
constexpr int NCHUNK_O = N_ / KC_O;  // 64
constexpr int STAGE_O = 32768;       // A 16K + V 16K
constexpr int EPI_P = 132;           // epilogue smem pitch (floats)
constexpr int DYN_OUT = 3 * STAGE_O; // 98304 (3-stage ring; epi 33.8K reuses)
constexpr int DYN_E = 128 * EPI_P * 4;  // 67584
constexpr int DYN_V = 128 * EPI_P * 4;  // 67584 (> 2*32768)
constexpr int DYN_QK = 2 * STAGE_O;  // 65536 (2-stage ring, no smem epilogue)
}

// Scratch (device globals; no runtime allocation allowed).
__device__ __nv_bfloat16 g_qhi[B_ * N_ * D_];           // [B][N][D]
__device__ __nv_bfloat16 g_qlo[B_ * N_ * D_];
__device__ __nv_bfloat16 g_khi[B_ * N_ * D_];
__device__ __nv_bfloat16 g_klo[B_ * N_ * D_];
__device__ __nv_bfloat16 g_xthi[(size_t)B_ * N_ * C_];  // x^T [B][N][C] k-contig
__device__ __nv_bfloat16 g_xtlo[(size_t)B_ * N_ * C_];
__device__ __nv_bfloat16 g_wvhi[C_ * C_];               // Wv [c][k]
__device__ __nv_bfloat16 g_wvlo[C_ * C_];
__device__ __nv_bfloat16 g_wqkhi[128 * C_];             // stacked [Wq;Wk] [d][c]
__device__ __nv_bfloat16 g_wqklo[128 * C_];
__device__ __half g_vf16[(size_t)B_ * C_ * N_];         // v [B][C][N] fp16
__device__ __half g_af16[(size_t)B_ * N_ * N_];         // attn fp16 [B][M][N]

// ---------------------------------------------------------------------------
// helpers
// ---------------------------------------------------------------------------
__device__ __forceinline__ uint32_t smem_u32(const void* p) {
    uint32_t a;
    asm("{ .reg .u64 t; cvta.to.shared.u64 t, %1; cvt.u32.u64 %0, t; }" : "=r"(a) : "l"(p));
    return a;
}

__device__ __forceinline__ void cp16(uint32_t dst, const void* src) {
    asm volatile("cp.async.cg.shared.global [%0], [%1], 16;" :: "r"(dst), "l"(src) : "memory");
}

__device__ __forceinline__ void ldsm4(uint32_t* r, uint32_t addr) {
    asm volatile("ldmatrix.sync.aligned.m8n8.x4.shared.b16 {%0,%1,%2,%3}, [%4];"
                 : "=r"(r[0]), "=r"(r[1]), "=r"(r[2]), "=r"(r[3]) : "r"(addr));
}

__device__ __forceinline__ void mma_bf16(float* d, const uint32_t* a, uint32_t b0, uint32_t b1) {
    asm volatile(
        "mma.sync.aligned.m16n8k16.row.col.f32.bf16.bf16.f32 "
        "{%0,%1,%2,%3}, {%4,%5,%6,%7}, {%8,%9}, {%0,%1,%2,%3};"
        : "+f"(d[0]), "+f"(d[1]), "+f"(d[2]), "+f"(d[3])
        : "r"(a[0]), "r"(a[1]), "r"(a[2]), "r"(a[3]), "r"(b0), "r"(b1));
}

__device__ __forceinline__ void mma_f16(float* d, const uint32_t* a, uint32_t b0, uint32_t b1) {
    asm volatile(
        "mma.sync.aligned.m16n8k16.row.col.f32.f16.f16.f32 "
        "{%0,%1,%2,%3}, {%4,%5,%6,%7}, {%8,%9}, {%0,%1,%2,%3};"
        : "+f"(d[0]), "+f"(d[1]), "+f"(d[2]), "+f"(d[3])
        : "r"(a[0]), "r"(a[1]), "r"(a[2]), "r"(a[3]), "r"(b0), "r"(b1));
}

__device__ __forceinline__ uint32_t swz(uint32_t row, uint32_t colbyte) {
    return row * 128u + (colbyte ^ ((row & 7u) << 4));
}

__device__ __forceinline__ uint32_t pack_bf16(float a, float b) {
    __nv_bfloat162 h = __floats2bfloat162_rn(a, b);
    return *reinterpret_cast<uint32_t*>(&h);
}

// ---------------------------------------------------------------------------
// Transpose + split x: x[b][k][n] fp32 -> xT[b][n][k] bf16 hi/lo.
// ---------------------------------------------------------------------------
__global__ void convert_x_kernel(const float* __restrict__ x,
                                 __nv_bfloat16* __restrict__ xthi,
                                 __nv_bfloat16* __restrict__ xtlo) {
    const int b  = blockIdx.z;
    const int n0 = blockIdx.x * 32;
    const int k0 = blockIdx.y * 32;
    __shared__ float t[32][33];
    const int tid = threadIdx.x;
#pragma unroll
    for (int i = 0; i < 4; i++) {
        int idx = tid + i * 256;
        int k = idx >> 5, n = idx & 31;
        t[k][n] = x[((size_t)b * C_ + k0 + k) * N_ + n0 + n];
    }
    __syncthreads();
#pragma unroll
    for (int i = 0; i < 4; i++) {
        int idx = tid + i * 256;
        int n = idx >> 5, k = idx & 31;
        float val = t[k][n];
        __nv_bfloat16 h = __float2bfloat16(val);
        size_t off = ((size_t)b * N_ + n0 + n) * C_ + k0 + k;
        xthi[off] = h;
        xtlo[off] = __float2bfloat16(val - __bfloat162float(h));
    }
}

// Split Wv fp32 -> bf16 hi/lo (elementwise, layout [c][k] already k-contig).
__global__ void convert_w_kernel(const float* __restrict__ W,
                                 __nv_bfloat16* __restrict__ whi,
                                 __nv_bfloat16* __restrict__ wlo) {
    const int i = blockIdx.x * 256 + threadIdx.x;
    float val = W[i];
    __nv_bfloat16 h = __float2bfloat16(val);
    whi[i] = h;
    wlo[i] = __float2bfloat16(val - __bfloat162float(h));
}

// Stack Wq (rows 0..63) and Wk (rows 64..127) into Wqk bf16 hi/lo.
__global__ void convert_wqk_kernel(const float* __restrict__ Wq,
                                   const float* __restrict__ Wk,
                                   __nv_bfloat16* __restrict__ whi,
                                   __nv_bfloat16* __restrict__ wlo) {
    const int i = blockIdx.x * 256 + threadIdx.x;   // over 128*512
    const int d = i >> 9, c = i & 511;
    float val = d < 64 ? Wq[(size_t)d * C_ + c] : Wk[(size_t)(d - 64) * C_ + c];
    __nv_bfloat16 h = __float2bfloat16(val);
    whi[i] = h;
    wlo[i] = __float2bfloat16(val - __bfloat162float(h));
}

// ---------------------------------------------------------------------------
// proj_qk (HMMA, fused): [q|k][b,n,d] = sum_c Wqk[d,c] x[b,c,n] + bias,
// compensated bf16 (3 terms). A = xT [n][c], B = Wqk [d][c], both K-major.
// CTA 128n x 128d (d: 0..63 = q, 64..127 = k), 8 warps, KC=32 packed rows,
// 2-stage ring. Epilogue writes packed bf16x2 hi/lo straight from registers.
// ---------------------------------------------------------------------------
__global__ void __launch_bounds__(256, 2)
proj_qk_hmma_kernel(const float* __restrict__ bq, const float* __restrict__ bk,
                    __nv_bfloat16* __restrict__ qhi, __nv_bfloat16* __restrict__ qlo,
                    __nv_bfloat16* __restrict__ khi, __nv_bfloat16* __restrict__ klo) {
    extern __shared__ char dynsmem[];
    const uint32_t sbase = smem_u32(dynsmem);

    const int tid  = threadIdx.x;
    const int wid  = tid >> 5;
    const int lane = tid & 31;

    const int b  = blockIdx.z;
    const int n0 = blockIdx.x * 128;

    const __nv_bfloat16* Xhi = g_xthi + (size_t)b * N_ * C_;
    const __nv_bfloat16* Xlo = g_xtlo + (size_t)b * N_ * C_;

    const int wm = (wid >> 2) * 64;   // n
    const int wc = (wid & 3) * 32;    // d

    const uint32_t lrow = lane & 15;
    const uint32_t lswz = (lane & 7) << 4;
    const uint32_t lcol = (lane >> 4) << 4;

    float acc[4][4][4] = {};

    auto load_chunk = [&](int kc) {
        const uint32_t st = (uint32_t)(kc & 1) * STAGE_O;
        const size_t koff = (size_t)kc * 32;
#pragma unroll
        for (int t = 0; t < 8; t++) {
            const int idx = tid + t * 256;
            const int part = idx >> 10;          // 0=A(xT), 1=B(Wqk)
            const int a = idx & 1023;
            const int row = a >> 3, seg = a & 7;
            const __nv_bfloat16* src;
            if (part == 0)
                src = (seg < 4 ? Xhi : Xlo) + (size_t)(n0 + row) * C_ + koff + (seg & 3) * 8;
            else
                src = (seg < 4 ? g_wqkhi : g_wqklo) + (size_t)row * C_ + koff + (seg & 3) * 8;
            cp16(sbase + st + (uint32_t)part * 16384u + swz(row, seg * 16), src);
        }
        asm volatile("cp.async.commit_group;" ::: "memory");
    };

    load_chunk(0);

    for (int kc = 0; kc < C_ / 32; kc++) {
        if (kc + 1 < C_ / 32) {
            __syncthreads();
            load_chunk(kc + 1);
            asm volatile("cp.async.wait_group 1;" ::: "memory");
        } else {
            asm volatile("cp.async.wait_group 0;" ::: "memory");
        }
        __syncthreads();

        const uint32_t st = (uint32_t)(kc & 1) * STAGE_O;
        const uint32_t Ab = sbase + st, Bb = Ab + 16384;

#pragma unroll
        for (int ks = 0; ks < 2; ks++) {
            const uint32_t kbHi = (uint32_t)(ks * 32);
            const uint32_t kbLo = 64u + kbHi;

            uint32_t ah[4][4], al[4][4], bh[2][4], bl[2][4];
#pragma unroll
            for (int i = 0; i < 4; i++) {
                const uint32_t row = (uint32_t)(wm + i * 16) + lrow;
                ldsm4(ah[i], Ab + row * 128u + ((kbHi + lcol) ^ lswz));
                ldsm4(al[i], Ab + row * 128u + ((kbLo + lcol) ^ lswz));
            }
#pragma unroll
            for (int j = 0; j < 2; j++) {
                const uint32_t row = (uint32_t)(wc + j * 16) + lrow;
                ldsm4(bh[j], Bb + row * 128u + ((kbHi + lcol) ^ lswz));
                ldsm4(bl[j], Bb + row * 128u + ((kbLo + lcol) ^ lswz));
            }
#pragma unroll
            for (int i = 0; i < 4; i++)
#pragma unroll
                for (int j = 0; j < 4; j++) {
                    const int t2 = j >> 1, p2 = j & 1;
                    mma_bf16(acc[i][j], ah[i], bh[t2][p2], bh[t2][2 + p2]);
                    mma_bf16(acc[i][j], al[i], bh[t2][p2], bh[t2][2 + p2]);
                    mma_bf16(acc[i][j], ah[i], bl[t2][p2], bl[t2][2 + p2]);
                }
        }
    }

    // Epilogue: bias add, split hi/lo, packed bf16x2 stores from registers.
#pragma unroll
    for (int j = 0; j < 4; j++) {
        const int d = wc + j * 8 + (lane & 3) * 2;   // even; pair never straddles 64
        const bool isq = d < 64;
        const int dd = isq ? d : d - 64;
        const float b0v = isq ? bq[dd] : bk[dd];
        const float b1v = isq ? bq[dd + 1] : bk[dd + 1];
        __nv_bfloat16* dhi = isq ? qhi : khi;
        __nv_bfloat16* dlo = isq ? qlo : klo;
#pragma unroll
        for (int i = 0; i < 4; i++) {
            const int n = n0 + wm + i * 16 + (lane >> 2);
#pragma unroll
            for (int r = 0; r < 2; r++) {          // row n, n+8
                const float v0 = acc[i][j][r * 2] + b0v;
                const float v1 = acc[i][j][r * 2 + 1] + b1v;
                const float h0 = __bfloat162float(__float2bfloat16(v0));
                const float h1 = __bfloat162float(__float2bfloat16(v1));
                const size_t off = ((size_t)b * N_ + n + r * 8) * D_ + dd;
                *reinterpret_cast<uint32_t*>(dhi + off) = pack_bf16(v0, v1);
                *reinterpret_cast<uint32_t*>(dlo + off) = pack_bf16(v0 - h0, v1 - h1);
            }
        }
    }
}

// ---------------------------------------------------------------------------
// proj_v (HMMA): v[b,c,n] = sum_k Wv[c,k] x[b,k,n] + bv[c], compensated bf16.
// ---------------------------------------------------------------------------
__global__ void __launch_bounds__(256, 2)
proj_v_hmma_kernel(const float* __restrict__ bias, __half* __restrict__ vf16) {
    extern __shared__ char dynsmem[];
    const uint32_t sbase = smem_u32(dynsmem);

    const int tid  = threadIdx.x;
    const int wid  = tid >> 5;
    const int lane = tid & 31;

    const int b  = blockIdx.z;
    const int n0 = blockIdx.x * 128;
    const int c0 = blockIdx.y * 128;

    const __nv_bfloat16* Whi = g_wvhi;
    const __nv_bfloat16* Wlo = g_wvlo;
    const __nv_bfloat16* Xhi = g_xthi + (size_t)b * N_ * C_;
    const __nv_bfloat16* Xlo = g_xtlo + (size_t)b * N_ * C_;

    const int wm = (wid >> 2) * 64;   // c
    const int wn = (wid & 3) * 32;    // n

    const uint32_t lrow = lane & 15;
    const uint32_t lswz = (lane & 7) << 4;
    const uint32_t lcol = (lane >> 4) << 4;

    float acc[4][4][4] = {};

    auto load_chunk = [&](int kc) {
        const uint32_t st = (uint32_t)(kc & 1) * STAGE_O;
        const size_t koff = (size_t)kc * 32;
#pragma unroll
        for (int t = 0; t < 8; t++) {
            const int idx = tid + t * 256;
            const int part = idx >> 10;          // 0=A(Wv), 1=B(xT)
            const int a = idx & 1023;
            const int row = a >> 3, seg = a & 7;
            const __nv_bfloat16* src;
            if (part == 0)
                src = (seg < 4 ? Whi : Wlo) + (size_t)(c0 + row) * C_ + koff + (seg & 3) * 8;
            else
                src = (seg < 4 ? Xhi : Xlo) + (size_t)(n0 + row) * C_ + koff + (seg & 3) * 8;
            cp16(sbase + st + (uint32_t)part * 16384u + swz(row, seg * 16), src);
        }
        asm volatile("cp.async.commit_group;" ::: "memory");
    };

    load_chunk(0);

    for (int kc = 0; kc < C_ / 32; kc++) {
        if (kc + 1 < C_ / 32) {
            __syncthreads();
            load_chunk(kc + 1);
            asm volatile("cp.async.wait_group 1;" ::: "memory");
        } else {
            asm volatile("cp.async.wait_group 0;" ::: "memory");
        }
        __syncthreads();

        const uint32_t st = (uint32_t)(kc & 1) * STAGE_O;
        const uint32_t Ab = sbase + st, Bb = Ab + 16384;

#pragma unroll
        for (int ks = 0; ks < 2; ks++) {
            const uint32_t kbHi = (uint32_t)(ks * 32);
            const uint32_t kbLo = 64u + kbHi;

            uint32_t ah[4][4], al[4][4], bh[2][4], bl[2][4];
#pragma unroll
            for (int i = 0; i < 4; i++) {
                const uint32_t row = (uint32_t)(wm + i * 16) + lrow;
                ldsm4(ah[i], Ab + row * 128u + ((kbHi + lcol) ^ lswz));
                ldsm4(al[i], Ab + row * 128u + ((kbLo + lcol) ^ lswz));
            }
#pragma unroll
            for (int j = 0; j < 2; j++) {
                const uint32_t row = (uint32_t)(wn + j * 16) + lrow;
                ldsm4(bh[j], Bb + row * 128u + ((kbHi + lcol) ^ lswz));
                ldsm4(bl[j], Bb + row * 128u + ((kbLo + lcol) ^ lswz));
            }
#pragma unroll
            for (int i = 0; i < 4; i++)
#pragma unroll
                for (int j = 0; j < 4; j++) {
                    const int t2 = j >> 1, p2 = j & 1;
                    mma_bf16(acc[i][j], ah[i], bh[t2][p2], bh[t2][2 + p2]);
                    mma_bf16(acc[i][j], al[i], bh[t2][p2], bh[t2][2 + p2]);
                    mma_bf16(acc[i][j], ah[i], bl[t2][p2], bl[t2][2 + p2]);
                }
        }
    }
    __syncthreads();

    // Epilogue: c-major rows in smem (n contiguous), add bias, emit fp16.
    float* sOut = reinterpret_cast<float*>(dynsmem);
#pragma unroll
    for (int i = 0; i < 4; i++) {
        const int ct = wm + i * 16 + (lane >> 2);
#pragma unroll
        for (int j = 0; j < 4; j++) {
            const int nt = wn + j * 8 + (lane & 3) * 2;
            sOut[ct * EPI_P + nt]           = acc[i][j][0];
            sOut[ct * EPI_P + nt + 1]       = acc[i][j][1];
            sOut[(ct + 8) * EPI_P + nt]     = acc[i][j][2];
            sOut[(ct + 8) * EPI_P + nt + 1] = acc[i][j][3];
        }
    }
    __syncthreads();

    const int row = tid >> 1;             // c within tile
    const int col0 = (tid & 1) * 64;      // n offset
    const float bv = bias[c0 + row];
    const float* srow = sOut + row * EPI_P + col0;
    __half* dst = vf16 + ((size_t)b * C_ + c0 + row) * N_ + n0 + col0;
#pragma unroll
    for (int v = 0; v < 16; v++) {
        float4 f = *reinterpret_cast<const float4*>(srow + v * 4);
        __half2 h01 = __floats2half2_rn(f.x + bv, f.y + bv);
        __half2 h23 = __floats2half2_rn(f.z + bv, f.w + bv);
        uint2 u;
        u.x = *reinterpret_cast<uint32_t*>(&h01);
        u.y = *reinterpret_cast<uint32_t*>(&h23);
        *reinterpret_cast<uint2*>(dst + v * 4) = u;
    }
}

// ---------------------------------------------------------------------------
// Energy (HMMA): E[b,m,n] = sum_d q[b,m,d] k[b,n,d], compensated bf16 split.
// ---------------------------------------------------------------------------
__global__ void __launch_bounds__(256)
energy_hmma_kernel(float* __restrict__ attn) {
    extern __shared__ char dynsmem[];
    const uint32_t sbase = smem_u32(dynsmem);

    const int tid  = threadIdx.x;
    const int wid  = tid >> 5;
    const int lane = tid & 31;

    const int b  = blockIdx.z;
    const int n0 = blockIdx.x * 128;
    const int m0 = blockIdx.y * 128;

    const __nv_bfloat16* Qhi = g_qhi + (size_t)b * N_ * D_;
    const __nv_bfloat16* Qlo = g_qlo + (size_t)b * N_ * D_;
    const __nv_bfloat16* Khi = g_khi + (size_t)b * N_ * D_;
    const __nv_bfloat16* Klo = g_klo + (size_t)b * N_ * D_;

    const int wm = (wid >> 2) * 64;
    const int wn = (wid & 3) * 32;

    const uint32_t lrow = lane & 15;
    const uint32_t lswz = (lane & 7) << 4;
    const uint32_t lcol = (lane >> 4) << 4;

#pragma unroll
    for (int t = 0; t < 4; t++) {
        const int idx = tid + t * 256;
        const int row = idx >> 3, seg = idx & 7;
        cp16(sbase + swz(row, seg * 16), Qhi + (size_t)(m0 + row) * D_ + seg * 8);
        cp16(sbase + 16384 + swz(row, seg * 16), Khi + (size_t)(n0 + row) * D_ + seg * 8);
    }
    asm volatile("cp.async.commit_group;" ::: "memory");
#pragma unroll
    for (int t = 0; t < 4; t++) {
        const int idx = tid + t * 256;
        const int row = idx >> 3, seg = idx & 7;
        cp16(sbase + 32768 + swz(row, seg * 16), Qlo + (size_t)(m0 + row) * D_ + seg * 8);
        cp16(sbase + 49152 + swz(row, seg * 16), Klo + (size_t)(n0 + row) * D_ + seg * 8);
    }
    asm volatile("cp.async.commit_group;" ::: "memory");

    float acc[4][4][4] = {};

    asm volatile("cp.async.wait_group 1;" ::: "memory");
    __syncthreads();
#pragma unroll
    for (int ks = 0; ks < 4; ks++) {
        const uint32_t kb = (uint32_t)(ks * 32);
        uint32_t a[4][4], bm[2][4];
#pragma unroll
        for (int i = 0; i < 4; i++) {
            const uint32_t row = (uint32_t)(wm + i * 16) + lrow;
            ldsm4(a[i], sbase + row * 128u + ((kb + lcol) ^ lswz));
        }
#pragma unroll
        for (int j = 0; j < 2; j++) {
            const uint32_t row = (uint32_t)(wn + j * 16) + lrow;
            ldsm4(bm[j], sbase + 16384 + row * 128u + ((kb + lcol) ^ lswz));
        }
#pragma unroll
        for (int i = 0; i < 4; i++)
#pragma unroll
            for (int j = 0; j < 4; j++) {
                const int t2 = j >> 1, p2 = j & 1;
                mma_bf16(acc[i][j], a[i], bm[t2][p2], bm[t2][2 + p2]);
            }
    }

    asm volatile("cp.async.wait_group 0;" ::: "memory");
    __syncthreads();
#pragma unroll
    for (int ks = 0; ks < 4; ks++) {
        const uint32_t kb = (uint32_t)(ks * 32);
        uint32_t ah[4][4], al[4][4], bh[2][4], bl[2][4];
#pragma unroll
        for (int i = 0; i < 4; i++) {
            const uint32_t row = (uint32_t)(wm + i * 16) + lrow;
            ldsm4(ah[i], sbase + row * 128u + ((kb + lcol) ^ lswz));
            ldsm4(al[i], sbase + 32768 + row * 128u + ((kb + lcol) ^ lswz));
        }
#pragma unroll
        for (int j = 0; j < 2; j++) {
            const uint32_t row = (uint32_t)(wn + j * 16) + lrow;
            ldsm4(bh[j], sbase + 16384 + row * 128u + ((kb + lcol) ^ lswz));
            ldsm4(bl[j], sbase + 49152 + row * 128u + ((kb + lcol) ^ lswz));
        }
#pragma unroll
        for (int i = 0; i < 4; i++)
#pragma unroll
            for (int j = 0; j < 4; j++) {
                const int t2 = j >> 1, p2 = j & 1;
                mma_bf16(acc[i][j], al[i], bh[t2][p2], bh[t2][2 + p2]);
                mma_bf16(acc[i][j], ah[i], bl[t2][p2], bl[t2][2 + p2]);
            }
    }

    __syncthreads();
    float* sOut = reinterpret_cast<float*>(dynsmem);
#pragma unroll
    for (int i = 0; i < 4; i++) {
        const int mt = wm + i * 16 + (lane >> 2);
#pragma unroll
        for (int j = 0; j < 4; j++) {
            const int nt = wn + j * 8 + (lane & 3) * 2;
            sOut[mt * EPI_P + nt]           = acc[i][j][0];
            sOut[mt * EPI_P + nt + 1]       = acc[i][j][1];
            sOut[(mt + 8) * EPI_P + nt]     = acc[i][j][2];
            sOut[(mt + 8) * EPI_P + nt + 1] = acc[i][j][3];
        }
    }
    __syncthreads();

    float* eb = attn + (size_t)b * N_ * N_;
    const int row = tid >> 1;
    const int col0 = (tid & 1) * 64;
    const float* srow = sOut + row * EPI_P + col0;
    float* grow = eb + (size_t)(m0 + row) * N_ + n0 + col0;
#pragma unroll
    for (int v = 0; v < 16; v++)
        *reinterpret_cast<float4*>(grow + v * 4) =
            *reinterpret_cast<const float4*>(srow + v * 4);
}

// ---------------------------------------------------------------------------
// Row softmax in place (vectorized); emit attn as single fp16.
// ---------------------------------------------------------------------------
__global__ void softmax_kernel(float* __restrict__ attn,
                               __half* __restrict__ af16) {
    const size_t row = blockIdx.x;
    float* p = attn + row * N_;
    const int tid = threadIdx.x;

    float4 v[4];
    float mx = -3.0e38f;
#pragma unroll
    for (int i = 0; i < 4; i++) {
        v[i] = *reinterpret_cast<const float4*>(p + tid * 4 + i * 1024);
        mx = fmaxf(mx, fmaxf(fmaxf(v[i].x, v[i].y), fmaxf(v[i].z, v[i].w)));
    }
    __shared__ float red[8];
#pragma unroll
    for (int o = 16; o; o >>= 1) mx = fmaxf(mx, __shfl_xor_sync(0xffffffffu, mx, o));
    if ((tid & 31) == 0) red[tid >> 5] = mx;
    __syncthreads();
    mx = red[0];
#pragma unroll
    for (int i = 1; i < 8; i++) mx = fmaxf(mx, red[i]);
    __syncthreads();

    float s = 0.f;
#pragma unroll
    for (int i = 0; i < 4; i++) {
        v[i].x = __expf(v[i].x - mx); v[i].y = __expf(v[i].y - mx);
        v[i].z = __expf(v[i].z - mx); v[i].w = __expf(v[i].w - mx);
        s += (v[i].x + v[i].y) + (v[i].z + v[i].w);
    }
#pragma unroll
    for (int o = 16; o; o >>= 1) s += __shfl_xor_sync(0xffffffffu, s, o);
    if ((tid & 31) == 0) red[tid >> 5] = s;
    __syncthreads();
    s = 0.f;
#pragma unroll
    for (int i = 0; i < 8; i++) s += red[i];
    const float inv = 1.0f / s;

    __half* ph = af16 + row * N_;
#pragma unroll
    for (int i = 0; i < 4; i++) {
        float4 r;
        r.x = v[i].x * inv; r.y = v[i].y * inv; r.z = v[i].z * inv; r.w = v[i].w * inv;
        *reinterpret_cast<float4*>(p + tid * 4 + i * 1024) = r;

        __half2 h01 = __floats2half2_rn(r.x, r.y);
        __half2 h23 = __floats2half2_rn(r.z, r.w);
        uint2 hh;
        hh.x = *reinterpret_cast<uint32_t*>(&h01);
        hh.y = *reinterpret_cast<uint32_t*>(&h23);
        *reinterpret_cast<uint2*>(ph + tid * 4 + i * 1024) = hh;
    }
}

// ---------------------------------------------------------------------------
// out[b,c,m] = gamma * sum_n attn[b,m,n] * v[b,c,n] + x[b,c,m]
// HMMA fp16, single-term; 3-stage ring; 2 CTAs/SM.
// ---------------------------------------------------------------------------
__global__ void __launch_bounds__(256, 2)
out_gemm_kernel(const float* __restrict__ x,
                const float* __restrict__ gamma,
                float* __restrict__ out) {
    extern __shared__ char dynsmem[];
    const uint32_t sbase = smem_u32(dynsmem);

    const int tid  = threadIdx.x;
    const int wid  = tid >> 5;
    const int lane = tid & 31;

    const int b  = blockIdx.z;
    const int c0 = blockIdx.x * 128;
    const int m0 = blockIdx.y * 128;

    const __half* A = g_af16 + (size_t)b * N_ * N_;
    const __half* V = g_vf16 + (size_t)b * C_ * N_;

    const int wm = (wid >> 2) * 64;
    const int wc = (wid & 3) * 32;

    const uint32_t lrow = lane & 15;
    const uint32_t lswz = (lane & 7) << 4;
    const uint32_t lcol = (lane >> 4) << 4;

    float acc[4][4][4] = {};

    auto load_chunk = [&](int kc) {
        const uint32_t st = (uint32_t)(kc % 3) * STAGE_O;
        const size_t koff = (size_t)kc * KC_O;
#pragma unroll
        for (int t = 0; t < 8; t++) {
            const int idx = tid + t * 256;
            const int part = idx >> 10;           // 0=A, 1=V
            const int a = idx & 1023;
            const int row = a >> 3, seg = a & 7;
            const __half* src = part == 0
                ? A + (size_t)(m0 + row) * N_ + koff + seg * 8
                : V + (size_t)(c0 + row) * N_ + koff + seg * 8;
            cp16(sbase + st + (uint32_t)part * 16384u + swz(row, seg * 16), src);
        }
        asm volatile("cp.async.commit_group;" ::: "memory");
    };

    load_chunk(0);
    load_chunk(1);

    for (int kc = 0; kc < NCHUNK_O; kc++) {
        if (kc + 2 < NCHUNK_O) {
            load_chunk(kc + 2);
            asm volatile("cp.async.wait_group 2;" ::: "memory");
        } else if (kc + 1 < NCHUNK_O) {
            asm volatile("cp.async.wait_group 1;" ::: "memory");
        } else {
            asm volatile("cp.async.wait_group 0;" ::: "memory");
        }
        __syncthreads();

        const uint32_t st = (uint32_t)(kc % 3) * STAGE_O;
        const uint32_t Ab = sbase + st, Vb = Ab + 16384;

#pragma unroll
        for (int ks = 0; ks < 4; ks++) {
            const uint32_t kb = (uint32_t)(ks * 32);
            uint32_t a[4][4], bh[2][4];
#pragma unroll
            for (int i = 0; i < 4; i++) {
                const uint32_t row = (uint32_t)(wm + i * 16) + lrow;
                ldsm4(a[i], Ab + row * 128u + ((kb + lcol) ^ lswz));
            }
#pragma unroll
            for (int j = 0; j < 2; j++) {
                const uint32_t row = (uint32_t)(wc + j * 16) + lrow;
                ldsm4(bh[j], Vb + row * 128u + ((kb + lcol) ^ lswz));
            }
#pragma unroll
            for (int i = 0; i < 4; i++)
#pragma unroll
                for (int j = 0; j < 4; j++) {
                    const int t2 = j >> 1, p2 = j & 1;
                    mma_f16(acc[i][j], a[i], bh[t2][p2], bh[t2][2 + p2]);
                }
        }
        __syncthreads();
    }

    // ---- epilogue: two 64-col halves; transpose via smem (33.8KB reuse) ----
    float* sOut = reinterpret_cast<float*>(dynsmem);
    const float g = gamma[0];
#pragma unroll
    for (int h = 0; h < 2; h++) {
        if (((wid & 3) >> 1) == h) {
            const int cbase = wc - h * 64;
#pragma unroll
            for (int i = 0; i < 4; i++) {
                const int mt = wm + i * 16 + (lane >> 2);
#pragma unroll
                for (int j = 0; j < 4; j++) {
                    const int ct = cbase + j * 8 + (lane & 3) * 2;
                    sOut[ct * EPI_P + mt]           = acc[i][j][0];
                    sOut[(ct + 1) * EPI_P + mt]     = acc[i][j][1];
                    sOut[ct * EPI_P + mt + 8]       = acc[i][j][2];
                    sOut[(ct + 1) * EPI_P + mt + 8] = acc[i][j][3];
                }
            }
        }
        __syncthreads();

        const int ce = tid >> 2;
        const int me = (tid & 3) * 32;
        const size_t gb = ((size_t)b * C_ + c0 + h * 64 + ce) * N_ + m0 + me;
        const float* srow = sOut + ce * EPI_P + me;
#pragma unroll
        for (int v = 0; v < 8; v++) {
            const float4 xv = *reinterpret_cast<const float4*>(x + gb + v * 4);
            float4 ov;
            ov.x = g * srow[v * 4 + 0] + xv.x;
            ov.y = g * srow[v * 4 + 1] + xv.y;
            ov.z = g * srow[v * 4 + 2] + xv.z;
            ov.w = g * srow[v * 4 + 3] + xv.w;
            *reinterpret_cast<float4*>(out + gb + v * 4) = ov;
        }
        __syncthreads();
    }
}

// ---------------------------------------------------------------------------
extern "C" void kernel_launch(void* const* d_in, const int* in_sizes, int n_in,
                              void* d_out, int out_size) {
    (void)in_sizes; (void)n_in; (void)out_size;
    const float* x     = (const float*)d_in[0];
    const float* Wq    = (const float*)d_in[1];
    const float* bq    = (const float*)d_in[2];
    const float* Wk    = (const float*)d_in[3];
    const float* bk    = (const float*)d_in[4];
    const float* Wv    = (const float*)d_in[5];
    const float* bv    = (const float*)d_in[6];
    const float* gamma = (const float*)d_in[7];

    float* out  = (float*)d_out;
    float* attn = out + (size_t)B_ * C_ * N_;   // tuple order: (out, attention)

    __nv_bfloat16 *qhi, *qlo, *khi, *klo, *xthi, *xtlo, *wvhi, *wvlo, *wqkhi, *wqklo;
    __half *vf16, *af16;
    cudaGetSymbolAddress((void**)&qhi, g_qhi);
    cudaGetSymbolAddress((void**)&qlo, g_qlo);
    cudaGetSymbolAddress((void**)&khi, g_khi);
    cudaGetSymbolAddress((void**)&klo, g_klo);
    cudaGetSymbolAddress((void**)&xthi, g_xthi);
    cudaGetSymbolAddress((void**)&xtlo, g_xtlo);
    cudaGetSymbolAddress((void**)&wvhi, g_wvhi);
    cudaGetSymbolAddress((void**)&wvlo, g_wvlo);
    cudaGetSymbolAddress((void**)&wqkhi, g_wqkhi);
    cudaGetSymbolAddress((void**)&wqklo, g_wqklo);
    cudaGetSymbolAddress((void**)&vf16, g_vf16);
    cudaGetSymbolAddress((void**)&af16, g_af16);

    cudaFuncSetAttribute(out_gemm_kernel,
                         cudaFuncAttributeMaxDynamicSharedMemorySize, DYN_OUT);
    cudaFuncSetAttribute(energy_hmma_kernel,
                         cudaFuncAttributeMaxDynamicSharedMemorySize, DYN_E);
    cudaFuncSetAttribute(proj_v_hmma_kernel,
                         cudaFuncAttributeMaxDynamicSharedMemorySize, DYN_V);
    cudaFuncSetAttribute(proj_qk_hmma_kernel,
                         cudaFuncAttributeMaxDynamicSharedMemorySize, DYN_QK);

    dim3 blk(256);
    convert_x_kernel<<<dim3(N_ / 32, C_ / 32, B_), blk>>>(x, xthi, xtlo);
    convert_w_kernel<<<dim3(C_ * C_ / 256), blk>>>(Wv, wvhi, wvlo);
    convert_wqk_kernel<<<dim3(128 * C_ / 256), blk>>>(Wq, Wk, wqkhi, wqklo);
    proj_qk_hmma_kernel<<<dim3(N_ / 128, 1, B_), blk, DYN_QK>>>(bq, bk, qhi, qlo, khi, klo);
    proj_v_hmma_kernel<<<dim3(N_ / 128, C_ / 128, B_), blk, DYN_V>>>(bv, vf16);
    energy_hmma_kernel<<<dim3(N_ / 128, N_ / 128, B_), blk, DYN_E>>>(attn);
    softmax_kernel<<<dim3(B_ * N_), blk>>>(attn, af16);
    out_gemm_kernel<<<dim3(C_ / 128, N_ / 128, B_), blk, DYN_OUT>>>(x, gamma, out);
}

// round 9
// speedup vs baseline: 5.5599x; 1.0168x over previous
#include <cuda_runtime.h>
#include <cuda_bf16.h>
#include <cuda_fp16.h>
#include <cstdint>

// Self_Attn: B=4, C=512, N=4096 (64x64), D=64
// Outputs (tuple order): out [B,C,64,64] fp32, attention [B,N,N] fp32.

namespace {
constexpr int B_ = 4;
constexpr int C_ = 512;
constexpr int N_ = 4096;
constexpr int D_ = 64;

constexpr int KC_O = 64;             // out-GEMM K elems per chunk (128B fp16 row)
constexpr int NCHUNK_O = N_ / KC_O;  // 64
constexpr int STAGE_P = 32768;       // proj stage: A 16K + B 16K
constexpr int STAGE_O = 24576;       // out stage: A 16K + V 8K
constexpr int EPI_P = 132;           // epilogue smem pitch (floats)
constexpr int DYN_OUT = 2 * STAGE_O; // 49152 (2-stage; epi 33.8K reuses)
constexpr int DYN_E = 128 * EPI_P * 4;  // 67584
constexpr int DYN_V = 128 * EPI_P * 4;  // 67584
constexpr int DYN_QK = 2 * STAGE_P;  // 65536
}

// Scratch (device globals; no runtime allocation allowed).
__device__ __nv_bfloat16 g_qhi[B_ * N_ * D_];           // [B][N][D]
__device__ __nv_bfloat16 g_qlo[B_ * N_ * D_];
__device__ __nv_bfloat16 g_khi[B_ * N_ * D_];
__device__ __nv_bfloat16 g_klo[B_ * N_ * D_];
__device__ __nv_bfloat16 g_xthi[(size_t)B_ * N_ * C_];  // x^T [B][N][C] k-contig
__device__ __nv_bfloat16 g_xtlo[(size_t)B_ * N_ * C_];
__device__ __nv_bfloat16 g_wvhi[C_ * C_];               // Wv [c][k]
__device__ __nv_bfloat16 g_wvlo[C_ * C_];
__device__ __nv_bfloat16 g_wqkhi[128 * C_];             // stacked [Wq;Wk] [d][c]
__device__ __nv_bfloat16 g_wqklo[128 * C_];
__device__ __half g_vf16[(size_t)B_ * C_ * N_];         // v [B][C][N] fp16
__device__ __half g_af16[(size_t)B_ * N_ * N_];         // attn fp16 [B][M][N]

// ---------------------------------------------------------------------------
// helpers
// ---------------------------------------------------------------------------
__device__ __forceinline__ uint32_t smem_u32(const void* p) {
    uint32_t a;
    asm("{ .reg .u64 t; cvta.to.shared.u64 t, %1; cvt.u32.u64 %0, t; }" : "=r"(a) : "l"(p));
    return a;
}

__device__ __forceinline__ void cp16(uint32_t dst, const void* src) {
    asm volatile("cp.async.cg.shared.global [%0], [%1], 16;" :: "r"(dst), "l"(src) : "memory");
}

__device__ __forceinline__ void ldsm4(uint32_t* r, uint32_t addr) {
    asm volatile("ldmatrix.sync.aligned.m8n8.x4.shared.b16 {%0,%1,%2,%3}, [%4];"
                 : "=r"(r[0]), "=r"(r[1]), "=r"(r[2]), "=r"(r[3]) : "r"(addr));
}

__device__ __forceinline__ void mma_bf16(float* d, const uint32_t* a, uint32_t b0, uint32_t b1) {
    asm volatile(
        "mma.sync.aligned.m16n8k16.row.col.f32.bf16.bf16.f32 "
        "{%0,%1,%2,%3}, {%4,%5,%6,%7}, {%8,%9}, {%0,%1,%2,%3};"
        : "+f"(d[0]), "+f"(d[1]), "+f"(d[2]), "+f"(d[3])
        : "r"(a[0]), "r"(a[1]), "r"(a[2]), "r"(a[3]), "r"(b0), "r"(b1));
}

__device__ __forceinline__ void mma_f16(float* d, const uint32_t* a, uint32_t b0, uint32_t b1) {
    asm volatile(
        "mma.sync.aligned.m16n8k16.row.col.f32.f16.f16.f32 "
        "{%0,%1,%2,%3}, {%4,%5,%6,%7}, {%8,%9}, {%0,%1,%2,%3};"
        : "+f"(d[0]), "+f"(d[1]), "+f"(d[2]), "+f"(d[3])
        : "r"(a[0]), "r"(a[1]), "r"(a[2]), "r"(a[3]), "r"(b0), "r"(b1));
}

__device__ __forceinline__ uint32_t swz(uint32_t row, uint32_t colbyte) {
    return row * 128u + (colbyte ^ ((row & 7u) << 4));
}

__device__ __forceinline__ uint32_t pack_bf16(float a, float b) {
    __nv_bfloat162 h = __floats2bfloat162_rn(a, b);
    return *reinterpret_cast<uint32_t*>(&h);
}

// ---------------------------------------------------------------------------
// Transpose + split x: x[b][k][n] fp32 -> xT[b][n][k] bf16 hi/lo.
// ---------------------------------------------------------------------------
__global__ void convert_x_kernel(const float* __restrict__ x,
                                 __nv_bfloat16* __restrict__ xthi,
                                 __nv_bfloat16* __restrict__ xtlo) {
    const int b  = blockIdx.z;
    const int n0 = blockIdx.x * 32;
    const int k0 = blockIdx.y * 32;
    __shared__ float t[32][33];
    const int tid = threadIdx.x;
#pragma unroll
    for (int i = 0; i < 4; i++) {
        int idx = tid + i * 256;
        int k = idx >> 5, n = idx & 31;
        t[k][n] = x[((size_t)b * C_ + k0 + k) * N_ + n0 + n];
    }
    __syncthreads();
#pragma unroll
    for (int i = 0; i < 4; i++) {
        int idx = tid + i * 256;
        int n = idx >> 5, k = idx & 31;
        float val = t[k][n];
        __nv_bfloat16 h = __float2bfloat16(val);
        size_t off = ((size_t)b * N_ + n0 + n) * C_ + k0 + k;
        xthi[off] = h;
        xtlo[off] = __float2bfloat16(val - __bfloat162float(h));
    }
}

// Split Wv fp32 -> bf16 hi/lo.
__global__ void convert_w_kernel(const float* __restrict__ W,
                                 __nv_bfloat16* __restrict__ whi,
                                 __nv_bfloat16* __restrict__ wlo) {
    const int i = blockIdx.x * 256 + threadIdx.x;
    float val = W[i];
    __nv_bfloat16 h = __float2bfloat16(val);
    whi[i] = h;
    wlo[i] = __float2bfloat16(val - __bfloat162float(h));
}

// Stack Wq (rows 0..63) and Wk (rows 64..127) into Wqk bf16 hi/lo.
__global__ void convert_wqk_kernel(const float* __restrict__ Wq,
                                   const float* __restrict__ Wk,
                                   __nv_bfloat16* __restrict__ whi,
                                   __nv_bfloat16* __restrict__ wlo) {
    const int i = blockIdx.x * 256 + threadIdx.x;   // over 128*512
    const int d = i >> 9, c = i & 511;
    float val = d < 64 ? Wq[(size_t)d * C_ + c] : Wk[(size_t)(d - 64) * C_ + c];
    __nv_bfloat16 h = __float2bfloat16(val);
    whi[i] = h;
    wlo[i] = __float2bfloat16(val - __bfloat162float(h));
}

// ---------------------------------------------------------------------------
// proj_qk (HMMA, fused): [q|k][b,n,d] = sum_c Wqk[d,c] x[b,c,n] + bias,
// compensated bf16 (3 terms). CTA 128n x 128d, 2-stage ring.
// ---------------------------------------------------------------------------
__global__ void __launch_bounds__(256, 2)
proj_qk_hmma_kernel(const float* __restrict__ bq, const float* __restrict__ bk,
                    __nv_bfloat16* __restrict__ qhi, __nv_bfloat16* __restrict__ qlo,
                    __nv_bfloat16* __restrict__ khi, __nv_bfloat16* __restrict__ klo) {
    extern __shared__ char dynsmem[];
    const uint32_t sbase = smem_u32(dynsmem);

    const int tid  = threadIdx.x;
    const int wid  = tid >> 5;
    const int lane = tid & 31;

    const int b  = blockIdx.z;
    const int n0 = blockIdx.x * 128;

    const __nv_bfloat16* Xhi = g_xthi + (size_t)b * N_ * C_;
    const __nv_bfloat16* Xlo = g_xtlo + (size_t)b * N_ * C_;

    const int wm = (wid >> 2) * 64;   // n
    const int wc = (wid & 3) * 32;    // d

    const uint32_t lrow = lane & 15;
    const uint32_t lswz = (lane & 7) << 4;
    const uint32_t lcol = (lane >> 4) << 4;

    float acc[4][4][4] = {};

    auto load_chunk = [&](int kc) {
        const uint32_t st = (uint32_t)(kc & 1) * STAGE_P;
        const size_t koff = (size_t)kc * 32;
#pragma unroll
        for (int t = 0; t < 8; t++) {
            const int idx = tid + t * 256;
            const int part = idx >> 10;          // 0=A(xT), 1=B(Wqk)
            const int a = idx & 1023;
            const int row = a >> 3, seg = a & 7;
            const __nv_bfloat16* src;
            if (part == 0)
                src = (seg < 4 ? Xhi : Xlo) + (size_t)(n0 + row) * C_ + koff + (seg & 3) * 8;
            else
                src = (seg < 4 ? g_wqkhi : g_wqklo) + (size_t)row * C_ + koff + (seg & 3) * 8;
            cp16(sbase + st + (uint32_t)part * 16384u + swz(row, seg * 16), src);
        }
        asm volatile("cp.async.commit_group;" ::: "memory");
    };

    load_chunk(0);

    for (int kc = 0; kc < C_ / 32; kc++) {
        asm volatile("cp.async.wait_group 0;" ::: "memory");
        __syncthreads();
        if (kc + 1 < C_ / 32) load_chunk(kc + 1);

        const uint32_t st = (uint32_t)(kc & 1) * STAGE_P;
        const uint32_t Ab = sbase + st, Bb = Ab + 16384;

#pragma unroll
        for (int ks = 0; ks < 2; ks++) {
            const uint32_t kbHi = (uint32_t)(ks * 32);
            const uint32_t kbLo = 64u + kbHi;

            uint32_t ah[4][4], al[4][4], bh[2][4], bl[2][4];
#pragma unroll
            for (int i = 0; i < 4; i++) {
                const uint32_t row = (uint32_t)(wm + i * 16) + lrow;
                ldsm4(ah[i], Ab + row * 128u + ((kbHi + lcol) ^ lswz));
                ldsm4(al[i], Ab + row * 128u + ((kbLo + lcol) ^ lswz));
            }
#pragma unroll
            for (int j = 0; j < 2; j++) {
                const uint32_t row = (uint32_t)(wc + j * 16) + lrow;
                ldsm4(bh[j], Bb + row * 128u + ((kbHi + lcol) ^ lswz));
                ldsm4(bl[j], Bb + row * 128u + ((kbLo + lcol) ^ lswz));
            }
#pragma unroll
            for (int i = 0; i < 4; i++)
#pragma unroll
                for (int j = 0; j < 4; j++) {
                    const int t2 = j >> 1, p2 = j & 1;
                    mma_bf16(acc[i][j], ah[i], bh[t2][p2], bh[t2][2 + p2]);
                    mma_bf16(acc[i][j], al[i], bh[t2][p2], bh[t2][2 + p2]);
                    mma_bf16(acc[i][j], ah[i], bl[t2][p2], bl[t2][2 + p2]);
                }
        }
        __syncthreads();
    }

    // Epilogue: bias add, split hi/lo, packed bf16x2 stores from registers.
#pragma unroll
    for (int j = 0; j < 4; j++) {
        const int d = wc + j * 8 + (lane & 3) * 2;   // even; pair never straddles 64
        const bool isq = d < 64;
        const int dd = isq ? d : d - 64;
        const float b0v = isq ? bq[dd] : bk[dd];
        const float b1v = isq ? bq[dd + 1] : bk[dd + 1];
        __nv_bfloat16* dhi = isq ? qhi : khi;
        __nv_bfloat16* dlo = isq ? qlo : klo;
#pragma unroll
        for (int i = 0; i < 4; i++) {
            const int n = n0 + wm + i * 16 + (lane >> 2);
#pragma unroll
            for (int r = 0; r < 2; r++) {          // row n, n+8
                const float v0 = acc[i][j][r * 2] + b0v;
                const float v1 = acc[i][j][r * 2 + 1] + b1v;
                const float h0 = __bfloat162float(__float2bfloat16(v0));
                const float h1 = __bfloat162float(__float2bfloat16(v1));
                const size_t off = ((size_t)b * N_ + n + r * 8) * D_ + dd;
                *reinterpret_cast<uint32_t*>(dhi + off) = pack_bf16(v0, v1);
                *reinterpret_cast<uint32_t*>(dlo + off) = pack_bf16(v0 - h0, v1 - h1);
            }
        }
    }
}

// ---------------------------------------------------------------------------
// proj_v (HMMA): v[b,c,n] = sum_k Wv[c,k] x[b,k,n] + bv[c], compensated bf16.
// Grid: x = c (adjacent CTAs share the xT tile in L2), y = n.
// ---------------------------------------------------------------------------
__global__ void __launch_bounds__(256, 2)
proj_v_hmma_kernel(const float* __restrict__ bias, __half* __restrict__ vf16) {
    extern __shared__ char dynsmem[];
    const uint32_t sbase = smem_u32(dynsmem);

    const int tid  = threadIdx.x;
    const int wid  = tid >> 5;
    const int lane = tid & 31;

    const int b  = blockIdx.z;
    const int c0 = blockIdx.x * 128;
    const int n0 = blockIdx.y * 128;

    const __nv_bfloat16* Whi = g_wvhi;
    const __nv_bfloat16* Wlo = g_wvlo;
    const __nv_bfloat16* Xhi = g_xthi + (size_t)b * N_ * C_;
    const __nv_bfloat16* Xlo = g_xtlo + (size_t)b * N_ * C_;

    const int wm = (wid >> 2) * 64;   // c
    const int wn = (wid & 3) * 32;    // n

    const uint32_t lrow = lane & 15;
    const uint32_t lswz = (lane & 7) << 4;
    const uint32_t lcol = (lane >> 4) << 4;

    float acc[4][4][4] = {};

    auto load_chunk = [&](int kc) {
        const uint32_t st = (uint32_t)(kc & 1) * STAGE_P;
        const size_t koff = (size_t)kc * 32;
#pragma unroll
        for (int t = 0; t < 8; t++) {
            const int idx = tid + t * 256;
            const int part = idx >> 10;          // 0=A(Wv), 1=B(xT)
            const int a = idx & 1023;
            const int row = a >> 3, seg = a & 7;
            const __nv_bfloat16* src;
            if (part == 0)
                src = (seg < 4 ? Whi : Wlo) + (size_t)(c0 + row) * C_ + koff + (seg & 3) * 8;
            else
                src = (seg < 4 ? Xhi : Xlo) + (size_t)(n0 + row) * C_ + koff + (seg & 3) * 8;
            cp16(sbase + st + (uint32_t)part * 16384u + swz(row, seg * 16), src);
        }
        asm volatile("cp.async.commit_group;" ::: "memory");
    };

    load_chunk(0);

    for (int kc = 0; kc < C_ / 32; kc++) {
        asm volatile("cp.async.wait_group 0;" ::: "memory");
        __syncthreads();
        if (kc + 1 < C_ / 32) load_chunk(kc + 1);

        const uint32_t st = (uint32_t)(kc & 1) * STAGE_P;
        const uint32_t Ab = sbase + st, Bb = Ab + 16384;

#pragma unroll
        for (int ks = 0; ks < 2; ks++) {
            const uint32_t kbHi = (uint32_t)(ks * 32);
            const uint32_t kbLo = 64u + kbHi;

            uint32_t ah[4][4], al[4][4], bh[2][4], bl[2][4];
#pragma unroll
            for (int i = 0; i < 4; i++) {
                const uint32_t row = (uint32_t)(wm + i * 16) + lrow;
                ldsm4(ah[i], Ab + row * 128u + ((kbHi + lcol) ^ lswz));
                ldsm4(al[i], Ab + row * 128u + ((kbLo + lcol) ^ lswz));
            }
#pragma unroll
            for (int j = 0; j < 2; j++) {
                const uint32_t row = (uint32_t)(wn + j * 16) + lrow;
                ldsm4(bh[j], Bb + row * 128u + ((kbHi + lcol) ^ lswz));
                ldsm4(bl[j], Bb + row * 128u + ((kbLo + lcol) ^ lswz));
            }
#pragma unroll
            for (int i = 0; i < 4; i++)
#pragma unroll
                for (int j = 0; j < 4; j++) {
                    const int t2 = j >> 1, p2 = j & 1;
                    mma_bf16(acc[i][j], ah[i], bh[t2][p2], bh[t2][2 + p2]);
                    mma_bf16(acc[i][j], al[i], bh[t2][p2], bh[t2][2 + p2]);
                    mma_bf16(acc[i][j], ah[i], bl[t2][p2], bl[t2][2 + p2]);
                }
        }
        __syncthreads();
    }

    // Epilogue: c-major rows in smem (n contiguous), add bias, emit fp16.
    float* sOut = reinterpret_cast<float*>(dynsmem);
#pragma unroll
    for (int i = 0; i < 4; i++) {
        const int ct = wm + i * 16 + (lane >> 2);
#pragma unroll
        for (int j = 0; j < 4; j++) {
            const int nt = wn + j * 8 + (lane & 3) * 2;
            sOut[ct * EPI_P + nt]           = acc[i][j][0];
            sOut[ct * EPI_P + nt + 1]       = acc[i][j][1];
            sOut[(ct + 8) * EPI_P + nt]     = acc[i][j][2];
            sOut[(ct + 8) * EPI_P + nt + 1] = acc[i][j][3];
        }
    }
    __syncthreads();

    const int row = tid >> 1;             // c within tile
    const int col0 = (tid & 1) * 64;      // n offset
    const float bv = bias[c0 + row];
    const float* srow = sOut + row * EPI_P + col0;
    __half* dst = vf16 + ((size_t)b * C_ + c0 + row) * N_ + n0 + col0;
#pragma unroll
    for (int v = 0; v < 16; v++) {
        float4 f = *reinterpret_cast<const float4*>(srow + v * 4);
        __half2 h01 = __floats2half2_rn(f.x + bv, f.y + bv);
        __half2 h23 = __floats2half2_rn(f.z + bv, f.w + bv);
        uint2 u;
        u.x = *reinterpret_cast<uint32_t*>(&h01);
        u.y = *reinterpret_cast<uint32_t*>(&h23);
        *reinterpret_cast<uint2*>(dst + v * 4) = u;
    }
}

// ---------------------------------------------------------------------------
// Energy (HMMA): E[b,m,n] = sum_d q[b,m,d] k[b,n,d], compensated bf16 split.
// ---------------------------------------------------------------------------
__global__ void __launch_bounds__(256)
energy_hmma_kernel(float* __restrict__ attn) {
    extern __shared__ char dynsmem[];
    const uint32_t sbase = smem_u32(dynsmem);

    const int tid  = threadIdx.x;
    const int wid  = tid >> 5;
    const int lane = tid & 31;

    const int b  = blockIdx.z;
    const int n0 = blockIdx.x * 128;
    const int m0 = blockIdx.y * 128;

    const __nv_bfloat16* Qhi = g_qhi + (size_t)b * N_ * D_;
    const __nv_bfloat16* Qlo = g_qlo + (size_t)b * N_ * D_;
    const __nv_bfloat16* Khi = g_khi + (size_t)b * N_ * D_;
    const __nv_bfloat16* Klo = g_klo + (size_t)b * N_ * D_;

    const int wm = (wid >> 2) * 64;
    const int wn = (wid & 3) * 32;

    const uint32_t lrow = lane & 15;
    const uint32_t lswz = (lane & 7) << 4;
    const uint32_t lcol = (lane >> 4) << 4;

#pragma unroll
    for (int t = 0; t < 4; t++) {
        const int idx = tid + t * 256;
        const int row = idx >> 3, seg = idx & 7;
        cp16(sbase + swz(row, seg * 16), Qhi + (size_t)(m0 + row) * D_ + seg * 8);
        cp16(sbase + 16384 + swz(row, seg * 16), Khi + (size_t)(n0 + row) * D_ + seg * 8);
    }
    asm volatile("cp.async.commit_group;" ::: "memory");
#pragma unroll
    for (int t = 0; t < 4; t++) {
        const int idx = tid + t * 256;
        const int row = idx >> 3, seg = idx & 7;
        cp16(sbase + 32768 + swz(row, seg * 16), Qlo + (size_t)(m0 + row) * D_ + seg * 8);
        cp16(sbase + 49152 + swz(row, seg * 16), Klo + (size_t)(n0 + row) * D_ + seg * 8);
    }
    asm volatile("cp.async.commit_group;" ::: "memory");

    float acc[4][4][4] = {};

    asm volatile("cp.async.wait_group 1;" ::: "memory");
    __syncthreads();
#pragma unroll
    for (int ks = 0; ks < 4; ks++) {
        const uint32_t kb = (uint32_t)(ks * 32);
        uint32_t a[4][4], bm[2][4];
#pragma unroll
        for (int i = 0; i < 4; i++) {
            const uint32_t row = (uint32_t)(wm + i * 16) + lrow;
            ldsm4(a[i], sbase + row * 128u + ((kb + lcol) ^ lswz));
        }
#pragma unroll
        for (int j = 0; j < 2; j++) {
            const uint32_t row = (uint32_t)(wn + j * 16) + lrow;
            ldsm4(bm[j], sbase + 16384 + row * 128u + ((kb + lcol) ^ lswz));
        }
#pragma unroll
        for (int i = 0; i < 4; i++)
#pragma unroll
            for (int j = 0; j < 4; j++) {
                const int t2 = j >> 1, p2 = j & 1;
                mma_bf16(acc[i][j], a[i], bm[t2][p2], bm[t2][2 + p2]);
            }
    }

    asm volatile("cp.async.wait_group 0;" ::: "memory");
    __syncthreads();
#pragma unroll
    for (int ks = 0; ks < 4; ks++) {
        const uint32_t kb = (uint32_t)(ks * 32);
        uint32_t ah[4][4], al[4][4], bh[2][4], bl[2][4];
#pragma unroll
        for (int i = 0; i < 4; i++) {
            const uint32_t row = (uint32_t)(wm + i * 16) + lrow;
            ldsm4(ah[i], sbase + row * 128u + ((kb + lcol) ^ lswz));
            ldsm4(al[i], sbase + 32768 + row * 128u + ((kb + lcol) ^ lswz));
        }
#pragma unroll
        for (int j = 0; j < 2; j++) {
            const uint32_t row = (uint32_t)(wn + j * 16) + lrow;
            ldsm4(bh[j], sbase + 16384 + row * 128u + ((kb + lcol) ^ lswz));
            ldsm4(bl[j], sbase + 49152 + row * 128u + ((kb + lcol) ^ lswz));
        }
#pragma unroll
        for (int i = 0; i < 4; i++)
#pragma unroll
            for (int j = 0; j < 4; j++) {
                const int t2 = j >> 1, p2 = j & 1;
                mma_bf16(acc[i][j], al[i], bh[t2][p2], bh[t2][2 + p2]);
                mma_bf16(acc[i][j], ah[i], bl[t2][p2], bl[t2][2 + p2]);
            }
    }

    __syncthreads();
    float* sOut = reinterpret_cast<float*>(dynsmem);
#pragma unroll
    for (int i = 0; i < 4; i++) {
        const int mt = wm + i * 16 + (lane >> 2);
#pragma unroll
        for (int j = 0; j < 4; j++) {
            const int nt = wn + j * 8 + (lane & 3) * 2;
            sOut[mt * EPI_P + nt]           = acc[i][j][0];
            sOut[mt * EPI_P + nt + 1]       = acc[i][j][1];
            sOut[(mt + 8) * EPI_P + nt]     = acc[i][j][2];
            sOut[(mt + 8) * EPI_P + nt + 1] = acc[i][j][3];
        }
    }
    __syncthreads();

    float* eb = attn + (size_t)b * N_ * N_;
    const int row = tid >> 1;
    const int col0 = (tid & 1) * 64;
    const float* srow = sOut + row * EPI_P + col0;
    float* grow = eb + (size_t)(m0 + row) * N_ + n0 + col0;
#pragma unroll
    for (int v = 0; v < 16; v++)
        *reinterpret_cast<float4*>(grow + v * 4) =
            *reinterpret_cast<const float4*>(srow + v * 4);
}

// ---------------------------------------------------------------------------
// Row softmax in place (vectorized); emit attn as single fp16.
// ---------------------------------------------------------------------------
__global__ void softmax_kernel(float* __restrict__ attn,
                               __half* __restrict__ af16) {
    const size_t row = blockIdx.x;
    float* p = attn + row * N_;
    const int tid = threadIdx.x;

    float4 v[4];
    float mx = -3.0e38f;
#pragma unroll
    for (int i = 0; i < 4; i++) {
        v[i] = *reinterpret_cast<const float4*>(p + tid * 4 + i * 1024);
        mx = fmaxf(mx, fmaxf(fmaxf(v[i].x, v[i].y), fmaxf(v[i].z, v[i].w)));
    }
    __shared__ float red[8];
#pragma unroll
    for (int o = 16; o; o >>= 1) mx = fmaxf(mx, __shfl_xor_sync(0xffffffffu, mx, o));
    if ((tid & 31) == 0) red[tid >> 5] = mx;
    __syncthreads();
    mx = red[0];
#pragma unroll
    for (int i = 1; i < 8; i++) mx = fmaxf(mx, red[i]);
    __syncthreads();

    float s = 0.f;
#pragma unroll
    for (int i = 0; i < 4; i++) {
        v[i].x = __expf(v[i].x - mx); v[i].y = __expf(v[i].y - mx);
        v[i].z = __expf(v[i].z - mx); v[i].w = __expf(v[i].w - mx);
        s += (v[i].x + v[i].y) + (v[i].z + v[i].w);
    }
#pragma unroll
    for (int o = 16; o; o >>= 1) s += __shfl_xor_sync(0xffffffffu, s, o);
    if ((tid & 31) == 0) red[tid >> 5] = s;
    __syncthreads();
    s = 0.f;
#pragma unroll
    for (int i = 0; i < 8; i++) s += red[i];
    const float inv = 1.0f / s;

    __half* ph = af16 + row * N_;
#pragma unroll
    for (int i = 0; i < 4; i++) {
        float4 r;
        r.x = v[i].x * inv; r.y = v[i].y * inv; r.z = v[i].z * inv; r.w = v[i].w * inv;
        *reinterpret_cast<float4*>(p + tid * 4 + i * 1024) = r;

        __half2 h01 = __floats2half2_rn(r.x, r.y);
        __half2 h23 = __floats2half2_rn(r.z, r.w);
        uint2 hh;
        hh.x = *reinterpret_cast<uint32_t*>(&h01);
        hh.y = *reinterpret_cast<uint32_t*>(&h23);
        *reinterpret_cast<uint2*>(ph + tid * 4 + i * 1024) = hh;
    }
}

// ---------------------------------------------------------------------------
// out[b,c,m] = gamma * sum_n attn[b,m,n] * v[b,c,n] + x[b,c,m]
// HMMA fp16, single-term. CTA 128m x 64c, warp tile 64x16, acc 32 floats.
// 2-stage ring (24KB/stage), __launch_bounds__(256,3) -> 3 CTAs/SM, 24 warps.
// One __syncthreads per chunk: wait -> sync -> load(kc+1) -> compute(kc).
// ---------------------------------------------------------------------------
__global__ void __launch_bounds__(256, 3)
out_gemm_kernel(const float* __restrict__ x,
                const float* __restrict__ gamma,
                float* __restrict__ out) {
    extern __shared__ char dynsmem[];
    const uint32_t sbase = smem_u32(dynsmem);

    const int tid  = threadIdx.x;
    const int wid  = tid >> 5;
    const int lane = tid & 31;

    const int b  = blockIdx.z;
    const int c0 = blockIdx.x * 64;    // c fastest: 8 siblings share A tile in L2
    const int m0 = blockIdx.y * 128;

    const __half* A = g_af16 + (size_t)b * N_ * N_;
    const __half* V = g_vf16 + (size_t)b * C_ * N_;

    const int wm = (wid >> 2) * 64;    // m offset of warp
    const int wc = (wid & 3) * 16;     // c offset of warp

    const uint32_t lrow = lane & 15;
    const uint32_t lswz = (lane & 7) << 4;
    const uint32_t lcol = (lane >> 4) << 4;

    float acc[4][2][4] = {};   // [m16][c8][reg]

    // per chunk: A 1024 cp16 (16KB) + V 512 cp16 (8KB) = 6 per thread
    auto load_chunk = [&](int kc) {
        const uint32_t st = (uint32_t)(kc & 1) * STAGE_O;
        const size_t koff = (size_t)kc * KC_O;
#pragma unroll
        for (int t = 0; t < 6; t++) {
            const int idx = tid + t * 256;
            if (idx < 1024) {
                const int row = idx >> 3, seg = idx & 7;
                cp16(sbase + st + swz(row, seg * 16),
                     A + (size_t)(m0 + row) * N_ + koff + seg * 8);
            } else {
                const int i2 = idx - 1024;
                const int row = i2 >> 3, seg = i2 & 7;
                cp16(sbase + st + 16384u + swz(row, seg * 16),
                     V + (size_t)(c0 + row) * N_ + koff + seg * 8);
            }
        }
        asm volatile("cp.async.commit_group;" ::: "memory");
    };

    load_chunk(0);

    for (int kc = 0; kc < NCHUNK_O; kc++) {
        asm volatile("cp.async.wait_group 0;" ::: "memory");
        __syncthreads();     // publishes stage kc; all warps done with stage kc-1
        if (kc + 1 < NCHUNK_O) load_chunk(kc + 1);   // writes stage (kc-1)&1: safe

        const uint32_t st = (uint32_t)(kc & 1) * STAGE_O;
        const uint32_t Ab = sbase + st, Vb = Ab + 16384;

#pragma unroll
        for (int ks = 0; ks < 4; ks++) {
            const uint32_t kb = (uint32_t)(ks * 32);
            uint32_t a[4][4], bm[4];
#pragma unroll
            for (int i = 0; i < 4; i++) {
                const uint32_t row = (uint32_t)(wm + i * 16) + lrow;
                ldsm4(a[i], Ab + row * 128u + ((kb + lcol) ^ lswz));
            }
            {
                const uint32_t row = (uint32_t)wc + lrow;
                ldsm4(bm, Vb + row * 128u + ((kb + lcol) ^ lswz));
            }
#pragma unroll
            for (int i = 0; i < 4; i++)
#pragma unroll
                for (int p2 = 0; p2 < 2; p2++)
                    mma_f16(acc[i][p2], a[i], bm[p2], bm[2 + p2]);
        }
    }
    __syncthreads();   // all warps done computing before epilogue reuses stages

    // ---- epilogue: full 64c x 128m transpose via smem (33.8KB <= 48KB) ----
    float* sOut = reinterpret_cast<float*>(dynsmem);
#pragma unroll
    for (int i = 0; i < 4; i++) {
        const int mt = wm + i * 16 + (lane >> 2);
#pragma unroll
        for (int p2 = 0; p2 < 2; p2++) {
            const int ct = wc + p2 * 8 + (lane & 3) * 2;
            sOut[ct * EPI_P + mt]           = acc[i][p2][0];
            sOut[(ct + 1) * EPI_P + mt]     = acc[i][p2][1];
            sOut[ct * EPI_P + mt + 8]       = acc[i][p2][2];
            sOut[(ct + 1) * EPI_P + mt + 8] = acc[i][p2][3];
        }
    }
    __syncthreads();

    const float g = gamma[0];
    const int ce = tid >> 2;             // 0..63
    const int me = (tid & 3) * 32;       // m offset
    const size_t gb = ((size_t)b * C_ + c0 + ce) * N_ + m0 + me;
    const float* srow = sOut + ce * EPI_P + me;
#pragma unroll
    for (int v = 0; v < 8; v++) {
        const float4 xv = *reinterpret_cast<const float4*>(x + gb + v * 4);
        float4 ov;
        ov.x = g * srow[v * 4 + 0] + xv.x;
        ov.y = g * srow[v * 4 + 1] + xv.y;
        ov.z = g * srow[v * 4 + 2] + xv.z;
        ov.w = g * srow[v * 4 + 3] + xv.w;
        *reinterpret_cast<float4*>(out + gb + v * 4) = ov;
    }
}

// ---------------------------------------------------------------------------
extern "C" void kernel_launch(void* const* d_in, const int* in_sizes, int n_in,
                              void* d_out, int out_size) {
    (void)in_sizes; (void)n_in; (void)out_size;
    const float* x     = (const float*)d_in[0];
    const float* Wq    = (const float*)d_in[1];
    const float* bq    = (const float*)d_in[2];
    const float* Wk    = (const float*)d_in[3];
    const float* bk    = (const float*)d_in[4];
    const float* Wv    = (const float*)d_in[5];
    const float* bv    = (const float*)d_in[6];
    const float* gamma = (const float*)d_in[7];

    float* out  = (float*)d_out;
    float* attn = out + (size_t)B_ * C_ * N_;   // tuple order: (out, attention)

    __nv_bfloat16 *qhi, *qlo, *khi, *klo, *xthi, *xtlo, *wvhi, *wvlo, *wqkhi, *wqklo;
    __half *vf16, *af16;
    cudaGetSymbolAddress((void**)&qhi, g_qhi);
    cudaGetSymbolAddress((void**)&qlo, g_qlo);
    cudaGetSymbolAddress((void**)&khi, g_khi);
    cudaGetSymbolAddress((void**)&klo, g_klo);
    cudaGetSymbolAddress((void**)&xthi, g_xthi);
    cudaGetSymbolAddress((void**)&xtlo, g_xtlo);
    cudaGetSymbolAddress((void**)&wvhi, g_wvhi);
    cudaGetSymbolAddress((void**)&wvlo, g_wvlo);
    cudaGetSymbolAddress((void**)&wqkhi, g_wqkhi);
    cudaGetSymbolAddress((void**)&wqklo, g_wqklo);
    cudaGetSymbolAddress((void**)&vf16, g_vf16);
    cudaGetSymbolAddress((void**)&af16, g_af16);

    cudaFuncSetAttribute(out_gemm_kernel,
                         cudaFuncAttributeMaxDynamicSharedMemorySize, DYN_OUT);
    cudaFuncSetAttribute(energy_hmma_kernel,
                         cudaFuncAttributeMaxDynamicSharedMemorySize, DYN_E);
    cudaFuncSetAttribute(proj_v_hmma_kernel,
                         cudaFuncAttributeMaxDynamicSharedMemorySize, DYN_V);
    cudaFuncSetAttribute(proj_qk_hmma_kernel,
                         cudaFuncAttributeMaxDynamicSharedMemorySize, DYN_QK);

    dim3 blk(256);
    convert_x_kernel<<<dim3(N_ / 32, C_ / 32, B_), blk>>>(x, xthi, xtlo);
    convert_w_kernel<<<dim3(C_ * C_ / 256), blk>>>(Wv, wvhi, wvlo);
    convert_wqk_kernel<<<dim3(128 * C_ / 256), blk>>>(Wq, Wk, wqkhi, wqklo);
    proj_qk_hmma_kernel<<<dim3(N_ / 128, 1, B_), blk, DYN_QK>>>(bq, bk, qhi, qlo, khi, klo);
    proj_v_hmma_kernel<<<dim3(C_ / 128, N_ / 128, B_), blk, DYN_V>>>(bv, vf16);
    energy_hmma_kernel<<<dim3(N_ / 128, N_ / 128, B_), blk, DYN_E>>>(attn);
    softmax_kernel<<<dim3(B_ * N_), blk>>>(attn, af16);
    out_gemm_kernel<<<dim3(C_ / 64, N_ / 128, B_), blk, DYN_OUT>>>(x, gamma, out);
}

// round 10
// speedup vs baseline: 5.7995x; 1.0431x over previous
#include <cuda_runtime.h>
#include <cuda_bf16.h>
#include <cuda_fp16.h>
#include <cstdint>

// Self_Attn: B=4, C=512, N=4096 (64x64), D=64
// Outputs (tuple order): out [B,C,64,64] fp32, attention [B,N,N] fp32.

namespace {
constexpr int B_ = 4;
constexpr int C_ = 512;
constexpr int N_ = 4096;
constexpr int D_ = 64;

constexpr int KC_O = 64;             // out-GEMM K elems per chunk (128B fp16 row)
constexpr int NCHUNK_O = N_ / KC_O;  // 64
constexpr int STAGE_P = 32768;       // proj stage: A 16K + B 16K
constexpr int STAGE_O = 24576;       // out stage: A 16K + V 8K
constexpr int EPI_P = 132;           // epilogue smem pitch (floats)
constexpr int DYN_OUT = 2 * STAGE_O; // 49152 (2-stage; epi 33.8K reuses)
constexpr int DYN_E = 128 * EPI_P * 4;  // 67584
constexpr int DYN_V = 128 * EPI_P * 4;  // 67584
constexpr int DYN_QK = 2 * STAGE_P;  // 65536
}

// Scratch (device globals; no runtime allocation allowed).
__device__ __nv_bfloat16 g_qhi[B_ * N_ * D_];           // [B][N][D]
__device__ __nv_bfloat16 g_qlo[B_ * N_ * D_];
__device__ __nv_bfloat16 g_khi[B_ * N_ * D_];
__device__ __nv_bfloat16 g_klo[B_ * N_ * D_];
__device__ __nv_bfloat16 g_xthi[(size_t)B_ * N_ * C_];  // x^T [B][N][C] k-contig
__device__ __nv_bfloat16 g_xtlo[(size_t)B_ * N_ * C_];
__device__ __nv_bfloat16 g_wvhi[C_ * C_];               // Wv [c][k]
__device__ __nv_bfloat16 g_wvlo[C_ * C_];
__device__ __nv_bfloat16 g_wqkhi[128 * C_];             // stacked [Wq;Wk] [d][c]
__device__ __nv_bfloat16 g_wqklo[128 * C_];
__device__ __half g_vf16[(size_t)B_ * C_ * N_];         // v [B][C][N] fp16
__device__ __half g_af16[(size_t)B_ * N_ * N_];         // attn fp16 [B][M][N]

// ---------------------------------------------------------------------------
// helpers
// ---------------------------------------------------------------------------
__device__ __forceinline__ uint32_t smem_u32(const void* p) {
    uint32_t a;
    asm("{ .reg .u64 t; cvta.to.shared.u64 t, %1; cvt.u32.u64 %0, t; }" : "=r"(a) : "l"(p));
    return a;
}

__device__ __forceinline__ void cp16(uint32_t dst, const void* src) {
    asm volatile("cp.async.cg.shared.global [%0], [%1], 16;" :: "r"(dst), "l"(src) : "memory");
}

__device__ __forceinline__ void ldsm4(uint32_t* r, uint32_t addr) {
    asm volatile("ldmatrix.sync.aligned.m8n8.x4.shared.b16 {%0,%1,%2,%3}, [%4];"
                 : "=r"(r[0]), "=r"(r[1]), "=r"(r[2]), "=r"(r[3]) : "r"(addr));
}

__device__ __forceinline__ void mma_bf16(float* d, const uint32_t* a, uint32_t b0, uint32_t b1) {
    asm volatile(
        "mma.sync.aligned.m16n8k16.row.col.f32.bf16.bf16.f32 "
        "{%0,%1,%2,%3}, {%4,%5,%6,%7}, {%8,%9}, {%0,%1,%2,%3};"
        : "+f"(d[0]), "+f"(d[1]), "+f"(d[2]), "+f"(d[3])
        : "r"(a[0]), "r"(a[1]), "r"(a[2]), "r"(a[3]), "r"(b0), "r"(b1));
}

__device__ __forceinline__ void mma_f16(float* d, const uint32_t* a, uint32_t b0, uint32_t b1) {
    asm volatile(
        "mma.sync.aligned.m16n8k16.row.col.f32.f16.f16.f32 "
        "{%0,%1,%2,%3}, {%4,%5,%6,%7}, {%8,%9}, {%0,%1,%2,%3};"
        : "+f"(d[0]), "+f"(d[1]), "+f"(d[2]), "+f"(d[3])
        : "r"(a[0]), "r"(a[1]), "r"(a[2]), "r"(a[3]), "r"(b0), "r"(b1));
}

__device__ __forceinline__ uint32_t swz(uint32_t row, uint32_t colbyte) {
    return row * 128u + (colbyte ^ ((row & 7u) << 4));
}

__device__ __forceinline__ uint32_t pack_bf16(float a, float b) {
    __nv_bfloat162 h = __floats2bfloat162_rn(a, b);
    return *reinterpret_cast<uint32_t*>(&h);
}

// ---------------------------------------------------------------------------
// Transpose + split x: x[b][k][n] fp32 -> xT[b][n][k] bf16 hi/lo.
// ---------------------------------------------------------------------------
__global__ void convert_x_kernel(const float* __restrict__ x,
                                 __nv_bfloat16* __restrict__ xthi,
                                 __nv_bfloat16* __restrict__ xtlo) {
    const int b  = blockIdx.z;
    const int n0 = blockIdx.x * 32;
    const int k0 = blockIdx.y * 32;
    __shared__ float t[32][33];
    const int tid = threadIdx.x;
#pragma unroll
    for (int i = 0; i < 4; i++) {
        int idx = tid + i * 256;
        int k = idx >> 5, n = idx & 31;
        t[k][n] = x[((size_t)b * C_ + k0 + k) * N_ + n0 + n];
    }
    __syncthreads();
#pragma unroll
    for (int i = 0; i < 4; i++) {
        int idx = tid + i * 256;
        int n = idx >> 5, k = idx & 31;
        float val = t[k][n];
        __nv_bfloat16 h = __float2bfloat16(val);
        size_t off = ((size_t)b * N_ + n0 + n) * C_ + k0 + k;
        xthi[off] = h;
        xtlo[off] = __float2bfloat16(val - __bfloat162float(h));
    }
}

// Split Wv fp32 -> bf16 hi/lo.
__global__ void convert_w_kernel(const float* __restrict__ W,
                                 __nv_bfloat16* __restrict__ whi,
                                 __nv_bfloat16* __restrict__ wlo) {
    const int i = blockIdx.x * 256 + threadIdx.x;
    float val = W[i];
    __nv_bfloat16 h = __float2bfloat16(val);
    whi[i] = h;
    wlo[i] = __float2bfloat16(val - __bfloat162float(h));
}

// Stack Wq (rows 0..63) and Wk (rows 64..127) into Wqk bf16 hi/lo.
__global__ void convert_wqk_kernel(const float* __restrict__ Wq,
                                   const float* __restrict__ Wk,
                                   __nv_bfloat16* __restrict__ whi,
                                   __nv_bfloat16* __restrict__ wlo) {
    const int i = blockIdx.x * 256 + threadIdx.x;   // over 128*512
    const int d = i >> 9, c = i & 511;
    float val = d < 64 ? Wq[(size_t)d * C_ + c] : Wk[(size_t)(d - 64) * C_ + c];
    __nv_bfloat16 h = __float2bfloat16(val);
    whi[i] = h;
    wlo[i] = __float2bfloat16(val - __bfloat162float(h));
}

// ---------------------------------------------------------------------------
// proj_qk (HMMA, fused): [q|k][b,n,d] = sum_c Wqk[d,c] x[b,c,n] + bias,
// compensated bf16 (3 terms). CTA 128n x 128d, 2-stage ring.
// ---------------------------------------------------------------------------
__global__ void __launch_bounds__(256, 2)
proj_qk_hmma_kernel(const float* __restrict__ bq, const float* __restrict__ bk,
                    __nv_bfloat16* __restrict__ qhi, __nv_bfloat16* __restrict__ qlo,
                    __nv_bfloat16* __restrict__ khi, __nv_bfloat16* __restrict__ klo) {
    extern __shared__ char dynsmem[];
    const uint32_t sbase = smem_u32(dynsmem);

    const int tid  = threadIdx.x;
    const int wid  = tid >> 5;
    const int lane = tid & 31;

    const int b  = blockIdx.z;
    const int n0 = blockIdx.x * 128;

    const __nv_bfloat16* Xhi = g_xthi + (size_t)b * N_ * C_;
    const __nv_bfloat16* Xlo = g_xtlo + (size_t)b * N_ * C_;

    const int wm = (wid >> 2) * 64;   // n
    const int wc = (wid & 3) * 32;    // d

    const uint32_t lrow = lane & 15;
    const uint32_t lswz = (lane & 7) << 4;
    const uint32_t lcol = (lane >> 4) << 4;

    float acc[4][4][4] = {};

    auto load_chunk = [&](int kc) {
        const uint32_t st = (uint32_t)(kc & 1) * STAGE_P;
        const size_t koff = (size_t)kc * 32;
#pragma unroll
        for (int t = 0; t < 8; t++) {
            const int idx = tid + t * 256;
            const int part = idx >> 10;          // 0=A(xT), 1=B(Wqk)
            const int a = idx & 1023;
            const int row = a >> 3, seg = a & 7;
            const __nv_bfloat16* src;
            if (part == 0)
                src = (seg < 4 ? Xhi : Xlo) + (size_t)(n0 + row) * C_ + koff + (seg & 3) * 8;
            else
                src = (seg < 4 ? g_wqkhi : g_wqklo) + (size_t)row * C_ + koff + (seg & 3) * 8;
            cp16(sbase + st + (uint32_t)part * 16384u + swz(row, seg * 16), src);
        }
        asm volatile("cp.async.commit_group;" ::: "memory");
    };

    load_chunk(0);

    for (int kc = 0; kc < C_ / 32; kc++) {
        asm volatile("cp.async.wait_group 0;" ::: "memory");
        __syncthreads();
        if (kc + 1 < C_ / 32) load_chunk(kc + 1);

        const uint32_t st = (uint32_t)(kc & 1) * STAGE_P;
        const uint32_t Ab = sbase + st, Bb = Ab + 16384;

#pragma unroll
        for (int ks = 0; ks < 2; ks++) {
            const uint32_t kbHi = (uint32_t)(ks * 32);
            const uint32_t kbLo = 64u + kbHi;

            uint32_t ah[4][4], al[4][4], bh[2][4], bl[2][4];
#pragma unroll
            for (int i = 0; i < 4; i++) {
                const uint32_t row = (uint32_t)(wm + i * 16) + lrow;
                ldsm4(ah[i], Ab + row * 128u + ((kbHi + lcol) ^ lswz));
                ldsm4(al[i], Ab + row * 128u + ((kbLo + lcol) ^ lswz));
            }
#pragma unroll
            for (int j = 0; j < 2; j++) {
                const uint32_t row = (uint32_t)(wc + j * 16) + lrow;
                ldsm4(bh[j], Bb + row * 128u + ((kbHi + lcol) ^ lswz));
                ldsm4(bl[j], Bb + row * 128u + ((kbLo + lcol) ^ lswz));
            }
#pragma unroll
            for (int i = 0; i < 4; i++)
#pragma unroll
                for (int j = 0; j < 4; j++) {
                    const int t2 = j >> 1, p2 = j & 1;
                    mma_bf16(acc[i][j], ah[i], bh[t2][p2], bh[t2][2 + p2]);
                    mma_bf16(acc[i][j], al[i], bh[t2][p2], bh[t2][2 + p2]);
                    mma_bf16(acc[i][j], ah[i], bl[t2][p2], bl[t2][2 + p2]);
                }
        }
        __syncthreads();
    }

    // Epilogue: bias add, split hi/lo, packed bf16x2 stores from registers.
#pragma unroll
    for (int j = 0; j < 4; j++) {
        const int d = wc + j * 8 + (lane & 3) * 2;   // even; pair never straddles 64
        const bool isq = d < 64;
        const int dd = isq ? d : d - 64;
        const float b0v = isq ? bq[dd] : bk[dd];
        const float b1v = isq ? bq[dd + 1] : bk[dd + 1];
        __nv_bfloat16* dhi = isq ? qhi : khi;
        __nv_bfloat16* dlo = isq ? qlo : klo;
#pragma unroll
        for (int i = 0; i < 4; i++) {
            const int n = n0 + wm + i * 16 + (lane >> 2);
#pragma unroll
            for (int r = 0; r < 2; r++) {          // row n, n+8
                const float v0 = acc[i][j][r * 2] + b0v;
                const float v1 = acc[i][j][r * 2 + 1] + b1v;
                const float h0 = __bfloat162float(__float2bfloat16(v0));
                const float h1 = __bfloat162float(__float2bfloat16(v1));
                const size_t off = ((size_t)b * N_ + n + r * 8) * D_ + dd;
                *reinterpret_cast<uint32_t*>(dhi + off) = pack_bf16(v0, v1);
                *reinterpret_cast<uint32_t*>(dlo + off) = pack_bf16(v0 - h0, v1 - h1);
            }
        }
    }
}

// ---------------------------------------------------------------------------
// proj_v (HMMA): v[b,c,n] = sum_k Wv[c,k] x[b,k,n] + bv[c], compensated bf16.
// ---------------------------------------------------------------------------
__global__ void __launch_bounds__(256, 2)
proj_v_hmma_kernel(const float* __restrict__ bias, __half* __restrict__ vf16) {
    extern __shared__ char dynsmem[];
    const uint32_t sbase = smem_u32(dynsmem);

    const int tid  = threadIdx.x;
    const int wid  = tid >> 5;
    const int lane = tid & 31;

    const int b  = blockIdx.z;
    const int c0 = blockIdx.x * 128;
    const int n0 = blockIdx.y * 128;

    const __nv_bfloat16* Whi = g_wvhi;
    const __nv_bfloat16* Wlo = g_wvlo;
    const __nv_bfloat16* Xhi = g_xthi + (size_t)b * N_ * C_;
    const __nv_bfloat16* Xlo = g_xtlo + (size_t)b * N_ * C_;

    const int wm = (wid >> 2) * 64;   // c
    const int wn = (wid & 3) * 32;    // n

    const uint32_t lrow = lane & 15;
    const uint32_t lswz = (lane & 7) << 4;
    const uint32_t lcol = (lane >> 4) << 4;

    float acc[4][4][4] = {};

    auto load_chunk = [&](int kc) {
        const uint32_t st = (uint32_t)(kc & 1) * STAGE_P;
        const size_t koff = (size_t)kc * 32;
#pragma unroll
        for (int t = 0; t < 8; t++) {
            const int idx = tid + t * 256;
            const int part = idx >> 10;          // 0=A(Wv), 1=B(xT)
            const int a = idx & 1023;
            const int row = a >> 3, seg = a & 7;
            const __nv_bfloat16* src;
            if (part == 0)
                src = (seg < 4 ? Whi : Wlo) + (size_t)(c0 + row) * C_ + koff + (seg & 3) * 8;
            else
                src = (seg < 4 ? Xhi : Xlo) + (size_t)(n0 + row) * C_ + koff + (seg & 3) * 8;
            cp16(sbase + st + (uint32_t)part * 16384u + swz(row, seg * 16), src);
        }
        asm volatile("cp.async.commit_group;" ::: "memory");
    };

    load_chunk(0);

    for (int kc = 0; kc < C_ / 32; kc++) {
        asm volatile("cp.async.wait_group 0;" ::: "memory");
        __syncthreads();
        if (kc + 1 < C_ / 32) load_chunk(kc + 1);

        const uint32_t st = (uint32_t)(kc & 1) * STAGE_P;
        const uint32_t Ab = sbase + st, Bb = Ab + 16384;

#pragma unroll
        for (int ks = 0; ks < 2; ks++) {
            const uint32_t kbHi = (uint32_t)(ks * 32);
            const uint32_t kbLo = 64u + kbHi;

            uint32_t ah[4][4], al[4][4], bh[2][4], bl[2][4];
#pragma unroll
            for (int i = 0; i < 4; i++) {
                const uint32_t row = (uint32_t)(wm + i * 16) + lrow;
                ldsm4(ah[i], Ab + row * 128u + ((kbHi + lcol) ^ lswz));
                ldsm4(al[i], Ab + row * 128u + ((kbLo + lcol) ^ lswz));
            }
#pragma unroll
            for (int j = 0; j < 2; j++) {
                const uint32_t row = (uint32_t)(wn + j * 16) + lrow;
                ldsm4(bh[j], Bb + row * 128u + ((kbHi + lcol) ^ lswz));
                ldsm4(bl[j], Bb + row * 128u + ((kbLo + lcol) ^ lswz));
            }
#pragma unroll
            for (int i = 0; i < 4; i++)
#pragma unroll
                for (int j = 0; j < 4; j++) {
                    const int t2 = j >> 1, p2 = j & 1;
                    mma_bf16(acc[i][j], ah[i], bh[t2][p2], bh[t2][2 + p2]);
                    mma_bf16(acc[i][j], al[i], bh[t2][p2], bh[t2][2 + p2]);
                    mma_bf16(acc[i][j], ah[i], bl[t2][p2], bl[t2][2 + p2]);
                }
        }
        __syncthreads();
    }

    // Epilogue: c-major rows in smem (n contiguous), add bias, emit fp16.
    float* sOut = reinterpret_cast<float*>(dynsmem);
#pragma unroll
    for (int i = 0; i < 4; i++) {
        const int ct = wm + i * 16 + (lane >> 2);
#pragma unroll
        for (int j = 0; j < 4; j++) {
            const int nt = wn + j * 8 + (lane & 3) * 2;
            sOut[ct * EPI_P + nt]           = acc[i][j][0];
            sOut[ct * EPI_P + nt + 1]       = acc[i][j][1];
            sOut[(ct + 8) * EPI_P + nt]     = acc[i][j][2];
            sOut[(ct + 8) * EPI_P + nt + 1] = acc[i][j][3];
        }
    }
    __syncthreads();

    const int row = tid >> 1;             // c within tile
    const int col0 = (tid & 1) * 64;      // n offset
    const float bv = bias[c0 + row];
    const float* srow = sOut + row * EPI_P + col0;
    __half* dst = vf16 + ((size_t)b * C_ + c0 + row) * N_ + n0 + col0;
#pragma unroll
    for (int v = 0; v < 16; v++) {
        float4 f = *reinterpret_cast<const float4*>(srow + v * 4);
        __half2 h01 = __floats2half2_rn(f.x + bv, f.y + bv);
        __half2 h23 = __floats2half2_rn(f.z + bv, f.w + bv);
        uint2 u;
        u.x = *reinterpret_cast<uint32_t*>(&h01);
        u.y = *reinterpret_cast<uint32_t*>(&h23);
        *reinterpret_cast<uint2*>(dst + v * 4) = u;
    }
}

// ---------------------------------------------------------------------------
// Energy (HMMA): E[b,m,n] = sum_d q[b,m,d] k[b,n,d], compensated bf16 split.
// ---------------------------------------------------------------------------
__global__ void __launch_bounds__(256)
energy_hmma_kernel(float* __restrict__ attn) {
    extern __shared__ char dynsmem[];
    const uint32_t sbase = smem_u32(dynsmem);

    const int tid  = threadIdx.x;
    const int wid  = tid >> 5;
    const int lane = tid & 31;

    const int b  = blockIdx.z;
    const int n0 = blockIdx.x * 128;
    const int m0 = blockIdx.y * 128;

    const __nv_bfloat16* Qhi = g_qhi + (size_t)b * N_ * D_;
    const __nv_bfloat16* Qlo = g_qlo + (size_t)b * N_ * D_;
    const __nv_bfloat16* Khi = g_khi + (size_t)b * N_ * D_;
    const __nv_bfloat16* Klo = g_klo + (size_t)b * N_ * D_;

    const int wm = (wid >> 2) * 64;
    const int wn = (wid & 3) * 32;

    const uint32_t lrow = lane & 15;
    const uint32_t lswz = (lane & 7) << 4;
    const uint32_t lcol = (lane >> 4) << 4;

#pragma unroll
    for (int t = 0; t < 4; t++) {
        const int idx = tid + t * 256;
        const int row = idx >> 3, seg = idx & 7;
        cp16(sbase + swz(row, seg * 16), Qhi + (size_t)(m0 + row) * D_ + seg * 8);
        cp16(sbase + 16384 + swz(row, seg * 16), Khi + (size_t)(n0 + row) * D_ + seg * 8);
    }
    asm volatile("cp.async.commit_group;" ::: "memory");
#pragma unroll
    for (int t = 0; t < 4; t++) {
        const int idx = tid + t * 256;
        const int row = idx >> 3, seg = idx & 7;
        cp16(sbase + 32768 + swz(row, seg * 16), Qlo + (size_t)(m0 + row) * D_ + seg * 8);
        cp16(sbase + 49152 + swz(row, seg * 16), Klo + (size_t)(n0 + row) * D_ + seg * 8);
    }
    asm volatile("cp.async.commit_group;" ::: "memory");

    float acc[4][4][4] = {};

    asm volatile("cp.async.wait_group 1;" ::: "memory");
    __syncthreads();
#pragma unroll
    for (int ks = 0; ks < 4; ks++) {
        const uint32_t kb = (uint32_t)(ks * 32);
        uint32_t a[4][4], bm[2][4];
#pragma unroll
        for (int i = 0; i < 4; i++) {
            const uint32_t row = (uint32_t)(wm + i * 16) + lrow;
            ldsm4(a[i], sbase + row * 128u + ((kb + lcol) ^ lswz));
        }
#pragma unroll
        for (int j = 0; j < 2; j++) {
            const uint32_t row = (uint32_t)(wn + j * 16) + lrow;
            ldsm4(bm[j], sbase + 16384 + row * 128u + ((kb + lcol) ^ lswz));
        }
#pragma unroll
        for (int i = 0; i < 4; i++)
#pragma unroll
            for (int j = 0; j < 4; j++) {
                const int t2 = j >> 1, p2 = j & 1;
                mma_bf16(acc[i][j], a[i], bm[t2][p2], bm[t2][2 + p2]);
            }
    }

    asm volatile("cp.async.wait_group 0;" ::: "memory");
    __syncthreads();
#pragma unroll
    for (int ks = 0; ks < 4; ks++) {
        const uint32_t kb = (uint32_t)(ks * 32);
        uint32_t ah[4][4], al[4][4], bh[2][4], bl[2][4];
#pragma unroll
        for (int i = 0; i < 4; i++) {
            const uint32_t row = (uint32_t)(wm + i * 16) + lrow;
            ldsm4(ah[i], sbase + row * 128u + ((kb + lcol) ^ lswz));
            ldsm4(al[i], sbase + 32768 + row * 128u + ((kb + lcol) ^ lswz));
        }
#pragma unroll
        for (int j = 0; j < 2; j++) {
            const uint32_t row = (uint32_t)(wn + j * 16) + lrow;
            ldsm4(bh[j], sbase + 16384 + row * 128u + ((kb + lcol) ^ lswz));
            ldsm4(bl[j], sbase + 49152 + row * 128u + ((kb + lcol) ^ lswz));
        }
#pragma unroll
        for (int i = 0; i < 4; i++)
#pragma unroll
            for (int j = 0; j < 4; j++) {
                const int t2 = j >> 1, p2 = j & 1;
                mma_bf16(acc[i][j], al[i], bh[t2][p2], bh[t2][2 + p2]);
                mma_bf16(acc[i][j], ah[i], bl[t2][p2], bl[t2][2 + p2]);
            }
    }

    __syncthreads();
    float* sOut = reinterpret_cast<float*>(dynsmem);
#pragma unroll
    for (int i = 0; i < 4; i++) {
        const int mt = wm + i * 16 + (lane >> 2);
#pragma unroll
        for (int j = 0; j < 4; j++) {
            const int nt = wn + j * 8 + (lane & 3) * 2;
            sOut[mt * EPI_P + nt]           = acc[i][j][0];
            sOut[mt * EPI_P + nt + 1]       = acc[i][j][1];
            sOut[(mt + 8) * EPI_P + nt]     = acc[i][j][2];
            sOut[(mt + 8) * EPI_P + nt + 1] = acc[i][j][3];
        }
    }
    __syncthreads();

    float* eb = attn + (size_t)b * N_ * N_;
    const int row = tid >> 1;
    const int col0 = (tid & 1) * 64;
    const float* srow = sOut + row * EPI_P + col0;
    float* grow = eb + (size_t)(m0 + row) * N_ + n0 + col0;
#pragma unroll
    for (int v = 0; v < 16; v++)
        *reinterpret_cast<float4*>(grow + v * 4) =
            *reinterpret_cast<const float4*>(srow + v * 4);
}

// ---------------------------------------------------------------------------
// Row softmax in place (vectorized); emit attn as single fp16.
// ---------------------------------------------------------------------------
__global__ void softmax_kernel(float* __restrict__ attn,
                               __half* __restrict__ af16) {
    const size_t row = blockIdx.x;
    float* p = attn + row * N_;
    const int tid = threadIdx.x;

    float4 v[4];
    float mx = -3.0e38f;
#pragma unroll
    for (int i = 0; i < 4; i++) {
        v[i] = *reinterpret_cast<const float4*>(p + tid * 4 + i * 1024);
        mx = fmaxf(mx, fmaxf(fmaxf(v[i].x, v[i].y), fmaxf(v[i].z, v[i].w)));
    }
    __shared__ float red[8];
#pragma unroll
    for (int o = 16; o; o >>= 1) mx = fmaxf(mx, __shfl_xor_sync(0xffffffffu, mx, o));
    if ((tid & 31) == 0) red[tid >> 5] = mx;
    __syncthreads();
    mx = red[0];
#pragma unroll
    for (int i = 1; i < 8; i++) mx = fmaxf(mx, red[i]);
    __syncthreads();

    float s = 0.f;
#pragma unroll
    for (int i = 0; i < 4; i++) {
        v[i].x = __expf(v[i].x - mx); v[i].y = __expf(v[i].y - mx);
        v[i].z = __expf(v[i].z - mx); v[i].w = __expf(v[i].w - mx);
        s += (v[i].x + v[i].y) + (v[i].z + v[i].w);
    }
#pragma unroll
    for (int o = 16; o; o >>= 1) s += __shfl_xor_sync(0xffffffffu, s, o);
    if ((tid & 31) == 0) red[tid >> 5] = s;
    __syncthreads();
    s = 0.f;
#pragma unroll
    for (int i = 0; i < 8; i++) s += red[i];
    const float inv = 1.0f / s;

    __half* ph = af16 + row * N_;
#pragma unroll
    for (int i = 0; i < 4; i++) {
        float4 r;
        r.x = v[i].x * inv; r.y = v[i].y * inv; r.z = v[i].z * inv; r.w = v[i].w * inv;
        *reinterpret_cast<float4*>(p + tid * 4 + i * 1024) = r;

        __half2 h01 = __floats2half2_rn(r.x, r.y);
        __half2 h23 = __floats2half2_rn(r.z, r.w);
        uint2 hh;
        hh.x = *reinterpret_cast<uint32_t*>(&h01);
        hh.y = *reinterpret_cast<uint32_t*>(&h23);
        *reinterpret_cast<uint2*>(ph + tid * 4 + i * 1024) = hh;
    }
}

// ---------------------------------------------------------------------------
// out[b,c,m] = gamma * sum_n attn[b,m,n] * v[b,c,n] + x[b,c,m]
// HMMA fp16, single-term. CTA 128m x 64c, 2-stage ring, 3 CTAs/SM.
// ---------------------------------------------------------------------------
__global__ void __launch_bounds__(256, 3)
out_gemm_kernel(const float* __restrict__ x,
                const float* __restrict__ gamma,
                float* __restrict__ out) {
    extern __shared__ char dynsmem[];
    const uint32_t sbase = smem_u32(dynsmem);

    const int tid  = threadIdx.x;
    const int wid  = tid >> 5;
    const int lane = tid & 31;

    const int b  = blockIdx.z;
    const int c0 = blockIdx.x * 64;    // c fastest: 8 siblings share A tile in L2
    const int m0 = blockIdx.y * 128;

    const __half* A = g_af16 + (size_t)b * N_ * N_;
    const __half* V = g_vf16 + (size_t)b * C_ * N_;

    const int wm = (wid >> 2) * 64;    // m offset of warp
    const int wc = (wid & 3) * 16;     // c offset of warp

    const uint32_t lrow = lane & 15;
    const uint32_t lswz = (lane & 7) << 4;
    const uint32_t lcol = (lane >> 4) << 4;

    float acc[4][2][4] = {};   // [m16][c8][reg]

    auto load_chunk = [&](int kc) {
        const uint32_t st = (uint32_t)(kc & 1) * STAGE_O;
        const size_t koff = (size_t)kc * KC_O;
#pragma unroll
        for (int t = 0; t < 6; t++) {
            const int idx = tid + t * 256;
            if (idx < 1024) {
                const int row = idx >> 3, seg = idx & 7;
                cp16(sbase + st + swz(row, seg * 16),
                     A + (size_t)(m0 + row) * N_ + koff + seg * 8);
            } else {
                const int i2 = idx - 1024;
                const int row = i2 >> 3, seg = i2 & 7;
                cp16(sbase + st + 16384u + swz(row, seg * 16),
                     V + (size_t)(c0 + row) * N_ + koff + seg * 8);
            }
        }
        asm volatile("cp.async.commit_group;" ::: "memory");
    };

    load_chunk(0);

    for (int kc = 0; kc < NCHUNK_O; kc++) {
        asm volatile("cp.async.wait_group 0;" ::: "memory");
        __syncthreads();
        if (kc + 1 < NCHUNK_O) load_chunk(kc + 1);

        const uint32_t st = (uint32_t)(kc & 1) * STAGE_O;
        const uint32_t Ab = sbase + st, Vb = Ab + 16384;

#pragma unroll
        for (int ks = 0; ks < 4; ks++) {
            const uint32_t kb = (uint32_t)(ks * 32);
            uint32_t a[4][4], bm[4];
#pragma unroll
            for (int i = 0; i < 4; i++) {
                const uint32_t row = (uint32_t)(wm + i * 16) + lrow;
                ldsm4(a[i], Ab + row * 128u + ((kb + lcol) ^ lswz));
            }
            {
                const uint32_t row = (uint32_t)wc + lrow;
                ldsm4(bm, Vb + row * 128u + ((kb + lcol) ^ lswz));
            }
#pragma unroll
            for (int i = 0; i < 4; i++)
#pragma unroll
                for (int p2 = 0; p2 < 2; p2++)
                    mma_f16(acc[i][p2], a[i], bm[p2], bm[2 + p2]);
        }
    }
    __syncthreads();

    // ---- epilogue: full 64c x 128m transpose via smem ----
    float* sOut = reinterpret_cast<float*>(dynsmem);
#pragma unroll
    for (int i = 0; i < 4; i++) {
        const int mt = wm + i * 16 + (lane >> 2);
#pragma unroll
        for (int p2 = 0; p2 < 2; p2++) {
            const int ct = wc + p2 * 8 + (lane & 3) * 2;
            sOut[ct * EPI_P + mt]           = acc[i][p2][0];
            sOut[(ct + 1) * EPI_P + mt]     = acc[i][p2][1];
            sOut[ct * EPI_P + mt + 8]       = acc[i][p2][2];
            sOut[(ct + 1) * EPI_P + mt + 8] = acc[i][p2][3];
        }
    }
    __syncthreads();

    const float g = gamma[0];
    const int ce = tid >> 2;             // 0..63
    const int me = (tid & 3) * 32;       // m offset
    const size_t gb = ((size_t)b * C_ + c0 + ce) * N_ + m0 + me;
    const float* srow = sOut + ce * EPI_P + me;
#pragma unroll
    for (int v = 0; v < 8; v++) {
        const float4 xv = *reinterpret_cast<const float4*>(x + gb + v * 4);
        float4 ov;
        ov.x = g * srow[v * 4 + 0] + xv.x;
        ov.y = g * srow[v * 4 + 1] + xv.y;
        ov.z = g * srow[v * 4 + 2] + xv.z;
        ov.w = g * srow[v * 4 + 3] + xv.w;
        *reinterpret_cast<float4*>(out + gb + v * 4) = ov;
    }
}

// ---------------------------------------------------------------------------
extern "C" void kernel_launch(void* const* d_in, const int* in_sizes, int n_in,
                              void* d_out, int out_size) {
    (void)in_sizes; (void)n_in; (void)out_size;
    const float* x     = (const float*)d_in[0];
    const float* Wq    = (const float*)d_in[1];
    const float* bq    = (const float*)d_in[2];
    const float* Wk    = (const float*)d_in[3];
    const float* bk    = (const float*)d_in[4];
    const float* Wv    = (const float*)d_in[5];
    const float* bv    = (const float*)d_in[6];
    const float* gamma = (const float*)d_in[7];

    float* out  = (float*)d_out;
    float* attn = out + (size_t)B_ * C_ * N_;   // tuple order: (out, attention)

    __nv_bfloat16 *qhi, *qlo, *khi, *klo, *xthi, *xtlo, *wvhi, *wvlo, *wqkhi, *wqklo;
    __half *vf16, *af16;
    cudaGetSymbolAddress((void**)&qhi, g_qhi);
    cudaGetSymbolAddress((void**)&qlo, g_qlo);
    cudaGetSymbolAddress((void**)&khi, g_khi);
    cudaGetSymbolAddress((void**)&klo, g_klo);
    cudaGetSymbolAddress((void**)&xthi, g_xthi);
    cudaGetSymbolAddress((void**)&xtlo, g_xtlo);
    cudaGetSymbolAddress((void**)&wvhi, g_wvhi);
    cudaGetSymbolAddress((void**)&wvlo, g_wvlo);
    cudaGetSymbolAddress((void**)&wqkhi, g_wqkhi);
    cudaGetSymbolAddress((void**)&wqklo, g_wqklo);
    cudaGetSymbolAddress((void**)&vf16, g_vf16);
    cudaGetSymbolAddress((void**)&af16, g_af16);

    cudaFuncSetAttribute(out_gemm_kernel,
                         cudaFuncAttributeMaxDynamicSharedMemorySize, DYN_OUT);
    cudaFuncSetAttribute(energy_hmma_kernel,
                         cudaFuncAttributeMaxDynamicSharedMemorySize, DYN_E);
    cudaFuncSetAttribute(proj_v_hmma_kernel,
                         cudaFuncAttributeMaxDynamicSharedMemorySize, DYN_V);
    cudaFuncSetAttribute(proj_qk_hmma_kernel,
                         cudaFuncAttributeMaxDynamicSharedMemorySize, DYN_QK);

    // Fork-join onto a side stream so proj_v/converts overlap the main chain.
    // kernel_launch runs only twice (correctness + capture); the created
    // stream/events are intentionally not destroyed (no device memory).
    cudaStream_t s1;
    cudaStreamCreateWithFlags(&s1, cudaStreamNonBlocking);
    cudaEvent_t eFork, eX, eWqk, eV;
    cudaEventCreateWithFlags(&eFork, cudaEventDisableTiming);
    cudaEventCreateWithFlags(&eX,    cudaEventDisableTiming);
    cudaEventCreateWithFlags(&eWqk,  cudaEventDisableTiming);
    cudaEventCreateWithFlags(&eV,    cudaEventDisableTiming);

    dim3 blk(256);

    // fork: s1 branches off the (captured) legacy stream
    cudaEventRecord(eFork, 0);
    cudaStreamWaitEvent(s1, eFork, 0);

    // s1: weight converts (independent of x)
    convert_w_kernel<<<dim3(C_ * C_ / 256), blk, 0, s1>>>(Wv, wvhi, wvlo);
    convert_wqk_kernel<<<dim3(128 * C_ / 256), blk, 0, s1>>>(Wq, Wk, wqkhi, wqklo);
    cudaEventRecord(eWqk, s1);

    // s0: x transpose/split
    convert_x_kernel<<<dim3(N_ / 32, C_ / 32, B_), blk>>>(x, xthi, xtlo);
    cudaEventRecord(eX, 0);

    // s1: proj_v (needs convert_x + convert_w) — overlaps proj_qk + energy
    cudaStreamWaitEvent(s1, eX, 0);
    proj_v_hmma_kernel<<<dim3(C_ / 128, N_ / 128, B_), blk, DYN_V, s1>>>(bv, vf16);
    cudaEventRecord(eV, s1);

    // s0: proj_qk (needs convert_x + convert_wqk) -> energy -> softmax
    cudaStreamWaitEvent(0, eWqk, 0);
    proj_qk_hmma_kernel<<<dim3(N_ / 128, 1, B_), blk, DYN_QK>>>(bq, bk, qhi, qlo, khi, klo);
    energy_hmma_kernel<<<dim3(N_ / 128, N_ / 128, B_), blk, DYN_E>>>(attn);
    softmax_kernel<<<dim3(B_ * N_), blk>>>(attn, af16);

    // join: out_gemm needs softmax (s0) + proj_v (s1)
    cudaStreamWaitEvent(0, eV, 0);
    out_gemm_kernel<<<dim3(C_ / 64, N_ / 128, B_), blk, DYN_OUT>>>(x, gamma, out);
}

// round 12
// speedup vs baseline: 5.8064x; 1.0012x over previous
#include <cuda_runtime.h>
#include <cuda_bf16.h>
#include <cuda_fp16.h>
#include <cstdint>

// Self_Attn: B=4, C=512, N=4096 (64x64), D=64
// Outputs (tuple order): out [B,C,64,64] fp32, attention [B,N,N] fp32.

namespace {
constexpr int B_ = 4;
constexpr int C_ = 512;
constexpr int N_ = 4096;
constexpr int D_ = 64;

constexpr int KC_O = 64;             // out-GEMM K elems per chunk (128B fp16 row)
constexpr int NCHUNK_O = N_ / KC_O;  // 64
constexpr int STAGE_P = 32768;       // proj stage: A 16K + B 16K
constexpr int STAGE_O = 24576;       // out stage: A 16K + V 8K
constexpr int EPI_P = 132;           // epilogue smem pitch (floats)
constexpr int DYN_OUT = 2 * STAGE_O; // 49152 (2-stage; epi 33.8K reuses)
constexpr int DYN_E = 128 * EPI_P * 4;  // 67584
constexpr int DYN_V = 128 * EPI_P * 4;  // 67584
constexpr int DYN_QK = 2 * STAGE_P;  // 65536
}

// Scratch (device globals; no runtime allocation allowed).
__device__ __nv_bfloat16 g_qhi[B_ * N_ * D_];           // [B][N][D]
__device__ __nv_bfloat16 g_qlo[B_ * N_ * D_];
__device__ __nv_bfloat16 g_khi[B_ * N_ * D_];
__device__ __nv_bfloat16 g_klo[B_ * N_ * D_];
__device__ __nv_bfloat16 g_xthi[(size_t)B_ * N_ * C_];  // x^T [B][N][C] k-contig
__device__ __nv_bfloat16 g_xtlo[(size_t)B_ * N_ * C_];
__device__ __nv_bfloat16 g_wvhi[C_ * C_];               // Wv [c][k]
__device__ __nv_bfloat16 g_wvlo[C_ * C_];
__device__ __nv_bfloat16 g_wqkhi[128 * C_];             // stacked [Wq;Wk] [d][c]
__device__ __nv_bfloat16 g_wqklo[128 * C_];
__device__ __half g_vf16[(size_t)B_ * C_ * N_];         // v [B][C][N] fp16
__device__ __half g_af16[(size_t)B_ * N_ * N_];         // attn fp16 [B][M][N]

// ---------------------------------------------------------------------------
// helpers
// ---------------------------------------------------------------------------
__device__ __forceinline__ uint32_t smem_u32(const void* p) {
    uint32_t a;
    asm("{ .reg .u64 t; cvta.to.shared.u64 t, %1; cvt.u32.u64 %0, t; }" : "=r"(a) : "l"(p));
    return a;
}

__device__ __forceinline__ void cp16(uint32_t dst, const void* src) {
    asm volatile("cp.async.cg.shared.global [%0], [%1], 16;" :: "r"(dst), "l"(src) : "memory");
}

__device__ __forceinline__ void ldsm4(uint32_t* r, uint32_t addr) {
    asm volatile("ldmatrix.sync.aligned.m8n8.x4.shared.b16 {%0,%1,%2,%3}, [%4];"
                 : "=r"(r[0]), "=r"(r[1]), "=r"(r[2]), "=r"(r[3]) : "r"(addr));
}

__device__ __forceinline__ void mma_bf16(float* d, const uint32_t* a, uint32_t b0, uint32_t b1) {
    asm volatile(
        "mma.sync.aligned.m16n8k16.row.col.f32.bf16.bf16.f32 "
        "{%0,%1,%2,%3}, {%4,%5,%6,%7}, {%8,%9}, {%0,%1,%2,%3};"
        : "+f"(d[0]), "+f"(d[1]), "+f"(d[2]), "+f"(d[3])
        : "r"(a[0]), "r"(a[1]), "r"(a[2]), "r"(a[3]), "r"(b0), "r"(b1));
}

__device__ __forceinline__ void mma_f16(float* d, const uint32_t* a, uint32_t b0, uint32_t b1) {
    asm volatile(
        "mma.sync.aligned.m16n8k16.row.col.f32.f16.f16.f32 "
        "{%0,%1,%2,%3}, {%4,%5,%6,%7}, {%8,%9}, {%0,%1,%2,%3};"
        : "+f"(d[0]), "+f"(d[1]), "+f"(d[2]), "+f"(d[3])
        : "r"(a[0]), "r"(a[1]), "r"(a[2]), "r"(a[3]), "r"(b0), "r"(b1));
}

__device__ __forceinline__ uint32_t swz(uint32_t row, uint32_t colbyte) {
    return row * 128u + (colbyte ^ ((row & 7u) << 4));
}

__device__ __forceinline__ uint32_t pack_bf16(float a, float b) {
    __nv_bfloat162 h = __floats2bfloat162_rn(a, b);
    return *reinterpret_cast<uint32_t*>(&h);
}

// ---------------------------------------------------------------------------
// Transpose + split x: x[b][k][n] fp32 -> xT[b][n][k] bf16 hi/lo.
// ---------------------------------------------------------------------------
__global__ void convert_x_kernel(const float* __restrict__ x,
                                 __nv_bfloat16* __restrict__ xthi,
                                 __nv_bfloat16* __restrict__ xtlo) {
    const int b  = blockIdx.z;
    const int n0 = blockIdx.x * 32;
    const int k0 = blockIdx.y * 32;
    __shared__ float t[32][33];
    const int tid = threadIdx.x;
#pragma unroll
    for (int i = 0; i < 4; i++) {
        int idx = tid + i * 256;
        int k = idx >> 5, n = idx & 31;
        t[k][n] = x[((size_t)b * C_ + k0 + k) * N_ + n0 + n];
    }
    __syncthreads();
#pragma unroll
    for (int i = 0; i < 4; i++) {
        int idx = tid + i * 256;
        int n = idx >> 5, k = idx & 31;
        float val = t[k][n];
        __nv_bfloat16 h = __float2bfloat16(val);
        size_t off = ((size_t)b * N_ + n0 + n) * C_ + k0 + k;
        xthi[off] = h;
        xtlo[off] = __float2bfloat16(val - __bfloat162float(h));
    }
}

// Split Wv fp32 -> bf16 hi/lo.
__global__ void convert_w_kernel(const float* __restrict__ W,
                                 __nv_bfloat16* __restrict__ whi,
                                 __nv_bfloat16* __restrict__ wlo) {
    const int i = blockIdx.x * 256 + threadIdx.x;
    float val = W[i];
    __nv_bfloat16 h = __float2bfloat16(val);
    whi[i] = h;
    wlo[i] = __float2bfloat16(val - __bfloat162float(h));
}

// Stack Wq (rows 0..63) and Wk (rows 64..127) into Wqk bf16 hi/lo.
__global__ void convert_wqk_kernel(const float* __restrict__ Wq,
                                   const float* __restrict__ Wk,
                                   __nv_bfloat16* __restrict__ whi,
                                   __nv_bfloat16* __restrict__ wlo) {
    const int i = blockIdx.x * 256 + threadIdx.x;   // over 128*512
    const int d = i >> 9, c = i & 511;
    float val = d < 64 ? Wq[(size_t)d * C_ + c] : Wk[(size_t)(d - 64) * C_ + c];
    __nv_bfloat16 h = __float2bfloat16(val);
    whi[i] = h;
    wlo[i] = __float2bfloat16(val - __bfloat162float(h));
}

// ---------------------------------------------------------------------------
// proj_qk (HMMA, fused): CTA 128n x 128d, 2-stage ring, compensated bf16.
// ---------------------------------------------------------------------------
__global__ void __launch_bounds__(256, 2)
proj_qk_hmma_kernel(const float* __restrict__ bq, const float* __restrict__ bk,
                    __nv_bfloat16* __restrict__ qhi, __nv_bfloat16* __restrict__ qlo,
                    __nv_bfloat16* __restrict__ khi, __nv_bfloat16* __restrict__ klo) {
    extern __shared__ char dynsmem[];
    const uint32_t sbase = smem_u32(dynsmem);

    const int tid  = threadIdx.x;
    const int wid  = tid >> 5;
    const int lane = tid & 31;

    const int b  = blockIdx.z;
    const int n0 = blockIdx.x * 128;

    const __nv_bfloat16* Xhi = g_xthi + (size_t)b * N_ * C_;
    const __nv_bfloat16* Xlo = g_xtlo + (size_t)b * N_ * C_;

    const int wm = (wid >> 2) * 64;   // n
    const int wc = (wid & 3) * 32;    // d

    const uint32_t lrow = lane & 15;
    const uint32_t lswz = (lane & 7) << 4;
    const uint32_t lcol = (lane >> 4) << 4;

    float acc[4][4][4] = {};

    auto load_chunk = [&](int kc) {
        const uint32_t st = (uint32_t)(kc & 1) * STAGE_P;
        const size_t koff = (size_t)kc * 32;
#pragma unroll
        for (int t = 0; t < 8; t++) {
            const int idx = tid + t * 256;
            const int part = idx >> 10;          // 0=A(xT), 1=B(Wqk)
            const int a = idx & 1023;
            const int row = a >> 3, seg = a & 7;
            const __nv_bfloat16* src;
            if (part == 0)
                src = (seg < 4 ? Xhi : Xlo) + (size_t)(n0 + row) * C_ + koff + (seg & 3) * 8;
            else
                src = (seg < 4 ? g_wqkhi : g_wqklo) + (size_t)row * C_ + koff + (seg & 3) * 8;
            cp16(sbase + st + (uint32_t)part * 16384u + swz(row, seg * 16), src);
        }
        asm volatile("cp.async.commit_group;" ::: "memory");
    };

    load_chunk(0);

    for (int kc = 0; kc < C_ / 32; kc++) {
        asm volatile("cp.async.wait_group 0;" ::: "memory");
        __syncthreads();
        if (kc + 1 < C_ / 32) load_chunk(kc + 1);

        const uint32_t st = (uint32_t)(kc & 1) * STAGE_P;
        const uint32_t Ab = sbase + st, Bb = Ab + 16384;

#pragma unroll
        for (int ks = 0; ks < 2; ks++) {
            const uint32_t kbHi = (uint32_t)(ks * 32);
            const uint32_t kbLo = 64u + kbHi;

            uint32_t ah[4][4], al[4][4], bh[2][4], bl[2][4];
#pragma unroll
            for (int i = 0; i < 4; i++) {
                const uint32_t row = (uint32_t)(wm + i * 16) + lrow;
                ldsm4(ah[i], Ab + row * 128u + ((kbHi + lcol) ^ lswz));
                ldsm4(al[i], Ab + row * 128u + ((kbLo + lcol) ^ lswz));
            }
#pragma unroll
            for (int j = 0; j < 2; j++) {
                const uint32_t row = (uint32_t)(wc + j * 16) + lrow;
                ldsm4(bh[j], Bb + row * 128u + ((kbHi + lcol) ^ lswz));
                ldsm4(bl[j], Bb + row * 128u + ((kbLo + lcol) ^ lswz));
            }
#pragma unroll
            for (int i = 0; i < 4; i++)
#pragma unroll
                for (int j = 0; j < 4; j++) {
                    const int t2 = j >> 1, p2 = j & 1;
                    mma_bf16(acc[i][j], ah[i], bh[t2][p2], bh[t2][2 + p2]);
                    mma_bf16(acc[i][j], al[i], bh[t2][p2], bh[t2][2 + p2]);
                    mma_bf16(acc[i][j], ah[i], bl[t2][p2], bl[t2][2 + p2]);
                }
        }
        __syncthreads();
    }

    // Epilogue: bias add, split hi/lo, packed bf16x2 stores from registers.
#pragma unroll
    for (int j = 0; j < 4; j++) {
        const int d = wc + j * 8 + (lane & 3) * 2;   // even; pair never straddles 64
        const bool isq = d < 64;
        const int dd = isq ? d : d - 64;
        const float b0v = isq ? bq[dd] : bk[dd];
        const float b1v = isq ? bq[dd + 1] : bk[dd + 1];
        __nv_bfloat16* dhi = isq ? qhi : khi;
        __nv_bfloat16* dlo = isq ? qlo : klo;
#pragma unroll
        for (int i = 0; i < 4; i++) {
            const int n = n0 + wm + i * 16 + (lane >> 2);
#pragma unroll
            for (int r = 0; r < 2; r++) {          // row n, n+8
                const float v0 = acc[i][j][r * 2] + b0v;
                const float v1 = acc[i][j][r * 2 + 1] + b1v;
                const float h0 = __bfloat162float(__float2bfloat16(v0));
                const float h1 = __bfloat162float(__float2bfloat16(v1));
                const size_t off = ((size_t)b * N_ + n + r * 8) * D_ + dd;
                *reinterpret_cast<uint32_t*>(dhi + off) = pack_bf16(v0, v1);
                *reinterpret_cast<uint32_t*>(dlo + off) = pack_bf16(v0 - h0, v1 - h1);
            }
        }
    }
}

// ---------------------------------------------------------------------------
// proj_v (HMMA): v[b,c,n] = sum_k Wv[c,k] x[b,k,n] + bv[c], compensated bf16.
// ---------------------------------------------------------------------------
__global__ void __launch_bounds__(256, 2)
proj_v_hmma_kernel(const float* __restrict__ bias, __half* __restrict__ vf16) {
    extern __shared__ char dynsmem[];
    const uint32_t sbase = smem_u32(dynsmem);

    const int tid  = threadIdx.x;
    const int wid  = tid >> 5;
    const int lane = tid & 31;

    const int b  = blockIdx.z;
    const int c0 = blockIdx.x * 128;
    const int n0 = blockIdx.y * 128;

    const __nv_bfloat16* Whi = g_wvhi;
    const __nv_bfloat16* Wlo = g_wvlo;
    const __nv_bfloat16* Xhi = g_xthi + (size_t)b * N_ * C_;
    const __nv_bfloat16* Xlo = g_xtlo + (size_t)b * N_ * C_;

    const int wm = (wid >> 2) * 64;   // c
    const int wn = (wid & 3) * 32;    // n

    const uint32_t lrow = lane & 15;
    const uint32_t lswz = (lane & 7) << 4;
    const uint32_t lcol = (lane >> 4) << 4;

    float acc[4][4][4] = {};

    auto load_chunk = [&](int kc) {
        const uint32_t st = (uint32_t)(kc & 1) * STAGE_P;
        const size_t koff = (size_t)kc * 32;
#pragma unroll
        for (int t = 0; t < 8; t++) {
            const int idx = tid + t * 256;
            const int part = idx >> 10;          // 0=A(Wv), 1=B(xT)
            const int a = idx & 1023;
            const int row = a >> 3, seg = a & 7;
            const __nv_bfloat16* src;
            if (part == 0)
                src = (seg < 4 ? Whi : Wlo) + (size_t)(c0 + row) * C_ + koff + (seg & 3) * 8;
            else
                src = (seg < 4 ? Xhi : Xlo) + (size_t)(n0 + row) * C_ + koff + (seg & 3) * 8;
            cp16(sbase + st + (uint32_t)part * 16384u + swz(row, seg * 16), src);
        }
        asm volatile("cp.async.commit_group;" ::: "memory");
    };

    load_chunk(0);

    for (int kc = 0; kc < C_ / 32; kc++) {
        asm volatile("cp.async.wait_group 0;" ::: "memory");
        __syncthreads();
        if (kc + 1 < C_ / 32) load_chunk(kc + 1);

        const uint32_t st = (uint32_t)(kc & 1) * STAGE_P;
        const uint32_t Ab = sbase + st, Bb = Ab + 16384;

#pragma unroll
        for (int ks = 0; ks < 2; ks++) {
            const uint32_t kbHi = (uint32_t)(ks * 32);
            const uint32_t kbLo = 64u + kbHi;

            uint32_t ah[4][4], al[4][4], bh[2][4], bl[2][4];
#pragma unroll
            for (int i = 0; i < 4; i++) {
                const uint32_t row = (uint32_t)(wm + i * 16) + lrow;
                ldsm4(ah[i], Ab + row * 128u + ((kbHi + lcol) ^ lswz));
                ldsm4(al[i], Ab + row * 128u + ((kbLo + lcol) ^ lswz));
            }
#pragma unroll
            for (int j = 0; j < 2; j++) {
                const uint32_t row = (uint32_t)(wn + j * 16) + lrow;
                ldsm4(bh[j], Bb + row * 128u + ((kbHi + lcol) ^ lswz));
                ldsm4(bl[j], Bb + row * 128u + ((kbLo + lcol) ^ lswz));
            }
#pragma unroll
            for (int i = 0; i < 4; i++)
#pragma unroll
                for (int j = 0; j < 4; j++) {
                    const int t2 = j >> 1, p2 = j & 1;
                    mma_bf16(acc[i][j], ah[i], bh[t2][p2], bh[t2][2 + p2]);
                    mma_bf16(acc[i][j], al[i], bh[t2][p2], bh[t2][2 + p2]);
                    mma_bf16(acc[i][j], ah[i], bl[t2][p2], bl[t2][2 + p2]);
                }
        }
        __syncthreads();
    }

    // Epilogue: c-major rows in smem (n contiguous), add bias, emit fp16.
    float* sOut = reinterpret_cast<float*>(dynsmem);
#pragma unroll
    for (int i = 0; i < 4; i++) {
        const int ct = wm + i * 16 + (lane >> 2);
#pragma unroll
        for (int j = 0; j < 4; j++) {
            const int nt = wn + j * 8 + (lane & 3) * 2;
            sOut[ct * EPI_P + nt]           = acc[i][j][0];
            sOut[ct * EPI_P + nt + 1]       = acc[i][j][1];
            sOut[(ct + 8) * EPI_P + nt]     = acc[i][j][2];
            sOut[(ct + 8) * EPI_P + nt + 1] = acc[i][j][3];
        }
    }
    __syncthreads();

    const int row = tid >> 1;             // c within tile
    const int col0 = (tid & 1) * 64;      // n offset
    const float bv = bias[c0 + row];
    const float* srow = sOut + row * EPI_P + col0;
    __half* dst = vf16 + ((size_t)b * C_ + c0 + row) * N_ + n0 + col0;
#pragma unroll
    for (int v = 0; v < 16; v++) {
        float4 f = *reinterpret_cast<const float4*>(srow + v * 4);
        __half2 h01 = __floats2half2_rn(f.x + bv, f.y + bv);
        __half2 h23 = __floats2half2_rn(f.z + bv, f.w + bv);
        uint2 u;
        u.x = *reinterpret_cast<uint32_t*>(&h01);
        u.y = *reinterpret_cast<uint32_t*>(&h23);
        *reinterpret_cast<uint2*>(dst + v * 4) = u;
    }
}

// ---------------------------------------------------------------------------
// Energy (HMMA): per-batch instance (b passed in; grid.z = 1).
// ---------------------------------------------------------------------------
__global__ void __launch_bounds__(256)
energy_hmma_kernel(float* __restrict__ attn, int b) {
    extern __shared__ char dynsmem[];
    const uint32_t sbase = smem_u32(dynsmem);

    const int tid  = threadIdx.x;
    const int wid  = tid >> 5;
    const int lane = tid & 31;

    const int n0 = blockIdx.x * 128;
    const int m0 = blockIdx.y * 128;

    const __nv_bfloat16* Qhi = g_qhi + (size_t)b * N_ * D_;
    const __nv_bfloat16* Qlo = g_qlo + (size_t)b * N_ * D_;
    const __nv_bfloat16* Khi = g_khi + (size_t)b * N_ * D_;
    const __nv_bfloat16* Klo = g_klo + (size_t)b * N_ * D_;

    const int wm = (wid >> 2) * 64;
    const int wn = (wid & 3) * 32;

    const uint32_t lrow = lane & 15;
    const uint32_t lswz = (lane & 7) << 4;
    const uint32_t lcol = (lane >> 4) << 4;

#pragma unroll
    for (int t = 0; t < 4; t++) {
        const int idx = tid + t * 256;
        const int row = idx >> 3, seg = idx & 7;
        cp16(sbase + swz(row, seg * 16), Qhi + (size_t)(m0 + row) * D_ + seg * 8);
        cp16(sbase + 16384 + swz(row, seg * 16), Khi + (size_t)(n0 + row) * D_ + seg * 8);
    }
    asm volatile("cp.async.commit_group;" ::: "memory");
#pragma unroll
    for (int t = 0; t < 4; t++) {
        const int idx = tid + t * 256;
        const int row = idx >> 3, seg = idx & 7;
        cp16(sbase + 32768 + swz(row, seg * 16), Qlo + (size_t)(m0 + row) * D_ + seg * 8);
        cp16(sbase + 49152 + swz(row, seg * 16), Klo + (size_t)(n0 + row) * D_ + seg * 8);
    }
    asm volatile("cp.async.commit_group;" ::: "memory");

    float acc[4][4][4] = {};

    asm volatile("cp.async.wait_group 1;" ::: "memory");
    __syncthreads();
#pragma unroll
    for (int ks = 0; ks < 4; ks++) {
        const uint32_t kb = (uint32_t)(ks * 32);
        uint32_t a[4][4], bm[2][4];
#pragma unroll
        for (int i = 0; i < 4; i++) {
            const uint32_t row = (uint32_t)(wm + i * 16) + lrow;
            ldsm4(a[i], sbase + row * 128u + ((kb + lcol) ^ lswz));
        }
#pragma unroll
        for (int j = 0; j < 2; j++) {
            const uint32_t row = (uint32_t)(wn + j * 16) + lrow;
            ldsm4(bm[j], sbase + 16384 + row * 128u + ((kb + lcol) ^ lswz));
        }
#pragma unroll
        for (int i = 0; i < 4; i++)
#pragma unroll
            for (int j = 0; j < 4; j++) {
                const int t2 = j >> 1, p2 = j & 1;
                mma_bf16(acc[i][j], a[i], bm[t2][p2], bm[t2][2 + p2]);
            }
    }

    asm volatile("cp.async.wait_group 0;" ::: "memory");
    __syncthreads();
#pragma unroll
    for (int ks = 0; ks < 4; ks++) {
        const uint32_t kb = (uint32_t)(ks * 32);
        uint32_t ah[4][4], al[4][4], bh[2][4], bl[2][4];
#pragma unroll
        for (int i = 0; i < 4; i++) {
            const uint32_t row = (uint32_t)(wm + i * 16) + lrow;
            ldsm4(ah[i], sbase + row * 128u + ((kb + lcol) ^ lswz));
            ldsm4(al[i], sbase + 32768 + row * 128u + ((kb + lcol) ^ lswz));
        }
#pragma unroll
        for (int j = 0; j < 2; j++) {
            const uint32_t row = (uint32_t)(wn + j * 16) + lrow;
            ldsm4(bh[j], sbase + 16384 + row * 128u + ((kb + lcol) ^ lswz));
            ldsm4(bl[j], sbase + 49152 + row * 128u + ((kb + lcol) ^ lswz));
        }
#pragma unroll
        for (int i = 0; i < 4; i++)
#pragma unroll
            for (int j = 0; j < 4; j++) {
                const int t2 = j >> 1, p2 = j & 1;
                mma_bf16(acc[i][j], al[i], bh[t2][p2], bh[t2][2 + p2]);
                mma_bf16(acc[i][j], ah[i], bl[t2][p2], bl[t2][2 + p2]);
            }
    }

    __syncthreads();
    float* sOut = reinterpret_cast<float*>(dynsmem);
#pragma unroll
    for (int i = 0; i < 4; i++) {
        const int mt = wm + i * 16 + (lane >> 2);
#pragma unroll
        for (int j = 0; j < 4; j++) {
            const int nt = wn + j * 8 + (lane & 3) * 2;
            sOut[mt * EPI_P + nt]           = acc[i][j][0];
            sOut[mt * EPI_P + nt + 1]       = acc[i][j][1];
            sOut[(mt + 8) * EPI_P + nt]     = acc[i][j][2];
            sOut[(mt + 8) * EPI_P + nt + 1] = acc[i][j][3];
        }
    }
    __syncthreads();

    float* eb = attn + (size_t)b * N_ * N_;
    const int row = tid >> 1;
    const int col0 = (tid & 1) * 64;
    const float* srow = sOut + row * EPI_P + col0;
    float* grow = eb + (size_t)(m0 + row) * N_ + n0 + col0;
#pragma unroll
    for (int v = 0; v < 16; v++)
        *reinterpret_cast<float4*>(grow + v * 4) =
            *reinterpret_cast<const float4*>(srow + v * 4);
}

// ---------------------------------------------------------------------------
// Row softmax in place (per-batch; blockIdx.x = row within batch b).
// ---------------------------------------------------------------------------
__global__ void softmax_kernel(float* __restrict__ attn,
                               __half* __restrict__ af16, int b) {
    const size_t row = (size_t)b * N_ + blockIdx.x;
    float* p = attn + row * N_;
    const int tid = threadIdx.x;

    float4 v[4];
    float mx = -3.0e38f;
#pragma unroll
    for (int i = 0; i < 4; i++) {
        v[i] = *reinterpret_cast<const float4*>(p + tid * 4 + i * 1024);
        mx = fmaxf(mx, fmaxf(fmaxf(v[i].x, v[i].y), fmaxf(v[i].z, v[i].w)));
    }
    __shared__ float red[8];
#pragma unroll
    for (int o = 16; o; o >>= 1) mx = fmaxf(mx, __shfl_xor_sync(0xffffffffu, mx, o));
    if ((tid & 31) == 0) red[tid >> 5] = mx;
    __syncthreads();
    mx = red[0];
#pragma unroll
    for (int i = 1; i < 8; i++) mx = fmaxf(mx, red[i]);
    __syncthreads();

    float s = 0.f;
#pragma unroll
    for (int i = 0; i < 4; i++) {
        v[i].x = __expf(v[i].x - mx); v[i].y = __expf(v[i].y - mx);
        v[i].z = __expf(v[i].z - mx); v[i].w = __expf(v[i].w - mx);
        s += (v[i].x + v[i].y) + (v[i].z + v[i].w);
    }
#pragma unroll
    for (int o = 16; o; o >>= 1) s += __shfl_xor_sync(0xffffffffu, s, o);
    if ((tid & 31) == 0) red[tid >> 5] = s;
    __syncthreads();
    s = 0.f;
#pragma unroll
    for (int i = 0; i < 8; i++) s += red[i];
    const float inv = 1.0f / s;

    __half* ph = af16 + row * N_;
#pragma unroll
    for (int i = 0; i < 4; i++) {
        float4 r;
        r.x = v[i].x * inv; r.y = v[i].y * inv; r.z = v[i].z * inv; r.w = v[i].w * inv;
        *reinterpret_cast<float4*>(p + tid * 4 + i * 1024) = r;

        __half2 h01 = __floats2half2_rn(r.x, r.y);
        __half2 h23 = __floats2half2_rn(r.z, r.w);
        uint2 hh;
        hh.x = *reinterpret_cast<uint32_t*>(&h01);
        hh.y = *reinterpret_cast<uint32_t*>(&h23);
        *reinterpret_cast<uint2*>(ph + tid * 4 + i * 1024) = hh;
    }
}

// ---------------------------------------------------------------------------
// out-GEMM (per-batch): HMMA fp16, CTA 128m x 64c, 2-stage ring, 3 CTAs/SM.
// ---------------------------------------------------------------------------
__global__ void __launch_bounds__(256, 3)
out_gemm_kernel(const float* __restrict__ x,
                const float* __restrict__ gamma,
                float* __restrict__ out, int b) {
    extern __shared__ char dynsmem[];
    const uint32_t sbase = smem_u32(dynsmem);

    const int tid  = threadIdx.x;
    const int wid  = tid >> 5;
    const int lane = tid & 31;

    const int c0 = blockIdx.x * 64;    // c fastest: 8 siblings share A tile in L2
    const int m0 = blockIdx.y * 128;

    const __half* A = g_af16 + (size_t)b * N_ * N_;
    const __half* V = g_vf16 + (size_t)b * C_ * N_;

    const int wm = (wid >> 2) * 64;    // m offset of warp
    const int wc = (wid & 3) * 16;     // c offset of warp

    const uint32_t lrow = lane & 15;
    const uint32_t lswz = (lane & 7) << 4;
    const uint32_t lcol = (lane >> 4) << 4;

    float acc[4][2][4] = {};   // [m16][c8][reg]

    auto load_chunk = [&](int kc) {
        const uint32_t st = (uint32_t)(kc & 1) * STAGE_O;
        const size_t koff = (size_t)kc * KC_O;
#pragma unroll
        for (int t = 0; t < 6; t++) {
            const int idx = tid + t * 256;
            if (idx < 1024) {
                const int row = idx >> 3, seg = idx & 7;
                cp16(sbase + st + swz(row, seg * 16),
                     A + (size_t)(m0 + row) * N_ + koff + seg * 8);
            } else {
                const int i2 = idx - 1024;
                const int row = i2 >> 3, seg = i2 & 7;
                cp16(sbase + st + 16384u + swz(row, seg * 16),
                     V + (size_t)(c0 + row) * N_ + koff + seg * 8);
            }
        }
        asm volatile("cp.async.commit_group;" ::: "memory");
    };

    load_chunk(0);

    for (int kc = 0; kc < NCHUNK_O; kc++) {
        asm volatile("cp.async.wait_group 0;" ::: "memory");
        __syncthreads();
        if (kc + 1 < NCHUNK_O) load_chunk(kc + 1);

        const uint32_t st = (uint32_t)(kc & 1) * STAGE_O;
        const uint32_t Ab = sbase + st, Vb = Ab + 16384;

#pragma unroll
        for (int ks = 0; ks < 4; ks++) {
            const uint32_t kb = (uint32_t)(ks * 32);
            uint32_t a[4][4], bm[4];
#pragma unroll
            for (int i = 0; i < 4; i++) {
                const uint32_t row = (uint32_t)(wm + i * 16) + lrow;
                ldsm4(a[i], Ab + row * 128u + ((kb + lcol) ^ lswz));
            }
            {
                const uint32_t row = (uint32_t)wc + lrow;
                ldsm4(bm, Vb + row * 128u + ((kb + lcol) ^ lswz));
            }
#pragma unroll
            for (int i = 0; i < 4; i++)
#pragma unroll
                for (int p2 = 0; p2 < 2; p2++)
                    mma_f16(acc[i][p2], a[i], bm[p2], bm[2 + p2]);
        }
    }
    __syncthreads();

    // ---- epilogue: full 64c x 128m transpose via smem ----
    float* sOut = reinterpret_cast<float*>(dynsmem);
#pragma unroll
    for (int i = 0; i < 4; i++) {
        const int mt = wm + i * 16 + (lane >> 2);
#pragma unroll
        for (int p2 = 0; p2 < 2; p2++) {
            const int ct = wc + p2 * 8 + (lane & 3) * 2;
            sOut[ct * EPI_P + mt]           = acc[i][p2][0];
            sOut[(ct + 1) * EPI_P + mt]     = acc[i][p2][1];
            sOut[ct * EPI_P + mt + 8]       = acc[i][p2][2];
            sOut[(ct + 1) * EPI_P + mt + 8] = acc[i][p2][3];
        }
    }
    __syncthreads();

    const float g = gamma[0];
    const int ce = tid >> 2;             // 0..63
    const int me = (tid & 3) * 32;       // m offset
    const size_t gb = ((size_t)b * C_ + c0 + ce) * N_ + m0 + me;
    const float* srow = sOut + ce * EPI_P + me;
#pragma unroll
    for (int v = 0; v < 8; v++) {
        const float4 xv = *reinterpret_cast<const float4*>(x + gb + v * 4);
        float4 ov;
        ov.x = g * srow[v * 4 + 0] + xv.x;
        ov.y = g * srow[v * 4 + 1] + xv.y;
        ov.z = g * srow[v * 4 + 2] + xv.z;
        ov.w = g * srow[v * 4 + 3] + xv.w;
        *reinterpret_cast<float4*>(out + gb + v * 4) = ov;
    }
}

// ---------------------------------------------------------------------------
extern "C" void kernel_launch(void* const* d_in, const int* in_sizes, int n_in,
                              void* d_out, int out_size) {
    (void)in_sizes; (void)n_in; (void)out_size;
    const float* x     = (const float*)d_in[0];
    const float* Wq    = (const float*)d_in[1];
    const float* bq    = (const float*)d_in[2];
    const float* Wk    = (const float*)d_in[3];
    const float* bk    = (const float*)d_in[4];
    const float* Wv    = (const float*)d_in[5];
    const float* bv    = (const float*)d_in[6];
    const float* gamma = (const float*)d_in[7];

    float* out  = (float*)d_out;
    float* attn = out + (size_t)B_ * C_ * N_;   // tuple order: (out, attention)

    __nv_bfloat16 *qhi, *qlo, *khi, *klo, *xthi, *xtlo, *wvhi, *wvlo, *wqkhi, *wqklo;
    __half *vf16, *af16;
    cudaGetSymbolAddress((void**)&qhi, g_qhi);
    cudaGetSymbolAddress((void**)&qlo, g_qlo);
    cudaGetSymbolAddress((void**)&khi, g_khi);
    cudaGetSymbolAddress((void**)&klo, g_klo);
    cudaGetSymbolAddress((void**)&xthi, g_xthi);
    cudaGetSymbolAddress((void**)&xtlo, g_xtlo);
    cudaGetSymbolAddress((void**)&wvhi, g_wvhi);
    cudaGetSymbolAddress((void**)&wvlo, g_wvlo);
    cudaGetSymbolAddress((void**)&wqkhi, g_wqkhi);
    cudaGetSymbolAddress((void**)&wqklo, g_wqklo);
    cudaGetSymbolAddress((void**)&vf16, g_vf16);
    cudaGetSymbolAddress((void**)&af16, g_af16);

    cudaFuncSetAttribute(out_gemm_kernel,
                         cudaFuncAttributeMaxDynamicSharedMemorySize, DYN_OUT);
    cudaFuncSetAttribute(energy_hmma_kernel,
                         cudaFuncAttributeMaxDynamicSharedMemorySize, DYN_E);
    cudaFuncSetAttribute(proj_v_hmma_kernel,
                         cudaFuncAttributeMaxDynamicSharedMemorySize, DYN_V);
    cudaFuncSetAttribute(proj_qk_hmma_kernel,
                         cudaFuncAttributeMaxDynamicSharedMemorySize, DYN_QK);

    // ONE extra stream (Round-10-proven resource budget) + 6 events.
    // kernel_launch runs only twice; these handles are intentionally leaked.
    cudaStream_t s1;
    cudaStreamCreateWithFlags(&s1, cudaStreamNonBlocking);
    cudaEvent_t eFork, eX, eWqk, eV, eQK, eDone;
    cudaEventCreateWithFlags(&eFork, cudaEventDisableTiming);
    cudaEventCreateWithFlags(&eX,    cudaEventDisableTiming);
    cudaEventCreateWithFlags(&eWqk,  cudaEventDisableTiming);
    cudaEventCreateWithFlags(&eV,    cudaEventDisableTiming);
    cudaEventCreateWithFlags(&eQK,   cudaEventDisableTiming);
    cudaEventCreateWithFlags(&eDone, cudaEventDisableTiming);

    dim3 blk(256);

    // fork side stream off the (captured) legacy stream
    cudaEventRecord(eFork, 0);
    cudaStreamWaitEvent(s1, eFork, 0);

    // s1: weight converts (independent of x)
    convert_w_kernel<<<dim3(C_ * C_ / 256), blk, 0, s1>>>(Wv, wvhi, wvlo);
    convert_wqk_kernel<<<dim3(128 * C_ / 256), blk, 0, s1>>>(Wq, Wk, wqkhi, wqklo);
    cudaEventRecord(eWqk, s1);

    // s0: x transpose/split
    convert_x_kernel<<<dim3(N_ / 32, C_ / 32, B_), blk>>>(x, xthi, xtlo);
    cudaEventRecord(eX, 0);

    // s1: proj_v (needs convert_x + convert_w) — overlaps proj_qk/energy(b0)
    cudaStreamWaitEvent(s1, eX, 0);
    proj_v_hmma_kernel<<<dim3(C_ / 128, N_ / 128, B_), blk, DYN_V, s1>>>(bv, vf16);
    cudaEventRecord(eV, s1);

    // s0: proj_qk (needs convert_x + convert_wqk)
    cudaStreamWaitEvent(0, eWqk, 0);
    proj_qk_hmma_kernel<<<dim3(N_ / 128, 1, B_), blk, DYN_QK>>>(bq, bk, qhi, qlo, khi, klo);
    cudaEventRecord(eQK, 0);

    // Two-way batch pipeline: s0 handles b=0,2; s1 handles b=1,3.
    // s1 already serializes after proj_v; it still needs q/k (eQK).
    cudaStreamWaitEvent(s1, eQK, 0);
    // s0 needs v before its out_gemm launches (eV).
    for (int i = 0; i < 2; i++) {
        const int b0 = 2 * i;      // s0 batches: 0, 2
        const int b1 = 2 * i + 1;  // s1 batches: 1, 3

        energy_hmma_kernel<<<dim3(N_ / 128, N_ / 128, 1), blk, DYN_E, 0>>>(attn, b0);
        energy_hmma_kernel<<<dim3(N_ / 128, N_ / 128, 1), blk, DYN_E, s1>>>(attn, b1);

        softmax_kernel<<<dim3(N_), blk, 0, 0>>>(attn, af16, b0);
        softmax_kernel<<<dim3(N_), blk, 0, s1>>>(attn, af16, b1);

        if (i == 0) cudaStreamWaitEvent(0, eV, 0);   // v ready before first out_gemm
        out_gemm_kernel<<<dim3(C_ / 64, N_ / 128, 1), blk, DYN_OUT, 0>>>(x, gamma, out, b0);
        out_gemm_kernel<<<dim3(C_ / 64, N_ / 128, 1), blk, DYN_OUT, s1>>>(x, gamma, out, b1);
    }

    // join s1 back to the legacy (capture-origin) stream
    cudaEventRecord(eDone, s1);
    cudaStreamWaitEvent(0, eDone, 0);
}

// round 13
// speedup vs baseline: 5.8284x; 1.0038x over previous
#include <cuda_runtime.h>
#include <cuda_bf16.h>
#include <cuda_fp16.h>
#include <cstdint>

// Self_Attn: B=4, C=512, N=4096 (64x64), D=64
// Outputs (tuple order): out [B,C,64,64] fp32, attention [B,N,N] fp32.

namespace {
constexpr int B_ = 4;
constexpr int C_ = 512;
constexpr int N_ = 4096;
constexpr int D_ = 64;

constexpr int KC_O = 64;             // out-GEMM K elems per chunk (128B fp16 row)
constexpr int NCHUNK_O = N_ / KC_O;  // 64
constexpr int STAGE_P = 32768;       // proj stage: A 16K + B 16K
constexpr int STAGE_O = 24576;       // out stage: A 16K + V 8K
constexpr int EPI_P = 132;           // epilogue smem pitch (floats)
constexpr int DYN_OUT = 2 * STAGE_O; // 49152 (2-stage; epi 33.8K reuses)
constexpr int DYN_E = 128 * EPI_P * 4;  // 67584
constexpr int DYN_V = 128 * EPI_P * 4;  // 67584
constexpr int DYN_QK = 2 * STAGE_P;  // 65536
}

// Scratch (device globals; no runtime allocation allowed).
__device__ __nv_bfloat16 g_qhi[B_ * N_ * D_];           // [B][N][D]
__device__ __nv_bfloat16 g_qlo[B_ * N_ * D_];
__device__ __nv_bfloat16 g_khi[B_ * N_ * D_];
__device__ __nv_bfloat16 g_klo[B_ * N_ * D_];
__device__ __nv_bfloat16 g_xthi[(size_t)B_ * N_ * C_];  // x^T [B][N][C] k-contig
__device__ __nv_bfloat16 g_xtlo[(size_t)B_ * N_ * C_];
__device__ __nv_bfloat16 g_wvhi[C_ * C_];               // Wv [c][k]
__device__ __nv_bfloat16 g_wvlo[C_ * C_];
__device__ __nv_bfloat16 g_wqkhi[128 * C_];             // stacked [Wq;Wk] [d][c]
__device__ __nv_bfloat16 g_wqklo[128 * C_];
__device__ __half g_vf16[(size_t)B_ * C_ * N_];         // v [B][C][N] fp16
__device__ __half g_af16[(size_t)B_ * N_ * N_];         // attn fp16 [B][M][N]

// ---------------------------------------------------------------------------
// helpers
// ---------------------------------------------------------------------------
__device__ __forceinline__ uint32_t smem_u32(const void* p) {
    uint32_t a;
    asm("{ .reg .u64 t; cvta.to.shared.u64 t, %1; cvt.u32.u64 %0, t; }" : "=r"(a) : "l"(p));
    return a;
}

__device__ __forceinline__ void cp16(uint32_t dst, const void* src) {
    asm volatile("cp.async.cg.shared.global [%0], [%1], 16;" :: "r"(dst), "l"(src) : "memory");
}

__device__ __forceinline__ void ldsm4(uint32_t* r, uint32_t addr) {
    asm volatile("ldmatrix.sync.aligned.m8n8.x4.shared.b16 {%0,%1,%2,%3}, [%4];"
                 : "=r"(r[0]), "=r"(r[1]), "=r"(r[2]), "=r"(r[3]) : "r"(addr));
}

__device__ __forceinline__ void mma_bf16(float* d, const uint32_t* a, uint32_t b0, uint32_t b1) {
    asm volatile(
        "mma.sync.aligned.m16n8k16.row.col.f32.bf16.bf16.f32 "
        "{%0,%1,%2,%3}, {%4,%5,%6,%7}, {%8,%9}, {%0,%1,%2,%3};"
        : "+f"(d[0]), "+f"(d[1]), "+f"(d[2]), "+f"(d[3])
        : "r"(a[0]), "r"(a[1]), "r"(a[2]), "r"(a[3]), "r"(b0), "r"(b1));
}

__device__ __forceinline__ void mma_f16(float* d, const uint32_t* a, uint32_t b0, uint32_t b1) {
    asm volatile(
        "mma.sync.aligned.m16n8k16.row.col.f32.f16.f16.f32 "
        "{%0,%1,%2,%3}, {%4,%5,%6,%7}, {%8,%9}, {%0,%1,%2,%3};"
        : "+f"(d[0]), "+f"(d[1]), "+f"(d[2]), "+f"(d[3])
        : "r"(a[0]), "r"(a[1]), "r"(a[2]), "r"(a[3]), "r"(b0), "r"(b1));
}

__device__ __forceinline__ uint32_t swz(uint32_t row, uint32_t colbyte) {
    return row * 128u + (colbyte ^ ((row & 7u) << 4));
}

__device__ __forceinline__ uint32_t pack_bf16(float a, float b) {
    __nv_bfloat162 h = __floats2bfloat162_rn(a, b);
    return *reinterpret_cast<uint32_t*>(&h);
}

// ---------------------------------------------------------------------------
// Transpose + split x: x[b][k][n] fp32 -> xT[b][n][k] bf16 hi/lo.
// ---------------------------------------------------------------------------
__global__ void convert_x_kernel(const float* __restrict__ x,
                                 __nv_bfloat16* __restrict__ xthi,
                                 __nv_bfloat16* __restrict__ xtlo) {
    const int b  = blockIdx.z;
    const int n0 = blockIdx.x * 32;
    const int k0 = blockIdx.y * 32;
    __shared__ float t[32][33];
    const int tid = threadIdx.x;
#pragma unroll
    for (int i = 0; i < 4; i++) {
        int idx = tid + i * 256;
        int k = idx >> 5, n = idx & 31;
        t[k][n] = x[((size_t)b * C_ + k0 + k) * N_ + n0 + n];
    }
    __syncthreads();
#pragma unroll
    for (int i = 0; i < 4; i++) {
        int idx = tid + i * 256;
        int n = idx >> 5, k = idx & 31;
        float val = t[k][n];
        __nv_bfloat16 h = __float2bfloat16(val);
        size_t off = ((size_t)b * N_ + n0 + n) * C_ + k0 + k;
        xthi[off] = h;
        xtlo[off] = __float2bfloat16(val - __bfloat162float(h));
    }
}

// Split Wv fp32 -> bf16 hi/lo.
__global__ void convert_w_kernel(const float* __restrict__ W,
                                 __nv_bfloat16* __restrict__ whi,
                                 __nv_bfloat16* __restrict__ wlo) {
    const int i = blockIdx.x * 256 + threadIdx.x;
    float val = W[i];
    __nv_bfloat16 h = __float2bfloat16(val);
    whi[i] = h;
    wlo[i] = __float2bfloat16(val - __bfloat162float(h));
}

// Stack Wq (rows 0..63) and Wk (rows 64..127) into Wqk bf16 hi/lo.
__global__ void convert_wqk_kernel(const float* __restrict__ Wq,
                                   const float* __restrict__ Wk,
                                   __nv_bfloat16* __restrict__ whi,
                                   __nv_bfloat16* __restrict__ wlo) {
    const int i = blockIdx.x * 256 + threadIdx.x;   // over 128*512
    const int d = i >> 9, c = i & 511;
    float val = d < 64 ? Wq[(size_t)d * C_ + c] : Wk[(size_t)(d - 64) * C_ + c];
    __nv_bfloat16 h = __float2bfloat16(val);
    whi[i] = h;
    wlo[i] = __float2bfloat16(val - __bfloat162float(h));
}

// ---------------------------------------------------------------------------
// proj_qk (HMMA, fused): CTA 128n x 128d, 2-stage ring, compensated bf16.
// ---------------------------------------------------------------------------
__global__ void __launch_bounds__(256, 2)
proj_qk_hmma_kernel(const float* __restrict__ bq, const float* __restrict__ bk,
                    __nv_bfloat16* __restrict__ qhi, __nv_bfloat16* __restrict__ qlo,
                    __nv_bfloat16* __restrict__ khi, __nv_bfloat16* __restrict__ klo) {
    extern __shared__ char dynsmem[];
    const uint32_t sbase = smem_u32(dynsmem);

    const int tid  = threadIdx.x;
    const int wid  = tid >> 5;
    const int lane = tid & 31;

    const int b  = blockIdx.z;
    const int n0 = blockIdx.x * 128;

    const __nv_bfloat16* Xhi = g_xthi + (size_t)b * N_ * C_;
    const __nv_bfloat16* Xlo = g_xtlo + (size_t)b * N_ * C_;

    const int wm = (wid >> 2) * 64;   // n
    const int wc = (wid & 3) * 32;    // d

    const uint32_t lrow = lane & 15;
    const uint32_t lswz = (lane & 7) << 4;
    const uint32_t lcol = (lane >> 4) << 4;

    float acc[4][4][4] = {};

    auto load_chunk = [&](int kc) {
        const uint32_t st = (uint32_t)(kc & 1) * STAGE_P;
        const size_t koff = (size_t)kc * 32;
#pragma unroll
        for (int t = 0; t < 8; t++) {
            const int idx = tid + t * 256;
            const int part = idx >> 10;          // 0=A(xT), 1=B(Wqk)
            const int a = idx & 1023;
            const int row = a >> 3, seg = a & 7;
            const __nv_bfloat16* src;
            if (part == 0)
                src = (seg < 4 ? Xhi : Xlo) + (size_t)(n0 + row) * C_ + koff + (seg & 3) * 8;
            else
                src = (seg < 4 ? g_wqkhi : g_wqklo) + (size_t)row * C_ + koff + (seg & 3) * 8;
            cp16(sbase + st + (uint32_t)part * 16384u + swz(row, seg * 16), src);
        }
        asm volatile("cp.async.commit_group;" ::: "memory");
    };

    load_chunk(0);

    for (int kc = 0; kc < C_ / 32; kc++) {
        asm volatile("cp.async.wait_group 0;" ::: "memory");
        __syncthreads();
        if (kc + 1 < C_ / 32) load_chunk(kc + 1);

        const uint32_t st = (uint32_t)(kc & 1) * STAGE_P;
        const uint32_t Ab = sbase + st, Bb = Ab + 16384;

#pragma unroll
        for (int ks = 0; ks < 2; ks++) {
            const uint32_t kbHi = (uint32_t)(ks * 32);
            const uint32_t kbLo = 64u + kbHi;

            uint32_t ah[4][4], al[4][4], bh[2][4], bl[2][4];
#pragma unroll
            for (int i = 0; i < 4; i++) {
                const uint32_t row = (uint32_t)(wm + i * 16) + lrow;
                ldsm4(ah[i], Ab + row * 128u + ((kbHi + lcol) ^ lswz));
                ldsm4(al[i], Ab + row * 128u + ((kbLo + lcol) ^ lswz));
            }
#pragma unroll
            for (int j = 0; j < 2; j++) {
                const uint32_t row = (uint32_t)(wc + j * 16) + lrow;
                ldsm4(bh[j], Bb + row * 128u + ((kbHi + lcol) ^ lswz));
                ldsm4(bl[j], Bb + row * 128u + ((kbLo + lcol) ^ lswz));
            }
#pragma unroll
            for (int i = 0; i < 4; i++)
#pragma unroll
                for (int j = 0; j < 4; j++) {
                    const int t2 = j >> 1, p2 = j & 1;
                    mma_bf16(acc[i][j], ah[i], bh[t2][p2], bh[t2][2 + p2]);
                    mma_bf16(acc[i][j], al[i], bh[t2][p2], bh[t2][2 + p2]);
                    mma_bf16(acc[i][j], ah[i], bl[t2][p2], bl[t2][2 + p2]);
                }
        }
        __syncthreads();
    }

    // Epilogue: bias add, split hi/lo, packed bf16x2 stores from registers.
#pragma unroll
    for (int j = 0; j < 4; j++) {
        const int d = wc + j * 8 + (lane & 3) * 2;   // even; pair never straddles 64
        const bool isq = d < 64;
        const int dd = isq ? d : d - 64;
        const float b0v = isq ? bq[dd] : bk[dd];
        const float b1v = isq ? bq[dd + 1] : bk[dd + 1];
        __nv_bfloat16* dhi = isq ? qhi : khi;
        __nv_bfloat16* dlo = isq ? qlo : klo;
#pragma unroll
        for (int i = 0; i < 4; i++) {
            const int n = n0 + wm + i * 16 + (lane >> 2);
#pragma unroll
            for (int r = 0; r < 2; r++) {          // row n, n+8
                const float v0 = acc[i][j][r * 2] + b0v;
                const float v1 = acc[i][j][r * 2 + 1] + b1v;
                const float h0 = __bfloat162float(__float2bfloat16(v0));
                const float h1 = __bfloat162float(__float2bfloat16(v1));
                const size_t off = ((size_t)b * N_ + n + r * 8) * D_ + dd;
                *reinterpret_cast<uint32_t*>(dhi + off) = pack_bf16(v0, v1);
                *reinterpret_cast<uint32_t*>(dlo + off) = pack_bf16(v0 - h0, v1 - h1);
            }
        }
    }
}

// ---------------------------------------------------------------------------
// proj_v (HMMA): v[b,c,n] = sum_k Wv[c,k] x[b,k,n] + bv[c], compensated bf16.
// ---------------------------------------------------------------------------
__global__ void __launch_bounds__(256, 2)
proj_v_hmma_kernel(const float* __restrict__ bias, __half* __restrict__ vf16) {
    extern __shared__ char dynsmem[];
    const uint32_t sbase = smem_u32(dynsmem);

    const int tid  = threadIdx.x;
    const int wid  = tid >> 5;
    const int lane = tid & 31;

    const int b  = blockIdx.z;
    const int c0 = blockIdx.x * 128;
    const int n0 = blockIdx.y * 128;

    const __nv_bfloat16* Whi = g_wvhi;
    const __nv_bfloat16* Wlo = g_wvlo;
    const __nv_bfloat16* Xhi = g_xthi + (size_t)b * N_ * C_;
    const __nv_bfloat16* Xlo = g_xtlo + (size_t)b * N_ * C_;

    const int wm = (wid >> 2) * 64;   // c
    const int wn = (wid & 3) * 32;    // n

    const uint32_t lrow = lane & 15;
    const uint32_t lswz = (lane & 7) << 4;
    const uint32_t lcol = (lane >> 4) << 4;

    float acc[4][4][4] = {};

    auto load_chunk = [&](int kc) {
        const uint32_t st = (uint32_t)(kc & 1) * STAGE_P;
        const size_t koff = (size_t)kc * 32;
#pragma unroll
        for (int t = 0; t < 8; t++) {
            const int idx = tid + t * 256;
            const int part = idx >> 10;          // 0=A(Wv), 1=B(xT)
            const int a = idx & 1023;
            const int row = a >> 3, seg = a & 7;
            const __nv_bfloat16* src;
            if (part == 0)
                src = (seg < 4 ? Whi : Wlo) + (size_t)(c0 + row) * C_ + koff + (seg & 3) * 8;
            else
                src = (seg < 4 ? Xhi : Xlo) + (size_t)(n0 + row) * C_ + koff + (seg & 3) * 8;
            cp16(sbase + st + (uint32_t)part * 16384u + swz(row, seg * 16), src);
        }
        asm volatile("cp.async.commit_group;" ::: "memory");
    };

    load_chunk(0);

    for (int kc = 0; kc < C_ / 32; kc++) {
        asm volatile("cp.async.wait_group 0;" ::: "memory");
        __syncthreads();
        if (kc + 1 < C_ / 32) load_chunk(kc + 1);

        const uint32_t st = (uint32_t)(kc & 1) * STAGE_P;
        const uint32_t Ab = sbase + st, Bb = Ab + 16384;

#pragma unroll
        for (int ks = 0; ks < 2; ks++) {
            const uint32_t kbHi = (uint32_t)(ks * 32);
            const uint32_t kbLo = 64u + kbHi;

            uint32_t ah[4][4], al[4][4], bh[2][4], bl[2][4];
#pragma unroll
            for (int i = 0; i < 4; i++) {
                const uint32_t row = (uint32_t)(wm + i * 16) + lrow;
                ldsm4(ah[i], Ab + row * 128u + ((kbHi + lcol) ^ lswz));
                ldsm4(al[i], Ab + row * 128u + ((kbLo + lcol) ^ lswz));
            }
#pragma unroll
            for (int j = 0; j < 2; j++) {
                const uint32_t row = (uint32_t)(wn + j * 16) + lrow;
                ldsm4(bh[j], Bb + row * 128u + ((kbHi + lcol) ^ lswz));
                ldsm4(bl[j], Bb + row * 128u + ((kbLo + lcol) ^ lswz));
            }
#pragma unroll
            for (int i = 0; i < 4; i++)
#pragma unroll
                for (int j = 0; j < 4; j++) {
                    const int t2 = j >> 1, p2 = j & 1;
                    mma_bf16(acc[i][j], ah[i], bh[t2][p2], bh[t2][2 + p2]);
                    mma_bf16(acc[i][j], al[i], bh[t2][p2], bh[t2][2 + p2]);
                    mma_bf16(acc[i][j], ah[i], bl[t2][p2], bl[t2][2 + p2]);
                }
        }
        __syncthreads();
    }

    // Epilogue: c-major rows in smem (n contiguous), add bias, emit fp16.
    float* sOut = reinterpret_cast<float*>(dynsmem);
#pragma unroll
    for (int i = 0; i < 4; i++) {
        const int ct = wm + i * 16 + (lane >> 2);
#pragma unroll
        for (int j = 0; j < 4; j++) {
            const int nt = wn + j * 8 + (lane & 3) * 2;
            sOut[ct * EPI_P + nt]           = acc[i][j][0];
            sOut[ct * EPI_P + nt + 1]       = acc[i][j][1];
            sOut[(ct + 8) * EPI_P + nt]     = acc[i][j][2];
            sOut[(ct + 8) * EPI_P + nt + 1] = acc[i][j][3];
        }
    }
    __syncthreads();

    const int row = tid >> 1;             // c within tile
    const int col0 = (tid & 1) * 64;      // n offset
    const float bv = bias[c0 + row];
    const float* srow = sOut + row * EPI_P + col0;
    __half* dst = vf16 + ((size_t)b * C_ + c0 + row) * N_ + n0 + col0;
#pragma unroll
    for (int v = 0; v < 16; v++) {
        float4 f = *reinterpret_cast<const float4*>(srow + v * 4);
        __half2 h01 = __floats2half2_rn(f.x + bv, f.y + bv);
        __half2 h23 = __floats2half2_rn(f.z + bv, f.w + bv);
        uint2 u;
        u.x = *reinterpret_cast<uint32_t*>(&h01);
        u.y = *reinterpret_cast<uint32_t*>(&h23);
        *reinterpret_cast<uint2*>(dst + v * 4) = u;
    }
}

// ---------------------------------------------------------------------------
// Energy (HMMA, single merged pass): per-batch instance.
// Loads all 4 tiles (q/k hi/lo), then one pass: 12 ldsm + 48 MMA per ks
// (was 18 ldsm across two passes -> 33% less L1tex issue, one less barrier).
// ---------------------------------------------------------------------------
__global__ void __launch_bounds__(256)
energy_hmma_kernel(float* __restrict__ attn, int b) {
    extern __shared__ char dynsmem[];
    const uint32_t sbase = smem_u32(dynsmem);

    const int tid  = threadIdx.x;
    const int wid  = tid >> 5;
    const int lane = tid & 31;

    const int n0 = blockIdx.x * 128;
    const int m0 = blockIdx.y * 128;

    const __nv_bfloat16* Qhi = g_qhi + (size_t)b * N_ * D_;
    const __nv_bfloat16* Qlo = g_qlo + (size_t)b * N_ * D_;
    const __nv_bfloat16* Khi = g_khi + (size_t)b * N_ * D_;
    const __nv_bfloat16* Klo = g_klo + (size_t)b * N_ * D_;

    const int wm = (wid >> 2) * 64;
    const int wn = (wid & 3) * 32;

    const uint32_t lrow = lane & 15;
    const uint32_t lswz = (lane & 7) << 4;
    const uint32_t lcol = (lane >> 4) << 4;

    // Load all four 16KB tiles: Qhi@0, Khi@16K, Qlo@32K, Klo@48K.
#pragma unroll
    for (int t = 0; t < 4; t++) {
        const int idx = tid + t * 256;
        const int row = idx >> 3, seg = idx & 7;
        cp16(sbase + swz(row, seg * 16), Qhi + (size_t)(m0 + row) * D_ + seg * 8);
        cp16(sbase + 16384 + swz(row, seg * 16), Khi + (size_t)(n0 + row) * D_ + seg * 8);
        cp16(sbase + 32768 + swz(row, seg * 16), Qlo + (size_t)(m0 + row) * D_ + seg * 8);
        cp16(sbase + 49152 + swz(row, seg * 16), Klo + (size_t)(n0 + row) * D_ + seg * 8);
    }
    asm volatile("cp.async.commit_group;" ::: "memory");

    float acc[4][4][4] = {};

    asm volatile("cp.async.wait_group 0;" ::: "memory");
    __syncthreads();

#pragma unroll
    for (int ks = 0; ks < 4; ks++) {
        const uint32_t kb = (uint32_t)(ks * 32);
        uint32_t ah[4][4], al[4][4], bh[2][4], bl[2][4];
#pragma unroll
        for (int i = 0; i < 4; i++) {
            const uint32_t row = (uint32_t)(wm + i * 16) + lrow;
            ldsm4(ah[i], sbase + row * 128u + ((kb + lcol) ^ lswz));
            ldsm4(al[i], sbase + 32768 + row * 128u + ((kb + lcol) ^ lswz));
        }
#pragma unroll
        for (int j = 0; j < 2; j++) {
            const uint32_t row = (uint32_t)(wn + j * 16) + lrow;
            ldsm4(bh[j], sbase + 16384 + row * 128u + ((kb + lcol) ^ lswz));
            ldsm4(bl[j], sbase + 49152 + row * 128u + ((kb + lcol) ^ lswz));
        }
#pragma unroll
        for (int i = 0; i < 4; i++)
#pragma unroll
            for (int j = 0; j < 4; j++) {
                const int t2 = j >> 1, p2 = j & 1;
                mma_bf16(acc[i][j], ah[i], bh[t2][p2], bh[t2][2 + p2]);
                mma_bf16(acc[i][j], al[i], bh[t2][p2], bh[t2][2 + p2]);
                mma_bf16(acc[i][j], ah[i], bl[t2][p2], bl[t2][2 + p2]);
            }
    }

    __syncthreads();
    float* sOut = reinterpret_cast<float*>(dynsmem);
#pragma unroll
    for (int i = 0; i < 4; i++) {
        const int mt = wm + i * 16 + (lane >> 2);
#pragma unroll
        for (int j = 0; j < 4; j++) {
            const int nt = wn + j * 8 + (lane & 3) * 2;
            sOut[mt * EPI_P + nt]           = acc[i][j][0];
            sOut[mt * EPI_P + nt + 1]       = acc[i][j][1];
            sOut[(mt + 8) * EPI_P + nt]     = acc[i][j][2];
            sOut[(mt + 8) * EPI_P + nt + 1] = acc[i][j][3];
        }
    }
    __syncthreads();

    float* eb = attn + (size_t)b * N_ * N_;
    const int row = tid >> 1;
    const int col0 = (tid & 1) * 64;
    const float* srow = sOut + row * EPI_P + col0;
    float* grow = eb + (size_t)(m0 + row) * N_ + n0 + col0;
#pragma unroll
    for (int v = 0; v < 16; v++)
        *reinterpret_cast<float4*>(grow + v * 4) =
            *reinterpret_cast<const float4*>(srow + v * 4);
}

// ---------------------------------------------------------------------------
// Row softmax in place (per-batch; blockIdx.x = row within batch b).
// ---------------------------------------------------------------------------
__global__ void softmax_kernel(float* __restrict__ attn,
                               __half* __restrict__ af16, int b) {
    const size_t row = (size_t)b * N_ + blockIdx.x;
    float* p = attn + row * N_;
    const int tid = threadIdx.x;

    float4 v[4];
    float mx = -3.0e38f;
#pragma unroll
    for (int i = 0; i < 4; i++) {
        v[i] = *reinterpret_cast<const float4*>(p + tid * 4 + i * 1024);
        mx = fmaxf(mx, fmaxf(fmaxf(v[i].x, v[i].y), fmaxf(v[i].z, v[i].w)));
    }
    __shared__ float red[8];
#pragma unroll
    for (int o = 16; o; o >>= 1) mx = fmaxf(mx, __shfl_xor_sync(0xffffffffu, mx, o));
    if ((tid & 31) == 0) red[tid >> 5] = mx;
    __syncthreads();
    mx = red[0];
#pragma unroll
    for (int i = 1; i < 8; i++) mx = fmaxf(mx, red[i]);
    __syncthreads();

    float s = 0.f;
#pragma unroll
    for (int i = 0; i < 4; i++) {
        v[i].x = __expf(v[i].x - mx); v[i].y = __expf(v[i].y - mx);
        v[i].z = __expf(v[i].z - mx); v[i].w = __expf(v[i].w - mx);
        s += (v[i].x + v[i].y) + (v[i].z + v[i].w);
    }
#pragma unroll
    for (int o = 16; o; o >>= 1) s += __shfl_xor_sync(0xffffffffu, s, o);
    if ((tid & 31) == 0) red[tid >> 5] = s;
    __syncthreads();
    s = 0.f;
#pragma unroll
    for (int i = 0; i < 8; i++) s += red[i];
    const float inv = 1.0f / s;

    __half* ph = af16 + row * N_;
#pragma unroll
    for (int i = 0; i < 4; i++) {
        float4 r;
        r.x = v[i].x * inv; r.y = v[i].y * inv; r.z = v[i].z * inv; r.w = v[i].w * inv;
        *reinterpret_cast<float4*>(p + tid * 4 + i * 1024) = r;

        __half2 h01 = __floats2half2_rn(r.x, r.y);
        __half2 h23 = __floats2half2_rn(r.z, r.w);
        uint2 hh;
        hh.x = *reinterpret_cast<uint32_t*>(&h01);
        hh.y = *reinterpret_cast<uint32_t*>(&h23);
        *reinterpret_cast<uint2*>(ph + tid * 4 + i * 1024) = hh;
    }
}

// ---------------------------------------------------------------------------
// out-GEMM (per-batch): HMMA fp16, CTA 128m x 64c, 2-stage ring, 3 CTAs/SM.
// ---------------------------------------------------------------------------
__global__ void __launch_bounds__(256, 3)
out_gemm_kernel(const float* __restrict__ x,
                const float* __restrict__ gamma,
                float* __restrict__ out, int b) {
    extern __shared__ char dynsmem[];
    const uint32_t sbase = smem_u32(dynsmem);

    const int tid  = threadIdx.x;
    const int wid  = tid >> 5;
    const int lane = tid & 31;

    const int c0 = blockIdx.x * 64;    // c fastest: 8 siblings share A tile in L2
    const int m0 = blockIdx.y * 128;

    const __half* A = g_af16 + (size_t)b * N_ * N_;
    const __half* V = g_vf16 + (size_t)b * C_ * N_;

    const int wm = (wid >> 2) * 64;    // m offset of warp
    const int wc = (wid & 3) * 16;     // c offset of warp

    const uint32_t lrow = lane & 15;
    const uint32_t lswz = (lane & 7) << 4;
    const uint32_t lcol = (lane >> 4) << 4;

    float acc[4][2][4] = {};   // [m16][c8][reg]

    auto load_chunk = [&](int kc) {
        const uint32_t st = (uint32_t)(kc & 1) * STAGE_O;
        const size_t koff = (size_t)kc * KC_O;
#pragma unroll
        for (int t = 0; t < 6; t++) {
            const int idx = tid + t * 256;
            if (idx < 1024) {
                const int row = idx >> 3, seg = idx & 7;
                cp16(sbase + st + swz(row, seg * 16),
                     A + (size_t)(m0 + row) * N_ + koff + seg * 8);
            } else {
                const int i2 = idx - 1024;
                const int row = i2 >> 3, seg = i2 & 7;
                cp16(sbase + st + 16384u + swz(row, seg * 16),
                     V + (size_t)(c0 + row) * N_ + koff + seg * 8);
            }
        }
        asm volatile("cp.async.commit_group;" ::: "memory");
    };

    load_chunk(0);

    for (int kc = 0; kc < NCHUNK_O; kc++) {
        asm volatile("cp.async.wait_group 0;" ::: "memory");
        __syncthreads();
        if (kc + 1 < NCHUNK_O) load_chunk(kc + 1);

        const uint32_t st = (uint32_t)(kc & 1) * STAGE_O;
        const uint32_t Ab = sbase + st, Vb = Ab + 16384;

#pragma unroll
        for (int ks = 0; ks < 4; ks++) {
            const uint32_t kb = (uint32_t)(ks * 32);
            uint32_t a[4][4], bm[4];
#pragma unroll
            for (int i = 0; i < 4; i++) {
                const uint32_t row = (uint32_t)(wm + i * 16) + lrow;
                ldsm4(a[i], Ab + row * 128u + ((kb + lcol) ^ lswz));
            }
            {
                const uint32_t row = (uint32_t)wc + lrow;
                ldsm4(bm, Vb + row * 128u + ((kb + lcol) ^ lswz));
            }
#pragma unroll
            for (int i = 0; i < 4; i++)
#pragma unroll
                for (int p2 = 0; p2 < 2; p2++)
                    mma_f16(acc[i][p2], a[i], bm[p2], bm[2 + p2]);
        }
    }
    __syncthreads();

    // ---- epilogue: full 64c x 128m transpose via smem ----
    float* sOut = reinterpret_cast<float*>(dynsmem);
#pragma unroll
    for (int i = 0; i < 4; i++) {
        const int mt = wm + i * 16 + (lane >> 2);
#pragma unroll
        for (int p2 = 0; p2 < 2; p2++) {
            const int ct = wc + p2 * 8 + (lane & 3) * 2;
            sOut[ct * EPI_P + mt]           = acc[i][p2][0];
            sOut[(ct + 1) * EPI_P + mt]     = acc[i][p2][1];
            sOut[ct * EPI_P + mt + 8]       = acc[i][p2][2];
            sOut[(ct + 1) * EPI_P + mt + 8] = acc[i][p2][3];
        }
    }
    __syncthreads();

    const float g = gamma[0];
    const int ce = tid >> 2;             // 0..63
    const int me = (tid & 3) * 32;       // m offset
    const size_t gb = ((size_t)b * C_ + c0 + ce) * N_ + m0 + me;
    const float* srow = sOut + ce * EPI_P + me;
#pragma unroll
    for (int v = 0; v < 8; v++) {
        const float4 xv = *reinterpret_cast<const float4*>(x + gb + v * 4);
        float4 ov;
        ov.x = g * srow[v * 4 + 0] + xv.x;
        ov.y = g * srow[v * 4 + 1] + xv.y;
        ov.z = g * srow[v * 4 + 2] + xv.z;
        ov.w = g * srow[v * 4 + 3] + xv.w;
        *reinterpret_cast<float4*>(out + gb + v * 4) = ov;
    }
}

// ---------------------------------------------------------------------------
extern "C" void kernel_launch(void* const* d_in, const int* in_sizes, int n_in,
                              void* d_out, int out_size) {
    (void)in_sizes; (void)n_in; (void)out_size;
    const float* x     = (const float*)d_in[0];
    const float* Wq    = (const float*)d_in[1];
    const float* bq    = (const float*)d_in[2];
    const float* Wk    = (const float*)d_in[3];
    const float* bk    = (const float*)d_in[4];
    const float* Wv    = (const float*)d_in[5];
    const float* bv    = (const float*)d_in[6];
    const float* gamma = (const float*)d_in[7];

    float* out  = (float*)d_out;
    float* attn = out + (size_t)B_ * C_ * N_;   // tuple order: (out, attention)

    __nv_bfloat16 *qhi, *qlo, *khi, *klo, *xthi, *xtlo, *wvhi, *wvlo, *wqkhi, *wqklo;
    __half *vf16, *af16;
    cudaGetSymbolAddress((void**)&qhi, g_qhi);
    cudaGetSymbolAddress((void**)&qlo, g_qlo);
    cudaGetSymbolAddress((void**)&khi, g_khi);
    cudaGetSymbolAddress((void**)&klo, g_klo);
    cudaGetSymbolAddress((void**)&xthi, g_xthi);
    cudaGetSymbolAddress((void**)&xtlo, g_xtlo);
    cudaGetSymbolAddress((void**)&wvhi, g_wvhi);
    cudaGetSymbolAddress((void**)&wvlo, g_wvlo);
    cudaGetSymbolAddress((void**)&wqkhi, g_wqkhi);
    cudaGetSymbolAddress((void**)&wqklo, g_wqklo);
    cudaGetSymbolAddress((void**)&vf16, g_vf16);
    cudaGetSymbolAddress((void**)&af16, g_af16);

    cudaFuncSetAttribute(out_gemm_kernel,
                         cudaFuncAttributeMaxDynamicSharedMemorySize, DYN_OUT);
    cudaFuncSetAttribute(energy_hmma_kernel,
                         cudaFuncAttributeMaxDynamicSharedMemorySize, DYN_E);
    cudaFuncSetAttribute(proj_v_hmma_kernel,
                         cudaFuncAttributeMaxDynamicSharedMemorySize, DYN_V);
    cudaFuncSetAttribute(proj_qk_hmma_kernel,
                         cudaFuncAttributeMaxDynamicSharedMemorySize, DYN_QK);

    // ONE extra stream (Round-10-proven resource budget) + 6 events.
    // kernel_launch runs only twice; these handles are intentionally leaked.
    cudaStream_t s1;
    cudaStreamCreateWithFlags(&s1, cudaStreamNonBlocking);
    cudaEvent_t eFork, eX, eWqk, eV, eQK, eDone;
    cudaEventCreateWithFlags(&eFork, cudaEventDisableTiming);
    cudaEventCreateWithFlags(&eX,    cudaEventDisableTiming);
    cudaEventCreateWithFlags(&eWqk,  cudaEventDisableTiming);
    cudaEventCreateWithFlags(&eV,    cudaEventDisableTiming);
    cudaEventCreateWithFlags(&eQK,   cudaEventDisableTiming);
    cudaEventCreateWithFlags(&eDone, cudaEventDisableTiming);

    dim3 blk(256);

    // fork side stream off the (captured) legacy stream
    cudaEventRecord(eFork, 0);
    cudaStreamWaitEvent(s1, eFork, 0);

    // s1: weight converts (independent of x)
    convert_w_kernel<<<dim3(C_ * C_ / 256), blk, 0, s1>>>(Wv, wvhi, wvlo);
    convert_wqk_kernel<<<dim3(128 * C_ / 256), blk, 0, s1>>>(Wq, Wk, wqkhi, wqklo);
    cudaEventRecord(eWqk, s1);

    // s0: x transpose/split
    convert_x_kernel<<<dim3(N_ / 32, C_ / 32, B_), blk>>>(x, xthi, xtlo);
    cudaEventRecord(eX, 0);

    // s1: proj_v (needs convert_x + convert_w) — overlaps proj_qk/energy(b0)
    cudaStreamWaitEvent(s1, eX, 0);
    proj_v_hmma_kernel<<<dim3(C_ / 128, N_ / 128, B_), blk, DYN_V, s1>>>(bv, vf16);
    cudaEventRecord(eV, s1);

    // s0: proj_qk (needs convert_x + convert_wqk)
    cudaStreamWaitEvent(0, eWqk, 0);
    proj_qk_hmma_kernel<<<dim3(N_ / 128, 1, B_), blk, DYN_QK>>>(bq, bk, qhi, qlo, khi, klo);
    cudaEventRecord(eQK, 0);

    // Two-way batch pipeline: s0 handles b=0,2; s1 handles b=1,3.
    cudaStreamWaitEvent(s1, eQK, 0);
    for (int i = 0; i < 2; i++) {
        const int b0 = 2 * i;      // s0 batches: 0, 2
        const int b1 = 2 * i + 1;  // s1 batches: 1, 3

        energy_hmma_kernel<<<dim3(N_ / 128, N_ / 128, 1), blk, DYN_E, 0>>>(attn, b0);
        energy_hmma_kernel<<<dim3(N_ / 128, N_ / 128, 1), blk, DYN_E, s1>>>(attn, b1);

        softmax_kernel<<<dim3(N_), blk, 0, 0>>>(attn, af16, b0);
        softmax_kernel<<<dim3(N_), blk, 0, s1>>>(attn, af16, b1);

        if (i == 0) cudaStreamWaitEvent(0, eV, 0);   // v ready before first out_gemm
        out_gemm_kernel<<<dim3(C_ / 64, N_ / 128, 1), blk, DYN_OUT, 0>>>(x, gamma, out, b0);
        out_gemm_kernel<<<dim3(C_ / 64, N_ / 128, 1), blk, DYN_OUT, s1>>>(x, gamma, out, b1);
    }

    // join s1 back to the legacy (capture-origin) stream
    cudaEventRecord(eDone, s1);
    cudaStreamWaitEvent(0, eDone, 0);
}